// round 7
// baseline (speedup 1.0000x reference)
#include <cuda_runtime.h>
#include <cstdint>

// ---------------- problem constants ----------------
namespace {
constexpr int B    = 2;
constexpr int C0   = 64;
constexpr int C1   = 128;
constexpr int H    = 128, W = 128;
constexpr int HW   = H * W;            // 16384
constexpr int NPIX = B * HW;           // 32768
constexpr int R2   = 256;              // 16x16 reduced K/V
constexpr int DH   = 32;               // dim_head
constexpr float BN_EPS = 1e-5f;
}

// ---------------- scratch (static device, no allocs) ----------------
__device__ float g_pool[B * C0 * HW];
__device__ float g_t   [B * C1 * HW];
__device__ float g_u   [B * C1 * HW];
__device__ float g_o   [B * C1 * HW];
__device__ float g_qkv [B * 3 * C1 * HW];
__device__ float g_kd  [B * C1 * R2];
__device__ float g_vd  [B * C1 * R2];
__device__ __align__(16) unsigned g_wt[128 * 1152];   // pre-converted tf32 weights
__device__ double2 g_part[128][4];           // BN partial sums
__device__ unsigned g_cnt = 0;               // bnpart completion counter
__device__ float g_A   [8 * 128];
__device__ float g_Bv  [8 * 128];

// ---------------- helpers ----------------
__device__ __forceinline__ unsigned f2tf(float x) {
    unsigned r;
    asm("cvt.rna.tf32.f32 %0, %1;" : "=r"(r) : "f"(x));
    return r;
}
__device__ __forceinline__ void mma8(float c[4], const unsigned a[4], const unsigned b[2]) {
    asm volatile(
        "mma.sync.aligned.m16n8k8.row.col.f32.tf32.tf32.f32 "
        "{%0,%1,%2,%3},{%4,%5,%6,%7},{%8,%9},{%0,%1,%2,%3};"
        : "+f"(c[0]), "+f"(c[1]), "+f"(c[2]), "+f"(c[3])
        : "r"(a[0]), "r"(a[1]), "r"(a[2]), "r"(a[3]), "r"(b[0]), "r"(b[1]));
}
__device__ __forceinline__ void ldm4(unsigned a[4], const unsigned* p) {
    unsigned addr = (unsigned)__cvta_generic_to_shared(p);
    asm volatile("ldmatrix.sync.aligned.m8n8.x4.shared.b16 {%0,%1,%2,%3}, [%4];"
        : "=r"(a[0]), "=r"(a[1]), "=r"(a[2]), "=r"(a[3]) : "r"(addr));
}
__device__ __forceinline__ void cpa16(unsigned* dst, const void* src) {
    unsigned d = (unsigned)__cvta_generic_to_shared(dst);
    asm volatile("cp.async.ca.shared.global [%0], [%1], 16;" :: "r"(d), "l"(src));
}

// ---------------- weight pre-convert fp32 -> tf32 ----------------
__global__ void k_wprep(const float* __restrict__ w, int n) {
    int i = (blockIdx.x * 256 + threadIdx.x) * 4;
    float4 v = *reinterpret_cast<const float4*>(w + i);
    uint4 r;
    r.x = f2tf(v.x); r.y = f2tf(v.y); r.z = f2tf(v.z); r.w = f2tf(v.w);
    *reinterpret_cast<uint4*>(g_wt + i) = r;
}

// ---------------- maxpool 2x2 (256x256 -> 128x128) ----------------
__global__ void k_maxpool(const float* __restrict__ x, float* __restrict__ out) {
    int i = blockIdx.x * 256 + threadIdx.x;
    int p  = i & (HW - 1);
    int bc = i >> 14;
    int y = p >> 7, xx = p & 127;
    const float* ip = x + (size_t)bc * 65536 + (size_t)(y * 2) * 256 + xx * 2;
    out[i] = fmaxf(fmaxf(ip[0], ip[1]), fmaxf(ip[256], ip[257]));
}

// ---------------- BN stats: partials + last-block finalize ----------------
__global__ void k_bnpart(const float* __restrict__ x, const float* __restrict__ gg,
                         const float* __restrict__ bb, int Cc, int slot) {
    int c = blockIdx.x, part = blockIdx.y;
    int tid = threadIdx.x;
    const float4* x0 = reinterpret_cast<const float4*>(x + (size_t)c * HW) + part * (HW / 16);
    const float4* x1 = reinterpret_cast<const float4*>(x + (size_t)(Cc + c) * HW) + part * (HW / 16);
    float s = 0.f, s2 = 0.f;
#pragma unroll
    for (int it = 0; it < 4; it++) {
        int p = tid + it * 256;
        float4 a = x0[p];
        s += a.x + a.y + a.z + a.w;
        s2 = fmaf(a.x, a.x, fmaf(a.y, a.y, fmaf(a.z, a.z, fmaf(a.w, a.w, s2))));
        float4 d = x1[p];
        s += d.x + d.y + d.z + d.w;
        s2 = fmaf(d.x, d.x, fmaf(d.y, d.y, fmaf(d.z, d.z, fmaf(d.w, d.w, s2))));
    }
    __shared__ double rs[256], rq[256];
    rs[tid] = (double)s; rq[tid] = (double)s2;
    __syncthreads();
    for (int off = 128; off > 0; off >>= 1) {
        if (tid < off) { rs[tid] += rs[tid + off]; rq[tid] += rq[tid + off]; }
        __syncthreads();
    }
    __shared__ bool lastf;
    if (tid == 0) {
        g_part[c][part] = make_double2(rs[0], rq[0]);
        __threadfence();
        unsigned v = atomicAdd(&g_cnt, 1u);
        lastf = (v == (unsigned)(Cc * 4 - 1));
    }
    __syncthreads();
    if (lastf) {
        __threadfence();   // acquire: see all partials
        int cc = tid;
        if (cc < Cc) {
            double ss = 0., q = 0.;
#pragma unroll
            for (int p = 0; p < 4; p++) { ss += g_part[cc][p].x; q += g_part[cc][p].y; }
            double mean = ss / (double)NPIX;
            double var  = q / (double)NPIX - mean * mean;
            double A    = (double)gg[cc] / sqrt(var + (double)BN_EPS);
            g_A[slot * 128 + cc]  = (float)A;
            g_Bv[slot * 128 + cc] = (float)((double)bb[cc] - mean * A);
        }
        if (tid == 0) g_cnt = 0;   // reset for next invocation (graph replay safe)
    }
}

// ---------------- tf32 GEMM: cp.async A (pre-converted), ldmatrix frags ----------
// C[M,N] = W[M,K] @ X[K,N] (+add). Block 128x128, 256 thr = 8 warps (m64 x n32).
template <int K, int CIN, bool IC, bool BN, bool RELU, bool ADD>
__global__ __launch_bounds__(256)
void k_gemm(const float* __restrict__ in,
            float* __restrict__ out, const float* __restrict__ add,
            int COUT, int slot) {
    __shared__ __align__(16) unsigned sA[128 * 36];   // [row][k] stride 36
    __shared__ __align__(16) unsigned sB[32 * 136];   // [k][n]  stride 136

    const int tid = threadIdx.x;
    const int lane = tid & 31, warp = tid >> 5;
    const int gid = lane >> 2, qid = lane & 3;
    const int wm = (warp & 1) * 64, wn = (warp >> 1) * 32;

    const int n0 = blockIdx.x * 128;
    const int m0 = blockIdx.y * 128;
    const int b  = n0 >> 14;
    const int pbase = n0 & (HW - 1);
    const int y = pbase >> 7;

    const float* Ap = g_A  + slot * 128;
    const float* Bp = g_Bv + slot * 128;

    float c[4][4][4];
#pragma unroll
    for (int mt = 0; mt < 4; mt++)
#pragma unroll
        for (int nt = 0; nt < 4; nt++)
#pragma unroll
            for (int e = 0; e < 4; e++) c[mt][nt][e] = 0.f;

    const int a_col4 = (tid & 7) * 4;
    const int a_row0 = tid >> 3;
    const int b_col4 = (tid & 31) * 4;
    const int b_row0 = tid >> 5;

    // per-thread ldmatrix base: row = wm + (lane&15), col-half = (lane>>4)*4
    const unsigned* a_ld = sA + (wm + (lane & 15)) * 36 + ((lane >> 4) << 2);

    for (int k0 = 0; k0 < K; k0 += 32) {
        __syncthreads();
        // ---- A: cp.async from pre-converted weights ----
#pragma unroll
        for (int i = 0; i < 4; i++) {
            int row = a_row0 + 32 * i;
            cpa16(sA + row * 36 + a_col4,
                  g_wt + (size_t)(m0 + row) * K + k0 + a_col4);
        }
        asm volatile("cp.async.commit_group;");
        // ---- B: stage with cvt (+BN/ReLU/im2col) ----
#pragma unroll
        for (int i = 0; i < 4; i++) {
            int r = b_row0 + 8 * i;
            int k = k0 + r;
            unsigned* d = sB + r * 136 + b_col4;
            if (IC) {
                int ci = k / 9, q = k - ci * 9;
                int dy = q / 3 - 1, dx = q - (q / 3) * 3 - 1;
                int gy = y + dy;
                float A = 1.f, Bb = 0.f;
                if (BN) { A = Ap[ci]; Bb = Bp[ci]; }
                const float* src = in + ((size_t)(b * CIN) + ci) * HW + gy * 128;
                bool yok = (unsigned)gy < 128u;
#pragma unroll
                for (int e = 0; e < 4; e++) {
                    int gx = b_col4 + dx + e;
                    float v = 0.f;
                    if (yok && (unsigned)gx < 128u) {
                        v = src[gx];
                        if (BN) v = fmaf(v, A, Bb);
                        if (RELU) v = fmaxf(v, 0.f);
                    }
                    d[e] = f2tf(v);
                }
            } else {
                float4 xv = *reinterpret_cast<const float4*>(
                    in + ((size_t)(b * CIN) + k) * HW + pbase + b_col4);
                if (BN) {
                    float A = Ap[k], Bb = Bp[k];
                    xv.x = fmaf(xv.x, A, Bb); xv.y = fmaf(xv.y, A, Bb);
                    xv.z = fmaf(xv.z, A, Bb); xv.w = fmaf(xv.w, A, Bb);
                    if (RELU) {
                        xv.x = fmaxf(xv.x, 0.f); xv.y = fmaxf(xv.y, 0.f);
                        xv.z = fmaxf(xv.z, 0.f); xv.w = fmaxf(xv.w, 0.f);
                    }
                }
                d[0] = f2tf(xv.x); d[1] = f2tf(xv.y); d[2] = f2tf(xv.z); d[3] = f2tf(xv.w);
            }
        }
        asm volatile("cp.async.wait_group 0;");
        __syncthreads();
        // ---- mma ----
#pragma unroll
        for (int ks = 0; ks < 4; ks++) {
            const int kk = ks * 8;
            unsigned af[4][4], bf[4][2];
#pragma unroll
            for (int mt = 0; mt < 4; mt++)
                ldm4(af[mt], a_ld + mt * 16 * 36 + kk);
#pragma unroll
            for (int nt = 0; nt < 4; nt++) {
                const unsigned* sb = sB + (kk + qid) * 136 + wn + nt * 8 + gid;
                bf[nt][0] = sb[0];
                bf[nt][1] = sb[4 * 136];
            }
#pragma unroll
            for (int mt = 0; mt < 4; mt++)
#pragma unroll
                for (int nt = 0; nt < 4; nt++)
                    mma8(c[mt][nt], af[mt], bf[nt]);
        }
    }

#pragma unroll
    for (int mt = 0; mt < 4; mt++) {
        int co = m0 + wm + mt * 16 + gid;
#pragma unroll
        for (int nt = 0; nt < 4; nt++) {
            int cb = wn + nt * 8 + qid * 2;
            size_t idx0 = ((size_t)(b * COUT) + co) * HW + pbase + cb;
            size_t idx1 = ((size_t)(b * COUT) + co + 8) * HW + pbase + cb;
            float2 r0 = make_float2(c[mt][nt][0], c[mt][nt][1]);
            float2 r1 = make_float2(c[mt][nt][2], c[mt][nt][3]);
            if (ADD) {
                float2 a0 = *reinterpret_cast<const float2*>(add + idx0);
                float2 a1 = *reinterpret_cast<const float2*>(add + idx1);
                r0.x += a0.x; r0.y += a0.y; r1.x += a1.x; r1.y += a1.y;
            }
            *reinterpret_cast<float2*>(out + idx0) = r0;
            *reinterpret_cast<float2*>(out + idx1) = r1;
        }
    }
}

// ---------------- depthwise 3x3, pad=1, optional fused BN ----------------
template <int BN>
__global__ void k_dw3(const float* __restrict__ in, const float* __restrict__ w,
                      float* __restrict__ out, int slot) {
    int i = blockIdx.x * 256 + threadIdx.x;
    int p  = i & (HW - 1);
    int bc = i >> 14;
    int c  = bc & 127;
    int y = p >> 7, x = p & 127;
    const float* ip = in + (size_t)bc * HW;
    const float* wp = w + c * 9;
    float A = 1.f, Bb = 0.f;
    if (BN) { A = g_A[slot * 128 + c]; Bb = g_Bv[slot * 128 + c]; }
    float s = 0.f;
#pragma unroll
    for (int dy = 0; dy < 3; dy++) {
        int gy = y + dy - 1;
        if ((unsigned)gy >= 128u) continue;
#pragma unroll
        for (int dx = 0; dx < 3; dx++) {
            int gx = x + dx - 1;
            if ((unsigned)gx >= 128u) continue;
            float v = ip[gy * 128 + gx];
            if (BN) v = fmaf(v, A, Bb);
            s = fmaf(v, wp[dy * 3 + dx], s);
        }
    }
    out[i] = s;
}

// ---------------- bilinear downsample k,v: 128x128 -> 16x16 ----------------
__global__ void k_ds(const float* __restrict__ qkv) {
    int i = blockIdx.x * 256 + threadIdx.x;
    int j  = i & 255;
    int oc = (i >> 8) & 255;
    int b  = i >> 16;
    const float* ip = qkv + ((size_t)(b * 384) + 128 + oc) * HW;
    int r = j >> 4, s = j & 15;
    const float step = (float)(127.0 / 15.0);
    float ph = (float)r * step;
    int   lh = min((int)ph, 126);
    float fh = ph - (float)lh;
    float pw = (float)s * step;
    int   lw = min((int)pw, 126);
    float fw = pw - (float)lw;
    const float* p0 = ip + lh * 128 + lw;
    float v00 = p0[0], v01 = p0[1], v10 = p0[128], v11 = p0[129];
    float val = (1.f - fh) * ((1.f - fw) * v00 + fw * v01)
              +        fh  * ((1.f - fw) * v10 + fw * v11);
    float* dst = (oc < 128) ? g_kd : g_vd;
    int cc = oc & 127;
    dst[(size_t)(b * 128 + cc) * R2 + j] = val;
}

// ---------------- tensor-core attention ----------------
__global__ __launch_bounds__(128)
void k_attn(const float* __restrict__ qkv, const float* __restrict__ table,
            float* __restrict__ outp) {
    extern __shared__ unsigned smu[];
    unsigned* k_s = smu;                    // [256][36]
    unsigned* v_s = smu + 256 * 36;         // [256][36]
    unsigned* q_s = v_s + 256 * 36;         // [64][36]
    float*    t_s = reinterpret_cast<float*>(q_s + 64 * 36);   // [961]

    const int tid  = threadIdx.x;
    const int lane = tid & 31, warp = tid >> 5;
    const int gid  = lane >> 2, qid = lane & 3;
    const int bh   = blockIdx.y;
    const int b = bh >> 2, head = bh & 3;
    const int px0 = blockIdx.x * 64;
    const float scale = 0.17677669529663687f;

    for (int i = tid; i < 256 * 32; i += 128) {
        int j = i & 255, d = i >> 8;
        size_t gi = ((size_t)(b * C1) + d * 4 + head) * R2 + j;
        k_s[j * 36 + d] = f2tf(g_kd[gi]);
        v_s[j * 36 + d] = f2tf(g_vd[gi]);
    }
    for (int i = tid; i < 64 * 32; i += 128) {
        int r = i & 63, d = i >> 6;
        q_s[r * 36 + d] = f2tf(qkv[((size_t)(b * 384) + d * 4 + head) * HW + px0 + r] * scale);
    }
    for (int i = tid; i < 961; i += 128) t_s[i] = table[i * 4 + head] * scale;
    __syncthreads();

    unsigned aq[4][4];
#pragma unroll
    for (int kc = 0; kc < 4; kc++) {
        const unsigned* sa = q_s + (warp * 16 + gid) * 36 + kc * 8 + qid;
        aq[kc][0] = sa[0];
        aq[kc][1] = sa[8 * 36];
        aq[kc][2] = sa[4];
        aq[kc][3] = sa[8 * 36 + 4];
    }
    float s[32][4];
#pragma unroll
    for (int nt = 0; nt < 32; nt++) { s[nt][0]=s[nt][1]=s[nt][2]=s[nt][3]=0.f; }
#pragma unroll
    for (int nt = 0; nt < 32; nt++) {
        const unsigned* kb = k_s + (nt * 8 + gid) * 36;
#pragma unroll
        for (int kc = 0; kc < 4; kc++) {
            unsigned bf[2];
            bf[0] = kb[kc * 8 + qid];
            bf[1] = kb[kc * 8 + qid + 4];
            mma8(s[nt], aq[kc], bf);
        }
    }

    const int xb = (px0 & 127) + warp * 16;
    const int rh = (px0 >> 7) >> 3;
    const int base0 = (rh + 15) * 31 + ((xb + gid) >> 3) + 15;
    const int base1 = (rh + 15) * 31 + ((xb + gid + 8) >> 3) + 15;
    float l0 = 0.f, l1 = 0.f;
#pragma unroll
    for (int nt = 0; nt < 32; nt++) {
        int j = nt * 8 + 2 * qid;
        int off = (j >> 4) * 31 + (j & 15);
        float e0 = __expf(s[nt][0] + t_s[base0 - off]);
        float e1 = __expf(s[nt][1] + t_s[base0 - off - 1]);
        float e2 = __expf(s[nt][2] + t_s[base1 - off]);
        float e3 = __expf(s[nt][3] + t_s[base1 - off - 1]);
        s[nt][0] = e0; s[nt][1] = e1; s[nt][2] = e2; s[nt][3] = e3;
        l0 += e0 + e1; l1 += e2 + e3;
    }
    l0 += __shfl_xor_sync(0xffffffffu, l0, 1);
    l0 += __shfl_xor_sync(0xffffffffu, l0, 2);
    l1 += __shfl_xor_sync(0xffffffffu, l1, 1);
    l1 += __shfl_xor_sync(0xffffffffu, l1, 2);
    const float inv0 = 1.f / l0, inv1 = 1.f / l1;

    float o[4][4];
#pragma unroll
    for (int nt = 0; nt < 4; nt++) { o[nt][0]=o[nt][1]=o[nt][2]=o[nt][3]=0.f; }
    const int src0 = (lane & ~3) | (qid >> 1);
    const int src1 = src0 + 2;
    const bool odd = (qid & 1);
#pragma unroll
    for (int kc = 0; kc < 32; kc++) {
        float p0 = s[kc][0], p1 = s[kc][1], p2 = s[kc][2], p3 = s[kc][3];
        float v00 = __shfl_sync(0xffffffffu, p0, src0);
        float v01 = __shfl_sync(0xffffffffu, p1, src0);
        float v10 = __shfl_sync(0xffffffffu, p2, src0);
        float v11 = __shfl_sync(0xffffffffu, p3, src0);
        float v20 = __shfl_sync(0xffffffffu, p0, src1);
        float v21 = __shfl_sync(0xffffffffu, p1, src1);
        float v30 = __shfl_sync(0xffffffffu, p2, src1);
        float v31 = __shfl_sync(0xffffffffu, p3, src1);
        unsigned a[4];
        a[0] = f2tf(odd ? v01 : v00);
        a[1] = f2tf(odd ? v11 : v10);
        a[2] = f2tf(odd ? v21 : v20);
        a[3] = f2tf(odd ? v31 : v30);
        const unsigned* vb0 = v_s + (kc * 8 + qid) * 36;
        const unsigned* vb1 = v_s + (kc * 8 + qid + 4) * 36;
#pragma unroll
        for (int ntd = 0; ntd < 4; ntd++) {
            unsigned bf[2];
            bf[0] = vb0[ntd * 8 + gid];
            bf[1] = vb1[ntd * 8 + gid];
            mma8(o[ntd], a, bf);
        }
    }

    const int px = px0 + warp * 16 + gid;
#pragma unroll
    for (int ntd = 0; ntd < 4; ntd++) {
        int d = ntd * 8 + 2 * qid;
        size_t c0 = ((size_t)(b * C1) + d * 4 + head) * HW;
        size_t c1 = ((size_t)(b * C1) + (d + 1) * 4 + head) * HW;
        outp[c0 + px]     = o[ntd][0] * inv0;
        outp[c1 + px]     = o[ntd][1] * inv0;
        outp[c0 + px + 8] = o[ntd][2] * inv1;
        outp[c1 + px + 8] = o[ntd][3] * inv1;
    }
}

// ---------------- host orchestration ----------------
extern "C" void kernel_launch(void* const* d_in, const int* in_sizes, int n_in,
                              void* d_out, int out_size) {
    (void)in_sizes; (void)n_in; (void)out_size;
    const float* x        = (const float*)d_in[0];
    const float* bb_bn1_g = (const float*)d_in[1];
    const float* bb_bn1_b = (const float*)d_in[2];
    const float* bb_conv1 = (const float*)d_in[3];
    const float* bb_bn2_g = (const float*)d_in[4];
    const float* bb_bn2_b = (const float*)d_in[5];
    const float* bb_conv2 = (const float*)d_in[6];
    const float* bb_sbn_g = (const float*)d_in[7];
    const float* bb_sbn_b = (const float*)d_in[8];
    const float* bb_sconv = (const float*)d_in[9];
    const float* tb_bn1_g = (const float*)d_in[10];
    const float* tb_bn1_b = (const float*)d_in[11];
    const float* tb_dwqkv = (const float*)d_in[12];
    const float* tb_pwqkv = (const float*)d_in[13];
    const float* tb_dwout = (const float*)d_in[14];
    const float* tb_pwout = (const float*)d_in[15];
    const float* tb_rel   = (const float*)d_in[16];
    const float* tb_bn2_g = (const float*)d_in[17];
    const float* tb_bn2_b = (const float*)d_in[18];
    const float* tb_mlp   = (const float*)d_in[19];

    void* pv;
    float *pool, *t, *u, *o, *qkv;
    cudaGetSymbolAddress(&pv, g_pool); pool = (float*)pv;
    cudaGetSymbolAddress(&pv, g_t);    t    = (float*)pv;
    cudaGetSymbolAddress(&pv, g_u);    u    = (float*)pv;
    cudaGetSymbolAddress(&pv, g_o);    o    = (float*)pv;
    cudaGetSymbolAddress(&pv, g_qkv);  qkv  = (float*)pv;

    const int ATTN_SMEM = (2 * 256 * 36 + 64 * 36) * 4 + 961 * 4;   // 86788
    cudaFuncSetAttribute(k_attn, cudaFuncAttributeMaxDynamicSharedMemorySize, ATTN_SMEM);

    const dim3 g1(NPIX / 128, 1);
    const dim3 g3(NPIX / 128, 3);
    const dim3 ga(HW / 64, B * 4);

    k_maxpool<<<(B * C0 * HW) / 256, 256>>>(x, pool);

    // ---- BasicBlock ----
    k_bnpart<<<dim3(C0, 4), 256>>>(pool, bb_bn1_g, bb_bn1_b, C0, 0);
    k_wprep<<<128 * 576 / 1024, 256>>>(bb_conv1, 128 * 576);
    k_gemm<576, 64, true, true, true, false><<<g1, 256>>>(pool, u, nullptr, 128, 0);
    k_bnpart<<<dim3(C1, 4), 256>>>(u, bb_bn2_g, bb_bn2_b, C1, 1);
    k_wprep<<<128 * 1152 / 1024, 256>>>(bb_conv2, 128 * 1152);
    k_gemm<1152, 128, true, true, true, false><<<g1, 256>>>(u, o, nullptr, 128, 1);
    k_bnpart<<<dim3(C0, 4), 256>>>(pool, bb_sbn_g, bb_sbn_b, C0, 2);
    k_wprep<<<128 * 64 / 1024, 256>>>(bb_sconv, 128 * 64);
    k_gemm<64, 64, false, true, true, true><<<g1, 256>>>(pool, o, o, 128, 2);

    // ---- 2 x BasicTransBlock (ping-pong residual between o and t) ----
    float* ob = o;
    float* tb = t;
    for (int i = 0; i < 2; i++) {
        k_bnpart<<<dim3(C1, 4), 256>>>(ob, tb_bn1_g + i * 128, tb_bn1_b + i * 128, C1, 3);
        k_dw3<1><<<(B * C1 * HW) / 256, 256>>>(ob, tb_dwqkv + (size_t)i * 128 * 9, u, 3);
        k_wprep<<<384 * 128 / 1024, 256>>>(tb_pwqkv + (size_t)i * 384 * 128, 384 * 128);
        k_gemm<128, 128, false, false, false, false><<<g3, 256>>>(u, qkv, nullptr, 384, 0);
        k_ds<<<(B * 256 * R2) / 256, 256>>>(qkv);
        k_attn<<<ga, 128, ATTN_SMEM>>>(qkv, tb_rel + (size_t)i * 961 * 4, tb);
        k_dw3<0><<<(B * C1 * HW) / 256, 256>>>(tb, tb_dwout + (size_t)i * 128 * 9, u, 0);
        k_wprep<<<128 * 128 / 1024, 256>>>(tb_pwout + (size_t)i * 128 * 128, 128 * 128);
        k_gemm<128, 128, false, false, false, true><<<g1, 256>>>(u, ob, ob, 128, 0);
        k_bnpart<<<dim3(C1, 4), 256>>>(ob, tb_bn2_g + i * 128, tb_bn2_b + i * 128, C1, 4);
        float* dest = (i == 1) ? (float*)d_out : tb;
        k_wprep<<<128 * 128 / 1024, 256>>>(tb_mlp + (size_t)i * 128 * 128, 128 * 128);
        k_gemm<128, 128, false, true, true, true><<<g1, 256>>>(ob, dest, ob, 128, 4);
        float* tmp = ob; ob = tb; tb = tmp;
    }
}

// round 8
// speedup vs baseline: 1.1408x; 1.1408x over previous
#include <cuda_runtime.h>
#include <cuda_fp16.h>
#include <cstdint>

// ---------------- problem constants ----------------
namespace {
constexpr int B    = 2;
constexpr int C0   = 64;
constexpr int C1   = 128;
constexpr int H    = 128, W = 128;
constexpr int HW   = H * W;            // 16384
constexpr int NPIX = B * HW;           // 32768
constexpr int R2   = 256;              // 16x16 reduced K/V
constexpr int DH   = 32;               // dim_head
constexpr float BN_EPS = 1e-5f;
// fp16 weight arena offsets
constexpr int WO_CONV1 = 0;                        // 128*576
constexpr int WO_CONV2 = 73728;                    // 128*1152
constexpr int WO_SCONV = 221184;                   // 128*64
constexpr int WO_TB    = 229376;                   // per block: qkv 49152, pwout 16384, mlp 16384
constexpr int WO_BLK   = 81920;
constexpr int W_TOTAL  = 393216;
}

// ---------------- scratch (static device, no allocs) ----------------
__device__ float g_pool[B * C0 * HW];
__device__ float g_t   [B * C1 * HW];
__device__ float g_u   [B * C1 * HW];
__device__ float g_o   [B * C1 * HW];
__device__ float g_qkv [B * 3 * C1 * HW];
__device__ float g_kd  [B * C1 * R2];
__device__ float g_vd  [B * C1 * R2];
__device__ __align__(16) __half g_wth[W_TOTAL];   // pre-converted fp16 weights
__device__ double2 g_part[128][4];
__device__ unsigned g_cnt = 0;
__device__ float g_A   [8 * 128];
__device__ float g_Bv  [8 * 128];

// ---------------- helpers ----------------
__device__ __forceinline__ unsigned f2tf(float x) {
    unsigned r;
    asm("cvt.rna.tf32.f32 %0, %1;" : "=r"(r) : "f"(x));
    return r;
}
__device__ __forceinline__ void mma8(float c[4], const unsigned a[4], const unsigned b[2]) {
    asm volatile(
        "mma.sync.aligned.m16n8k8.row.col.f32.tf32.tf32.f32 "
        "{%0,%1,%2,%3},{%4,%5,%6,%7},{%8,%9},{%0,%1,%2,%3};"
        : "+f"(c[0]), "+f"(c[1]), "+f"(c[2]), "+f"(c[3])
        : "r"(a[0]), "r"(a[1]), "r"(a[2]), "r"(a[3]), "r"(b[0]), "r"(b[1]));
}
__device__ __forceinline__ void mma16(float c[4], const unsigned a[4], const unsigned b[2]) {
    asm volatile(
        "mma.sync.aligned.m16n8k16.row.col.f32.f16.f16.f32 "
        "{%0,%1,%2,%3},{%4,%5,%6,%7},{%8,%9},{%0,%1,%2,%3};"
        : "+f"(c[0]), "+f"(c[1]), "+f"(c[2]), "+f"(c[3])
        : "r"(a[0]), "r"(a[1]), "r"(a[2]), "r"(a[3]), "r"(b[0]), "r"(b[1]));
}
__device__ __forceinline__ void ldm4(unsigned a[4], const void* p) {
    unsigned addr = (unsigned)__cvta_generic_to_shared(p);
    asm volatile("ldmatrix.sync.aligned.m8n8.x4.shared.b16 {%0,%1,%2,%3}, [%4];"
        : "=r"(a[0]), "=r"(a[1]), "=r"(a[2]), "=r"(a[3]) : "r"(addr));
}
__device__ __forceinline__ void cpa16(void* dst, const void* src) {
    unsigned d = (unsigned)__cvta_generic_to_shared(dst);
    asm volatile("cp.async.ca.shared.global [%0], [%1], 16;" :: "r"(d), "l"(src));
}
__device__ __forceinline__ unsigned h2u(__half2 h) {
    return *reinterpret_cast<unsigned*>(&h);
}

// ---------------- weight pre-convert fp32 -> fp16 (all tensors, one launch) ----------------
struct WSeg { const float* src; int dst; int n; };
struct WArgs { WSeg s[9]; };
__global__ void k_wprep_all(WArgs a) {
    int i = (blockIdx.x * 256 + threadIdx.x) * 4;
#pragma unroll
    for (int t = 0; t < 9; t++) {
        if (i < a.s[t].n) {
            float4 v = *reinterpret_cast<const float4*>(a.s[t].src + i);
            uint2 pk;
            pk.x = h2u(__floats2half2_rn(v.x, v.y));
            pk.y = h2u(__floats2half2_rn(v.z, v.w));
            *reinterpret_cast<uint2*>(g_wth + a.s[t].dst + i) = pk;
            return;
        }
        i -= a.s[t].n;
    }
}

// ---------------- maxpool 2x2 (256x256 -> 128x128) ----------------
__global__ void k_maxpool(const float* __restrict__ x, float* __restrict__ out) {
    int i = blockIdx.x * 256 + threadIdx.x;
    int p  = i & (HW - 1);
    int bc = i >> 14;
    int y = p >> 7, xx = p & 127;
    const float* ip = x + (size_t)bc * 65536 + (size_t)(y * 2) * 256 + xx * 2;
    out[i] = fmaxf(fmaxf(ip[0], ip[1]), fmaxf(ip[256], ip[257]));
}

// ---------------- BN stats: partials + last-block finalize (1 or 2 slots) ----------------
__global__ void k_bnpart(const float* __restrict__ x, const float* __restrict__ gg,
                         const float* __restrict__ bb, int Cc, int slot,
                         const float* __restrict__ gg2, const float* __restrict__ bb2,
                         int slot2) {
    int c = blockIdx.x, part = blockIdx.y;
    int tid = threadIdx.x;
    int lane = tid & 31, wid = tid >> 5;
    const float4* x0 = reinterpret_cast<const float4*>(x + (size_t)c * HW) + part * (HW / 16);
    const float4* x1 = reinterpret_cast<const float4*>(x + (size_t)(Cc + c) * HW) + part * (HW / 16);
    float s = 0.f, s2 = 0.f;
#pragma unroll
    for (int it = 0; it < 4; it++) {
        int p = tid + it * 256;
        float4 a = x0[p];
        s += a.x + a.y + a.z + a.w;
        s2 = fmaf(a.x, a.x, fmaf(a.y, a.y, fmaf(a.z, a.z, fmaf(a.w, a.w, s2))));
        float4 d = x1[p];
        s += d.x + d.y + d.z + d.w;
        s2 = fmaf(d.x, d.x, fmaf(d.y, d.y, fmaf(d.z, d.z, fmaf(d.w, d.w, s2))));
    }
#pragma unroll
    for (int off = 16; off > 0; off >>= 1) {
        s  += __shfl_down_sync(0xffffffffu, s, off);
        s2 += __shfl_down_sync(0xffffffffu, s2, off);
    }
    __shared__ double ws[8], wq[8];
    __shared__ bool lastf;
    if (lane == 0) { ws[wid] = (double)s; wq[wid] = (double)s2; }
    __syncthreads();
    if (tid == 0) {
        double S = 0., Q = 0.;
#pragma unroll
        for (int w = 0; w < 8; w++) { S += ws[w]; Q += wq[w]; }
        g_part[c][part] = make_double2(S, Q);
        __threadfence();
        unsigned v = atomicAdd(&g_cnt, 1u);
        lastf = (v == (unsigned)(Cc * 4 - 1));
    }
    __syncthreads();
    if (lastf) {
        __threadfence();
        int cc = tid;
        if (cc < Cc) {
            double ss = 0., q = 0.;
#pragma unroll
            for (int p = 0; p < 4; p++) { ss += g_part[cc][p].x; q += g_part[cc][p].y; }
            double mean = ss / (double)NPIX;
            double var  = q / (double)NPIX - mean * mean;
            double rstd = 1.0 / sqrt(var + (double)BN_EPS);
            double A    = (double)gg[cc] * rstd;
            g_A[slot * 128 + cc]  = (float)A;
            g_Bv[slot * 128 + cc] = (float)((double)bb[cc] - mean * A);
            if (gg2) {
                double A2 = (double)gg2[cc] * rstd;
                g_A[slot2 * 128 + cc]  = (float)A2;
                g_Bv[slot2 * 128 + cc] = (float)((double)bb2[cc] - mean * A2);
            }
        }
        if (tid == 0) g_cnt = 0;
    }
}

// ---------------- fp16 GEMM: C[M,N] = W[M,K] @ X[K,N] (+add) ----------------
// Block 128x128, 256 thr = 8 warps (m64 x n32), K-chunk 32 (2 x k16 mma steps).
// A: cp.async fp16 weights -> sA[128][40], ldmatrix frags.
// B: packed k-pair interleave sB[16 kpairs][136 words], word (kpair,n) = (h_even, h_odd).
template <int K, int CIN, bool IC, bool BN, bool RELU, bool ADD>
__global__ __launch_bounds__(256)
void k_gemm(const float* __restrict__ in,
            float* __restrict__ out, const float* __restrict__ add,
            int COUT, int slot, int woff) {
    __shared__ __align__(16) __half sA[128 * 40];
    __shared__ __align__(16) __half sB[16 * 272];

    const int tid = threadIdx.x;
    const int lane = tid & 31, warp = tid >> 5;
    const int gid = lane >> 2, qid = lane & 3;
    const int wm = (warp & 1) * 64, wn = (warp >> 1) * 32;

    const int n0 = blockIdx.x * 128;
    const int m0 = blockIdx.y * 128;
    const int b  = n0 >> 14;
    const int pbase = n0 & (HW - 1);
    const int y = pbase >> 7;

    const float* Ap = g_A  + slot * 128;
    const float* Bp = g_Bv + slot * 128;
    const __half* wbase = g_wth + woff;

    float c[4][4][4];
#pragma unroll
    for (int mt = 0; mt < 4; mt++)
#pragma unroll
        for (int nt = 0; nt < 4; nt++)
#pragma unroll
            for (int e = 0; e < 4; e++) c[mt][nt][e] = 0.f;

    const int a_row = tid >> 1;            // 0..127
    const int a_c   = (tid & 1) * 16;      // 0 or 16
    const int colg  = tid & 31;            // 4-px group
    const int kp    = tid >> 5;            // kpair 0..7 (+8)

    // ldmatrix per-thread base: row wm + (lane&15), half-col (lane>>4)*8
    __half* a_ld = sA + (wm + (lane & 15)) * 40 + ((lane >> 4) << 3);
    const unsigned* sbw = reinterpret_cast<const unsigned*>(sB);

    for (int k0 = 0; k0 < K; k0 += 32) {
        __syncthreads();
        // ---- A: cp.async fp16 weights ----
        {
            const __half* src = wbase + (size_t)(m0 + a_row) * K + k0 + a_c;
            __half* dst = sA + a_row * 40 + a_c;
            cpa16(dst, src);
            cpa16(dst + 8, src + 8);
        }
        asm volatile("cp.async.commit_group;");
        // ---- B: stage packed k-pairs ----
#pragma unroll
        for (int it = 0; it < 2; it++) {
            int kpair = kp + it * 8;
            int ke = k0 + kpair * 2;
            float ve[4], vo[4];
#pragma unroll
            for (int half = 0; half < 2; half++) {
                int k = ke + half;
                float* v = half ? vo : ve;
                if (IC) {
                    int ci = k / 9, q = k - ci * 9;
                    int dy = q / 3 - 1, dx = q - (q / 3) * 3 - 1;
                    int gy = y + dy;
                    float A = 1.f, Bb = 0.f;
                    if (BN) { A = Ap[ci]; Bb = Bp[ci]; }
                    const float* src = in + ((size_t)(b * CIN) + ci) * HW + gy * 128;
                    bool yok = (unsigned)gy < 128u;
#pragma unroll
                    for (int e = 0; e < 4; e++) {
                        int gx = colg * 4 + dx + e;
                        float vv = 0.f;
                        if (yok && (unsigned)gx < 128u) {
                            vv = src[gx];
                            if (BN) vv = fmaf(vv, A, Bb);
                            if (RELU) vv = fmaxf(vv, 0.f);
                        }
                        v[e] = vv;
                    }
                } else {
                    float4 xv = *reinterpret_cast<const float4*>(
                        in + ((size_t)(b * CIN) + k) * HW + pbase + colg * 4);
                    if (BN) {
                        float A = Ap[k], Bb = Bp[k];
                        xv.x = fmaf(xv.x, A, Bb); xv.y = fmaf(xv.y, A, Bb);
                        xv.z = fmaf(xv.z, A, Bb); xv.w = fmaf(xv.w, A, Bb);
                        if (RELU) {
                            xv.x = fmaxf(xv.x, 0.f); xv.y = fmaxf(xv.y, 0.f);
                            xv.z = fmaxf(xv.z, 0.f); xv.w = fmaxf(xv.w, 0.f);
                        }
                    }
                    v[0] = xv.x; v[1] = xv.y; v[2] = xv.z; v[3] = xv.w;
                }
            }
            uint4 pk;
            pk.x = h2u(__floats2half2_rn(ve[0], vo[0]));
            pk.y = h2u(__floats2half2_rn(ve[1], vo[1]));
            pk.z = h2u(__floats2half2_rn(ve[2], vo[2]));
            pk.w = h2u(__floats2half2_rn(ve[3], vo[3]));
            *reinterpret_cast<uint4*>(sB + kpair * 272 + colg * 8) = pk;
        }
        asm volatile("cp.async.wait_group 0;");
        __syncthreads();
        // ---- mma: 2 k16 steps ----
#pragma unroll
        for (int ks = 0; ks < 2; ks++) {
            unsigned af[4][4], bf[4][2];
#pragma unroll
            for (int mt = 0; mt < 4; mt++)
                ldm4(af[mt], a_ld + mt * 16 * 40 + ks * 16);
#pragma unroll
            for (int nt = 0; nt < 4; nt++) {
                int n = wn + nt * 8 + gid;
                bf[nt][0] = sbw[(8 * ks + qid) * 136 + n];
                bf[nt][1] = sbw[(8 * ks + qid + 4) * 136 + n];
            }
#pragma unroll
            for (int mt = 0; mt < 4; mt++)
#pragma unroll
                for (int nt = 0; nt < 4; nt++)
                    mma16(c[mt][nt], af[mt], bf[nt]);
        }
    }

#pragma unroll
    for (int mt = 0; mt < 4; mt++) {
        int co = m0 + wm + mt * 16 + gid;
#pragma unroll
        for (int nt = 0; nt < 4; nt++) {
            int cb = wn + nt * 8 + qid * 2;
            size_t idx0 = ((size_t)(b * COUT) + co) * HW + pbase + cb;
            size_t idx1 = ((size_t)(b * COUT) + co + 8) * HW + pbase + cb;
            float2 r0 = make_float2(c[mt][nt][0], c[mt][nt][1]);
            float2 r1 = make_float2(c[mt][nt][2], c[mt][nt][3]);
            if (ADD) {
                float2 a0 = *reinterpret_cast<const float2*>(add + idx0);
                float2 a1 = *reinterpret_cast<const float2*>(add + idx1);
                r0.x += a0.x; r0.y += a0.y; r1.x += a1.x; r1.y += a1.y;
            }
            *reinterpret_cast<float2*>(out + idx0) = r0;
            *reinterpret_cast<float2*>(out + idx1) = r1;
        }
    }
}

// ---------------- depthwise 3x3, pad=1, optional fused BN ----------------
template <int BN>
__global__ void k_dw3(const float* __restrict__ in, const float* __restrict__ w,
                      float* __restrict__ out, int slot) {
    int i = blockIdx.x * 256 + threadIdx.x;
    int p  = i & (HW - 1);
    int bc = i >> 14;
    int c  = bc & 127;
    int y = p >> 7, x = p & 127;
    const float* ip = in + (size_t)bc * HW;
    const float* wp = w + c * 9;
    float A = 1.f, Bb = 0.f;
    if (BN) { A = g_A[slot * 128 + c]; Bb = g_Bv[slot * 128 + c]; }
    float s = 0.f;
#pragma unroll
    for (int dy = 0; dy < 3; dy++) {
        int gy = y + dy - 1;
        if ((unsigned)gy >= 128u) continue;
#pragma unroll
        for (int dx = 0; dx < 3; dx++) {
            int gx = x + dx - 1;
            if ((unsigned)gx >= 128u) continue;
            float v = ip[gy * 128 + gx];
            if (BN) v = fmaf(v, A, Bb);
            s = fmaf(v, wp[dy * 3 + dx], s);
        }
    }
    out[i] = s;
}

// ---------------- bilinear downsample k,v: 128x128 -> 16x16 ----------------
__global__ void k_ds(const float* __restrict__ qkv) {
    int i = blockIdx.x * 256 + threadIdx.x;
    int j  = i & 255;
    int oc = (i >> 8) & 255;
    int b  = i >> 16;
    const float* ip = qkv + ((size_t)(b * 384) + 128 + oc) * HW;
    int r = j >> 4, s = j & 15;
    const float step = (float)(127.0 / 15.0);
    float ph = (float)r * step;
    int   lh = min((int)ph, 126);
    float fh = ph - (float)lh;
    float pw = (float)s * step;
    int   lw = min((int)pw, 126);
    float fw = pw - (float)lw;
    const float* p0 = ip + lh * 128 + lw;
    float v00 = p0[0], v01 = p0[1], v10 = p0[128], v11 = p0[129];
    float val = (1.f - fh) * ((1.f - fw) * v00 + fw * v01)
              +        fh  * ((1.f - fw) * v10 + fw * v11);
    float* dst = (oc < 128) ? g_kd : g_vd;
    int cc = oc & 127;
    dst[(size_t)(b * 128 + cc) * R2 + j] = val;
}

// ---------------- tensor-core attention (tf32) ----------------
__global__ __launch_bounds__(128)
void k_attn(const float* __restrict__ qkv, const float* __restrict__ table,
            float* __restrict__ outp) {
    extern __shared__ unsigned smu[];
    unsigned* k_s = smu;                    // [256][36]
    unsigned* v_s = smu + 256 * 36;         // [256][36]
    unsigned* q_s = v_s + 256 * 36;         // [64][36]
    float*    t_s = reinterpret_cast<float*>(q_s + 64 * 36);   // [961]

    const int tid  = threadIdx.x;
    const int lane = tid & 31, warp = tid >> 5;
    const int gid  = lane >> 2, qid = lane & 3;
    const int bh   = blockIdx.y;
    const int b = bh >> 2, head = bh & 3;
    const int px0 = blockIdx.x * 64;
    const float scale = 0.17677669529663687f;

    for (int i = tid; i < 256 * 32; i += 128) {
        int j = i & 255, d = i >> 8;
        size_t gi = ((size_t)(b * C1) + d * 4 + head) * R2 + j;
        k_s[j * 36 + d] = f2tf(g_kd[gi]);
        v_s[j * 36 + d] = f2tf(g_vd[gi]);
    }
    for (int i = tid; i < 64 * 32; i += 128) {
        int r = i & 63, d = i >> 6;
        q_s[r * 36 + d] = f2tf(qkv[((size_t)(b * 384) + d * 4 + head) * HW + px0 + r] * scale);
    }
    for (int i = tid; i < 961; i += 128) t_s[i] = table[i * 4 + head] * scale;
    __syncthreads();

    unsigned aq[4][4];
#pragma unroll
    for (int kc = 0; kc < 4; kc++) {
        const unsigned* sa = q_s + (warp * 16 + gid) * 36 + kc * 8 + qid;
        aq[kc][0] = sa[0];
        aq[kc][1] = sa[8 * 36];
        aq[kc][2] = sa[4];
        aq[kc][3] = sa[8 * 36 + 4];
    }
    float s[32][4];
#pragma unroll
    for (int nt = 0; nt < 32; nt++) { s[nt][0]=s[nt][1]=s[nt][2]=s[nt][3]=0.f; }
#pragma unroll
    for (int nt = 0; nt < 32; nt++) {
        const unsigned* kb = k_s + (nt * 8 + gid) * 36;
#pragma unroll
        for (int kc = 0; kc < 4; kc++) {
            unsigned bf[2];
            bf[0] = kb[kc * 8 + qid];
            bf[1] = kb[kc * 8 + qid + 4];
            mma8(s[nt], aq[kc], bf);
        }
    }

    const int xb = (px0 & 127) + warp * 16;
    const int rh = (px0 >> 7) >> 3;
    const int base0 = (rh + 15) * 31 + ((xb + gid) >> 3) + 15;
    const int base1 = (rh + 15) * 31 + ((xb + gid + 8) >> 3) + 15;
    float l0 = 0.f, l1 = 0.f;
#pragma unroll
    for (int nt = 0; nt < 32; nt++) {
        int j = nt * 8 + 2 * qid;
        int off = (j >> 4) * 31 + (j & 15);
        float e0 = __expf(s[nt][0] + t_s[base0 - off]);
        float e1 = __expf(s[nt][1] + t_s[base0 - off - 1]);
        float e2 = __expf(s[nt][2] + t_s[base1 - off]);
        float e3 = __expf(s[nt][3] + t_s[base1 - off - 1]);
        s[nt][0] = e0; s[nt][1] = e1; s[nt][2] = e2; s[nt][3] = e3;
        l0 += e0 + e1; l1 += e2 + e3;
    }
    l0 += __shfl_xor_sync(0xffffffffu, l0, 1);
    l0 += __shfl_xor_sync(0xffffffffu, l0, 2);
    l1 += __shfl_xor_sync(0xffffffffu, l1, 1);
    l1 += __shfl_xor_sync(0xffffffffu, l1, 2);
    const float inv0 = 1.f / l0, inv1 = 1.f / l1;

    float o[4][4];
#pragma unroll
    for (int nt = 0; nt < 4; nt++) { o[nt][0]=o[nt][1]=o[nt][2]=o[nt][3]=0.f; }
    const int src0 = (lane & ~3) | (qid >> 1);
    const int src1 = src0 + 2;
    const bool odd = (qid & 1);
#pragma unroll
    for (int kc = 0; kc < 32; kc++) {
        float p0 = s[kc][0], p1 = s[kc][1], p2 = s[kc][2], p3 = s[kc][3];
        float v00 = __shfl_sync(0xffffffffu, p0, src0);
        float v01 = __shfl_sync(0xffffffffu, p1, src0);
        float v10 = __shfl_sync(0xffffffffu, p2, src0);
        float v11 = __shfl_sync(0xffffffffu, p3, src0);
        float v20 = __shfl_sync(0xffffffffu, p0, src1);
        float v21 = __shfl_sync(0xffffffffu, p1, src1);
        float v30 = __shfl_sync(0xffffffffu, p2, src1);
        float v31 = __shfl_sync(0xffffffffu, p3, src1);
        unsigned a[4];
        a[0] = f2tf(odd ? v01 : v00);
        a[1] = f2tf(odd ? v11 : v10);
        a[2] = f2tf(odd ? v21 : v20);
        a[3] = f2tf(odd ? v31 : v30);
        const unsigned* vb0 = v_s + (kc * 8 + qid) * 36;
        const unsigned* vb1 = v_s + (kc * 8 + qid + 4) * 36;
#pragma unroll
        for (int ntd = 0; ntd < 4; ntd++) {
            unsigned bf[2];
            bf[0] = vb0[ntd * 8 + gid];
            bf[1] = vb1[ntd * 8 + gid];
            mma8(o[ntd], a, bf);
        }
    }

    const int px = px0 + warp * 16 + gid;
#pragma unroll
    for (int ntd = 0; ntd < 4; ntd++) {
        int d = ntd * 8 + 2 * qid;
        size_t c0 = ((size_t)(b * C1) + d * 4 + head) * HW;
        size_t c1 = ((size_t)(b * C1) + (d + 1) * 4 + head) * HW;
        outp[c0 + px]     = o[ntd][0] * inv0;
        outp[c1 + px]     = o[ntd][1] * inv0;
        outp[c0 + px + 8] = o[ntd][2] * inv1;
        outp[c1 + px + 8] = o[ntd][3] * inv1;
    }
}

// ---------------- host orchestration ----------------
extern "C" void kernel_launch(void* const* d_in, const int* in_sizes, int n_in,
                              void* d_out, int out_size) {
    (void)in_sizes; (void)n_in; (void)out_size;
    const float* x        = (const float*)d_in[0];
    const float* bb_bn1_g = (const float*)d_in[1];
    const float* bb_bn1_b = (const float*)d_in[2];
    const float* bb_conv1 = (const float*)d_in[3];
    const float* bb_bn2_g = (const float*)d_in[4];
    const float* bb_bn2_b = (const float*)d_in[5];
    const float* bb_conv2 = (const float*)d_in[6];
    const float* bb_sbn_g = (const float*)d_in[7];
    const float* bb_sbn_b = (const float*)d_in[8];
    const float* bb_sconv = (const float*)d_in[9];
    const float* tb_bn1_g = (const float*)d_in[10];
    const float* tb_bn1_b = (const float*)d_in[11];
    const float* tb_dwqkv = (const float*)d_in[12];
    const float* tb_pwqkv = (const float*)d_in[13];
    const float* tb_dwout = (const float*)d_in[14];
    const float* tb_pwout = (const float*)d_in[15];
    const float* tb_rel   = (const float*)d_in[16];
    const float* tb_bn2_g = (const float*)d_in[17];
    const float* tb_bn2_b = (const float*)d_in[18];
    const float* tb_mlp   = (const float*)d_in[19];

    void* pv;
    float *pool, *t, *u, *o, *qkv;
    cudaGetSymbolAddress(&pv, g_pool); pool = (float*)pv;
    cudaGetSymbolAddress(&pv, g_t);    t    = (float*)pv;
    cudaGetSymbolAddress(&pv, g_u);    u    = (float*)pv;
    cudaGetSymbolAddress(&pv, g_o);    o    = (float*)pv;
    cudaGetSymbolAddress(&pv, g_qkv);  qkv  = (float*)pv;

    const int ATTN_SMEM = (2 * 256 * 36 + 64 * 36) * 4 + 961 * 4;   // 86788
    cudaFuncSetAttribute(k_attn, cudaFuncAttributeMaxDynamicSharedMemorySize, ATTN_SMEM);

    const dim3 g1(NPIX / 128, 1);
    const dim3 g3(NPIX / 128, 3);
    const dim3 ga(HW / 64, B * 4);

    // ---- one-shot weight conversion (all 9 tensors) ----
    WArgs wa;
    wa.s[0] = { bb_conv1, WO_CONV1, 128 * 576 };
    wa.s[1] = { bb_conv2, WO_CONV2, 128 * 1152 };
    wa.s[2] = { bb_sconv, WO_SCONV, 128 * 64 };
    wa.s[3] = { tb_pwqkv,               WO_TB,                       384 * 128 };
    wa.s[4] = { tb_pwout,               WO_TB + 49152,               128 * 128 };
    wa.s[5] = { tb_mlp,                 WO_TB + 65536,               128 * 128 };
    wa.s[6] = { tb_pwqkv + 384 * 128,   WO_TB + WO_BLK,              384 * 128 };
    wa.s[7] = { tb_pwout + 128 * 128,   WO_TB + WO_BLK + 49152,      128 * 128 };
    wa.s[8] = { tb_mlp + 128 * 128,     WO_TB + WO_BLK + 65536,      128 * 128 };
    k_wprep_all<<<W_TOTAL / 1024, 256>>>(wa);

    k_maxpool<<<(B * C0 * HW) / 256, 256>>>(x, pool);

    // ---- BasicBlock ----
    k_bnpart<<<dim3(C0, 4), 256>>>(pool, bb_bn1_g, bb_bn1_b, C0, 0, bb_sbn_g, bb_sbn_b, 2);
    k_gemm<576, 64, true, true, true, false><<<g1, 256>>>(pool, u, nullptr, 128, 0, WO_CONV1);
    k_bnpart<<<dim3(C1, 4), 256>>>(u, bb_bn2_g, bb_bn2_b, C1, 1, nullptr, nullptr, 0);
    k_gemm<1152, 128, true, true, true, false><<<g1, 256>>>(u, o, nullptr, 128, 1, WO_CONV2);
    k_gemm<64, 64, false, true, true, true><<<g1, 256>>>(pool, o, o, 128, 2, WO_SCONV);

    // ---- 2 x BasicTransBlock (ping-pong residual between o and t) ----
    float* ob = o;
    float* tb = t;
    for (int i = 0; i < 2; i++) {
        const int wo = WO_TB + i * WO_BLK;
        k_bnpart<<<dim3(C1, 4), 256>>>(ob, tb_bn1_g + i * 128, tb_bn1_b + i * 128, C1, 3,
                                       nullptr, nullptr, 0);
        k_dw3<1><<<(B * C1 * HW) / 256, 256>>>(ob, tb_dwqkv + (size_t)i * 128 * 9, u, 3);
        k_gemm<128, 128, false, false, false, false><<<g3, 256>>>(u, qkv, nullptr, 384, 0, wo);
        k_ds<<<(B * 256 * R2) / 256, 256>>>(qkv);
        k_attn<<<ga, 128, ATTN_SMEM>>>(qkv, tb_rel + (size_t)i * 961 * 4, tb);
        k_dw3<0><<<(B * C1 * HW) / 256, 256>>>(tb, tb_dwout + (size_t)i * 128 * 9, u, 0);
        k_gemm<128, 128, false, false, false, true><<<g1, 256>>>(u, ob, ob, 128, 0, wo + 49152);
        k_bnpart<<<dim3(C1, 4), 256>>>(ob, tb_bn2_g + i * 128, tb_bn2_b + i * 128, C1, 4,
                                       nullptr, nullptr, 0);
        float* dest = (i == 1) ? (float*)d_out : tb;
        k_gemm<128, 128, false, true, true, true><<<g1, 256>>>(ob, dest, ob, 128, 4, wo + 65536);
        float* tmp = ob; ob = tb; tb = tmp;
    }
}

// round 9
// speedup vs baseline: 1.1604x; 1.0172x over previous
#include <cuda_runtime.h>
#include <cuda_fp16.h>
#include <cstdint>

// ---------------- problem constants ----------------
namespace {
constexpr int B    = 2;
constexpr int C0   = 64;
constexpr int C1   = 128;
constexpr int H    = 128, W = 128;
constexpr int HW   = H * W;            // 16384
constexpr int NPIX = B * HW;           // 32768
constexpr int R2   = 256;              // 16x16 reduced K/V
constexpr int DH   = 32;               // dim_head
constexpr float BN_EPS = 1e-5f;
// fp16 weight arena offsets
constexpr int WO_CONV1 = 0;                        // 128*576
constexpr int WO_CONV2 = 73728;                    // 128*1152
constexpr int WO_SCONV = 221184;                   // 128*64
constexpr int WO_TB    = 229376;                   // per block: qkv 49152, pwout 16384, mlp 16384
constexpr int WO_BLK   = 81920;
constexpr int W_TOTAL  = 393216;
}

// ---------------- scratch (static device, no allocs) ----------------
__device__ float g_pool[B * C0 * HW];
__device__ float g_t   [B * C1 * HW];
__device__ float g_u   [B * C1 * HW];
__device__ float g_o   [B * C1 * HW];
__device__ float g_qkv [B * 3 * C1 * HW];
__device__ float g_kd  [B * C1 * R2];
__device__ float g_vd  [B * C1 * R2];
__device__ __align__(16) __half g_wth[W_TOTAL];   // pre-converted fp16 weights
__device__ double2 g_part[128][4];
__device__ unsigned g_cnt = 0;
__device__ float g_A   [8 * 128];
__device__ float g_Bv  [8 * 128];

// ---------------- helpers ----------------
__device__ __forceinline__ unsigned f2tf(float x) {
    unsigned r;
    asm("cvt.rna.tf32.f32 %0, %1;" : "=r"(r) : "f"(x));
    return r;
}
__device__ __forceinline__ void mma8(float c[4], const unsigned a[4], const unsigned b[2]) {
    asm volatile(
        "mma.sync.aligned.m16n8k8.row.col.f32.tf32.tf32.f32 "
        "{%0,%1,%2,%3},{%4,%5,%6,%7},{%8,%9},{%0,%1,%2,%3};"
        : "+f"(c[0]), "+f"(c[1]), "+f"(c[2]), "+f"(c[3])
        : "r"(a[0]), "r"(a[1]), "r"(a[2]), "r"(a[3]), "r"(b[0]), "r"(b[1]));
}
__device__ __forceinline__ void mma16(float c[4], const unsigned a[4], const unsigned b[2]) {
    asm volatile(
        "mma.sync.aligned.m16n8k16.row.col.f32.f16.f16.f32 "
        "{%0,%1,%2,%3},{%4,%5,%6,%7},{%8,%9},{%0,%1,%2,%3};"
        : "+f"(c[0]), "+f"(c[1]), "+f"(c[2]), "+f"(c[3])
        : "r"(a[0]), "r"(a[1]), "r"(a[2]), "r"(a[3]), "r"(b[0]), "r"(b[1]));
}
__device__ __forceinline__ void ldm4(unsigned a[4], const void* p) {
    unsigned addr = (unsigned)__cvta_generic_to_shared(p);
    asm volatile("ldmatrix.sync.aligned.m8n8.x4.shared.b16 {%0,%1,%2,%3}, [%4];"
        : "=r"(a[0]), "=r"(a[1]), "=r"(a[2]), "=r"(a[3]) : "r"(addr));
}
__device__ __forceinline__ void cpa16(void* dst, const void* src) {
    unsigned d = (unsigned)__cvta_generic_to_shared(dst);
    asm volatile("cp.async.ca.shared.global [%0], [%1], 16;" :: "r"(d), "l"(src));
}
__device__ __forceinline__ unsigned h2u(__half2 h) {
    return *reinterpret_cast<unsigned*>(&h);
}

// ---------------- weight pre-convert fp32 -> fp16 (one launch) ----------------
// cin == 0: plain copy. cin > 0: 3x3 conv tensor, transpose k-order
// dst[co][q*cin+ci] = src[co][ci*9+q]  (offset-major im2col layout).
struct WSeg { const float* src; int dst; int n; int cin; };
struct WArgs { WSeg s[9]; };
__global__ void k_wprep_all(WArgs a) {
    int i = (blockIdx.x * 256 + threadIdx.x) * 4;
#pragma unroll
    for (int t = 0; t < 9; t++) {
        if (i < a.s[t].n) {
            float v0, v1, v2, v3;
            if (a.s[t].cin == 0) {
                float4 v = *reinterpret_cast<const float4*>(a.s[t].src + i);
                v0 = v.x; v1 = v.y; v2 = v.z; v3 = v.w;
            } else {
                int cin = a.s[t].cin;
                int K = cin * 9;
                int co = i / K, r = i - co * K;
                int q = r / cin, ci = r - q * cin;   // 4 consecutive ci share co,q
                const float* s = a.s[t].src + (size_t)co * K + ci * 9 + q;
                v0 = s[0]; v1 = s[9]; v2 = s[18]; v3 = s[27];
            }
            uint2 pk;
            pk.x = h2u(__floats2half2_rn(v0, v1));
            pk.y = h2u(__floats2half2_rn(v2, v3));
            *reinterpret_cast<uint2*>(g_wth + a.s[t].dst + i) = pk;
            return;
        }
        i -= a.s[t].n;
    }
}

// ---------------- maxpool 2x2 (256x256 -> 128x128) ----------------
__global__ void k_maxpool(const float* __restrict__ x, float* __restrict__ out) {
    int i = blockIdx.x * 256 + threadIdx.x;
    int p  = i & (HW - 1);
    int bc = i >> 14;
    int y = p >> 7, xx = p & 127;
    const float* ip = x + (size_t)bc * 65536 + (size_t)(y * 2) * 256 + xx * 2;
    out[i] = fmaxf(fmaxf(ip[0], ip[1]), fmaxf(ip[256], ip[257]));
}

// ---------------- BN stats: partials + last-block finalize (1 or 2 slots) ----------------
__global__ void k_bnpart(const float* __restrict__ x, const float* __restrict__ gg,
                         const float* __restrict__ bb, int Cc, int slot,
                         const float* __restrict__ gg2, const float* __restrict__ bb2,
                         int slot2) {
    int c = blockIdx.x, part = blockIdx.y;
    int tid = threadIdx.x;
    int lane = tid & 31, wid = tid >> 5;
    const float4* x0 = reinterpret_cast<const float4*>(x + (size_t)c * HW) + part * (HW / 16);
    const float4* x1 = reinterpret_cast<const float4*>(x + (size_t)(Cc + c) * HW) + part * (HW / 16);
    float s = 0.f, s2 = 0.f;
#pragma unroll
    for (int it = 0; it < 4; it++) {
        int p = tid + it * 256;
        float4 a = x0[p];
        s += a.x + a.y + a.z + a.w;
        s2 = fmaf(a.x, a.x, fmaf(a.y, a.y, fmaf(a.z, a.z, fmaf(a.w, a.w, s2))));
        float4 d = x1[p];
        s += d.x + d.y + d.z + d.w;
        s2 = fmaf(d.x, d.x, fmaf(d.y, d.y, fmaf(d.z, d.z, fmaf(d.w, d.w, s2))));
    }
#pragma unroll
    for (int off = 16; off > 0; off >>= 1) {
        s  += __shfl_down_sync(0xffffffffu, s, off);
        s2 += __shfl_down_sync(0xffffffffu, s2, off);
    }
    __shared__ double ws[8], wq[8];
    __shared__ bool lastf;
    if (lane == 0) { ws[wid] = (double)s; wq[wid] = (double)s2; }
    __syncthreads();
    if (tid == 0) {
        double S = 0., Q = 0.;
#pragma unroll
        for (int w = 0; w < 8; w++) { S += ws[w]; Q += wq[w]; }
        g_part[c][part] = make_double2(S, Q);
        __threadfence();
        unsigned v = atomicAdd(&g_cnt, 1u);
        lastf = (v == (unsigned)(Cc * 4 - 1));
    }
    __syncthreads();
    if (lastf) {
        __threadfence();
        int cc = tid;
        if (cc < Cc) {
            double ss = 0., q = 0.;
#pragma unroll
            for (int p = 0; p < 4; p++) { ss += g_part[cc][p].x; q += g_part[cc][p].y; }
            double mean = ss / (double)NPIX;
            double var  = q / (double)NPIX - mean * mean;
            double rstd = 1.0 / sqrt(var + (double)BN_EPS);
            double A    = (double)gg[cc] * rstd;
            g_A[slot * 128 + cc]  = (float)A;
            g_Bv[slot * 128 + cc] = (float)((double)bb[cc] - mean * A);
            if (gg2) {
                double A2 = (double)gg2[cc] * rstd;
                g_A[slot2 * 128 + cc]  = (float)A2;
                g_Bv[slot2 * 128 + cc] = (float)((double)bb2[cc] - mean * A2);
            }
        }
        if (tid == 0) g_cnt = 0;
    }
}

// ---------------- fp16 GEMM: C[M,N] = W[M,K] @ X[K,N] (+add) ----------------
// Block 128x128, 256 thr = 8 warps (m64 x n32), K-chunk 32 (2 x k16 mma steps).
// IC: offset-major im2col, k' = q*CIN + ci -> each 32-chunk has ONE (dy,dx).
template <int K, int CIN, bool IC, bool BN, bool RELU, bool ADD>
__global__ __launch_bounds__(256)
void k_gemm(const float* __restrict__ in,
            float* __restrict__ out, const float* __restrict__ add,
            int COUT, int slot, int woff) {
    __shared__ __align__(16) __half sA[128 * 40];
    __shared__ __align__(16) __half sB[16 * 272];

    const int tid = threadIdx.x;
    const int lane = tid & 31, warp = tid >> 5;
    const int gid = lane >> 2, qid = lane & 3;
    const int wm = (warp & 1) * 64, wn = (warp >> 1) * 32;

    const int n0 = blockIdx.x * 128;
    const int m0 = blockIdx.y * 128;
    const int b  = n0 >> 14;
    const int pbase = n0 & (HW - 1);
    const int y = pbase >> 7;

    const float* Ap = g_A  + slot * 128;
    const float* Bp = g_Bv + slot * 128;
    const __half* wbase = g_wth + woff;
    const float* inb = in + (size_t)b * CIN * HW;

    float c[4][4][4];
#pragma unroll
    for (int mt = 0; mt < 4; mt++)
#pragma unroll
        for (int nt = 0; nt < 4; nt++)
#pragma unroll
            for (int e = 0; e < 4; e++) c[mt][nt][e] = 0.f;

    const int a_row = tid >> 1;            // 0..127
    const int a_c   = (tid & 1) * 16;      // 0 or 16
    const int colg  = tid & 31;            // 4-px group
    const int kp    = tid >> 5;            // kpair 0..7 (+8)

    __half* a_ld = sA + (wm + (lane & 15)) * 40 + ((lane >> 4) << 3);
    const unsigned* sbw = reinterpret_cast<const unsigned*>(sB);

    for (int k0 = 0; k0 < K; k0 += 32) {
        __syncthreads();
        // ---- A: cp.async fp16 weights ----
        {
            const __half* src = wbase + (size_t)(m0 + a_row) * K + k0 + a_c;
            __half* dst = sA + a_row * 40 + a_c;
            cpa16(dst, src);
            cpa16(dst + 8, src + 8);
        }
        asm volatile("cp.async.commit_group;");
        // ---- B staging ----
        if (IC) {
            // one (dy,dx) per chunk: all hoisted
            const int q  = k0 / CIN;
            const int cb = k0 - q * CIN;       // base ci (multiple of 32)
            const int dy = q / 3 - 1, dx = q - (q / 3) * 3 - 1;
            const int gy = y + dy;
            const bool yok = (unsigned)gy < 128u;
            const float* rowp = inb + gy * 128;
            const int xbase = colg * 4 + dx;
#pragma unroll
            for (int it = 0; it < 2; it++) {
                int kpair = kp + it * 8;
                int ci0 = cb + kpair * 2;
                float ve[4], vo[4];
#pragma unroll
                for (int half = 0; half < 2; half++) {
                    int ci = ci0 + half;
                    float* v = half ? vo : ve;
                    float A = 1.f, Bb = 0.f;
                    if (BN) { A = Ap[ci]; Bb = Bp[ci]; }
                    const float* src = rowp + (size_t)ci * HW;
#pragma unroll
                    for (int e = 0; e < 4; e++) {
                        int gx = xbase + e;
                        float vv = 0.f;
                        if (yok && (unsigned)gx < 128u) {
                            vv = src[gx];
                            if (BN) vv = fmaf(vv, A, Bb);
                            if (RELU) vv = fmaxf(vv, 0.f);
                        }
                        v[e] = vv;
                    }
                }
                uint4 pk;
                pk.x = h2u(__floats2half2_rn(ve[0], vo[0]));
                pk.y = h2u(__floats2half2_rn(ve[1], vo[1]));
                pk.z = h2u(__floats2half2_rn(ve[2], vo[2]));
                pk.w = h2u(__floats2half2_rn(ve[3], vo[3]));
                *reinterpret_cast<uint4*>(sB + kpair * 272 + colg * 8) = pk;
            }
        } else {
#pragma unroll
            for (int it = 0; it < 2; it++) {
                int kpair = kp + it * 8;
                int ke = k0 + kpair * 2;
                float ve[4], vo[4];
#pragma unroll
                for (int half = 0; half < 2; half++) {
                    int k = ke + half;
                    float* v = half ? vo : ve;
                    float4 xv = *reinterpret_cast<const float4*>(
                        inb + (size_t)k * HW + pbase + colg * 4);
                    if (BN) {
                        float A = Ap[k], Bb = Bp[k];
                        xv.x = fmaf(xv.x, A, Bb); xv.y = fmaf(xv.y, A, Bb);
                        xv.z = fmaf(xv.z, A, Bb); xv.w = fmaf(xv.w, A, Bb);
                        if (RELU) {
                            xv.x = fmaxf(xv.x, 0.f); xv.y = fmaxf(xv.y, 0.f);
                            xv.z = fmaxf(xv.z, 0.f); xv.w = fmaxf(xv.w, 0.f);
                        }
                    }
                    v[0] = xv.x; v[1] = xv.y; v[2] = xv.z; v[3] = xv.w;
                }
                uint4 pk;
                pk.x = h2u(__floats2half2_rn(ve[0], vo[0]));
                pk.y = h2u(__floats2half2_rn(ve[1], vo[1]));
                pk.z = h2u(__floats2half2_rn(ve[2], vo[2]));
                pk.w = h2u(__floats2half2_rn(ve[3], vo[3]));
                *reinterpret_cast<uint4*>(sB + kpair * 272 + colg * 8) = pk;
            }
        }
        asm volatile("cp.async.wait_group 0;");
        __syncthreads();
        // ---- mma: 2 k16 steps ----
#pragma unroll
        for (int ks = 0; ks < 2; ks++) {
            unsigned af[4][4], bf[4][2];
#pragma unroll
            for (int mt = 0; mt < 4; mt++)
                ldm4(af[mt], a_ld + mt * 16 * 40 + ks * 16);
#pragma unroll
            for (int nt = 0; nt < 4; nt++) {
                int n = wn + nt * 8 + gid;
                bf[nt][0] = sbw[(8 * ks + qid) * 136 + n];
                bf[nt][1] = sbw[(8 * ks + qid + 4) * 136 + n];
            }
#pragma unroll
            for (int mt = 0; mt < 4; mt++)
#pragma unroll
                for (int nt = 0; nt < 4; nt++)
                    mma16(c[mt][nt], af[mt], bf[nt]);
        }
    }

#pragma unroll
    for (int mt = 0; mt < 4; mt++) {
        int co = m0 + wm + mt * 16 + gid;
#pragma unroll
        for (int nt = 0; nt < 4; nt++) {
            int cb = wn + nt * 8 + qid * 2;
            size_t idx0 = ((size_t)(b * COUT) + co) * HW + pbase + cb;
            size_t idx1 = ((size_t)(b * COUT) + co + 8) * HW + pbase + cb;
            float2 r0 = make_float2(c[mt][nt][0], c[mt][nt][1]);
            float2 r1 = make_float2(c[mt][nt][2], c[mt][nt][3]);
            if (ADD) {
                float2 a0 = *reinterpret_cast<const float2*>(add + idx0);
                float2 a1 = *reinterpret_cast<const float2*>(add + idx1);
                r0.x += a0.x; r0.y += a0.y; r1.x += a1.x; r1.y += a1.y;
            }
            *reinterpret_cast<float2*>(out + idx0) = r0;
            *reinterpret_cast<float2*>(out + idx1) = r1;
        }
    }
}

// ---------------- depthwise 3x3, pad=1, optional fused BN ----------------
template <int BN>
__global__ void k_dw3(const float* __restrict__ in, const float* __restrict__ w,
                      float* __restrict__ out, int slot) {
    int i = blockIdx.x * 256 + threadIdx.x;
    int p  = i & (HW - 1);
    int bc = i >> 14;
    int c  = bc & 127;
    int y = p >> 7, x = p & 127;
    const float* ip = in + (size_t)bc * HW;
    const float* wp = w + c * 9;
    float A = 1.f, Bb = 0.f;
    if (BN) { A = g_A[slot * 128 + c]; Bb = g_Bv[slot * 128 + c]; }
    float s = 0.f;
#pragma unroll
    for (int dy = 0; dy < 3; dy++) {
        int gy = y + dy - 1;
        if ((unsigned)gy >= 128u) continue;
#pragma unroll
        for (int dx = 0; dx < 3; dx++) {
            int gx = x + dx - 1;
            if ((unsigned)gx >= 128u) continue;
            float v = ip[gy * 128 + gx];
            if (BN) v = fmaf(v, A, Bb);
            s = fmaf(v, wp[dy * 3 + dx], s);
        }
    }
    out[i] = s;
}

// ---------------- bilinear downsample k,v: 128x128 -> 16x16 ----------------
__global__ void k_ds(const float* __restrict__ qkv) {
    int i = blockIdx.x * 256 + threadIdx.x;
    int j  = i & 255;
    int oc = (i >> 8) & 255;
    int b  = i >> 16;
    const float* ip = qkv + ((size_t)(b * 384) + 128 + oc) * HW;
    int r = j >> 4, s = j & 15;
    const float step = (float)(127.0 / 15.0);
    float ph = (float)r * step;
    int   lh = min((int)ph, 126);
    float fh = ph - (float)lh;
    float pw = (float)s * step;
    int   lw = min((int)pw, 126);
    float fw = pw - (float)lw;
    const float* p0 = ip + lh * 128 + lw;
    float v00 = p0[0], v01 = p0[1], v10 = p0[128], v11 = p0[129];
    float val = (1.f - fh) * ((1.f - fw) * v00 + fw * v01)
              +        fh  * ((1.f - fw) * v10 + fw * v11);
    float* dst = (oc < 128) ? g_kd : g_vd;
    int cc = oc & 127;
    dst[(size_t)(b * 128 + cc) * R2 + j] = val;
}

// ---------------- tensor-core attention (tf32) ----------------
__global__ __launch_bounds__(128)
void k_attn(const float* __restrict__ qkv, const float* __restrict__ table,
            float* __restrict__ outp) {
    extern __shared__ unsigned smu[];
    unsigned* k_s = smu;                    // [256][36]
    unsigned* v_s = smu + 256 * 36;         // [256][36]
    unsigned* q_s = v_s + 256 * 36;         // [64][36]
    float*    t_s = reinterpret_cast<float*>(q_s + 64 * 36);   // [961]

    const int tid  = threadIdx.x;
    const int lane = tid & 31, warp = tid >> 5;
    const int gid  = lane >> 2, qid = lane & 3;
    const int bh   = blockIdx.y;
    const int b = bh >> 2, head = bh & 3;
    const int px0 = blockIdx.x * 64;
    const float scale = 0.17677669529663687f;

    for (int i = tid; i < 256 * 32; i += 128) {
        int j = i & 255, d = i >> 8;
        size_t gi = ((size_t)(b * C1) + d * 4 + head) * R2 + j;
        k_s[j * 36 + d] = f2tf(g_kd[gi]);
        v_s[j * 36 + d] = f2tf(g_vd[gi]);
    }
    for (int i = tid; i < 64 * 32; i += 128) {
        int r = i & 63, d = i >> 6;
        q_s[r * 36 + d] = f2tf(qkv[((size_t)(b * 384) + d * 4 + head) * HW + px0 + r] * scale);
    }
    for (int i = tid; i < 961; i += 128) t_s[i] = table[i * 4 + head] * scale;
    __syncthreads();

    unsigned aq[4][4];
#pragma unroll
    for (int kc = 0; kc < 4; kc++) {
        const unsigned* sa = q_s + (warp * 16 + gid) * 36 + kc * 8 + qid;
        aq[kc][0] = sa[0];
        aq[kc][1] = sa[8 * 36];
        aq[kc][2] = sa[4];
        aq[kc][3] = sa[8 * 36 + 4];
    }
    float s[32][4];
#pragma unroll
    for (int nt = 0; nt < 32; nt++) { s[nt][0]=s[nt][1]=s[nt][2]=s[nt][3]=0.f; }
#pragma unroll
    for (int nt = 0; nt < 32; nt++) {
        const unsigned* kb = k_s + (nt * 8 + gid) * 36;
#pragma unroll
        for (int kc = 0; kc < 4; kc++) {
            unsigned bf[2];
            bf[0] = kb[kc * 8 + qid];
            bf[1] = kb[kc * 8 + qid + 4];
            mma8(s[nt], aq[kc], bf);
        }
    }

    const int xb = (px0 & 127) + warp * 16;
    const int rh = (px0 >> 7) >> 3;
    const int base0 = (rh + 15) * 31 + ((xb + gid) >> 3) + 15;
    const int base1 = (rh + 15) * 31 + ((xb + gid + 8) >> 3) + 15;
    float l0 = 0.f, l1 = 0.f;
#pragma unroll
    for (int nt = 0; nt < 32; nt++) {
        int j = nt * 8 + 2 * qid;
        int off = (j >> 4) * 31 + (j & 15);
        float e0 = __expf(s[nt][0] + t_s[base0 - off]);
        float e1 = __expf(s[nt][1] + t_s[base0 - off - 1]);
        float e2 = __expf(s[nt][2] + t_s[base1 - off]);
        float e3 = __expf(s[nt][3] + t_s[base1 - off - 1]);
        s[nt][0] = e0; s[nt][1] = e1; s[nt][2] = e2; s[nt][3] = e3;
        l0 += e0 + e1; l1 += e2 + e3;
    }
    l0 += __shfl_xor_sync(0xffffffffu, l0, 1);
    l0 += __shfl_xor_sync(0xffffffffu, l0, 2);
    l1 += __shfl_xor_sync(0xffffffffu, l1, 1);
    l1 += __shfl_xor_sync(0xffffffffu, l1, 2);
    const float inv0 = 1.f / l0, inv1 = 1.f / l1;

    float o[4][4];
#pragma unroll
    for (int nt = 0; nt < 4; nt++) { o[nt][0]=o[nt][1]=o[nt][2]=o[nt][3]=0.f; }
    const int src0 = (lane & ~3) | (qid >> 1);
    const int src1 = src0 + 2;
    const bool odd = (qid & 1);
#pragma unroll
    for (int kc = 0; kc < 32; kc++) {
        float p0 = s[kc][0], p1 = s[kc][1], p2 = s[kc][2], p3 = s[kc][3];
        float v00 = __shfl_sync(0xffffffffu, p0, src0);
        float v01 = __shfl_sync(0xffffffffu, p1, src0);
        float v10 = __shfl_sync(0xffffffffu, p2, src0);
        float v11 = __shfl_sync(0xffffffffu, p3, src0);
        float v20 = __shfl_sync(0xffffffffu, p0, src1);
        float v21 = __shfl_sync(0xffffffffu, p1, src1);
        float v30 = __shfl_sync(0xffffffffu, p2, src1);
        float v31 = __shfl_sync(0xffffffffu, p3, src1);
        unsigned a[4];
        a[0] = f2tf(odd ? v01 : v00);
        a[1] = f2tf(odd ? v11 : v10);
        a[2] = f2tf(odd ? v21 : v20);
        a[3] = f2tf(odd ? v31 : v30);
        const unsigned* vb0 = v_s + (kc * 8 + qid) * 36;
        const unsigned* vb1 = v_s + (kc * 8 + qid + 4) * 36;
#pragma unroll
        for (int ntd = 0; ntd < 4; ntd++) {
            unsigned bf[2];
            bf[0] = vb0[ntd * 8 + gid];
            bf[1] = vb1[ntd * 8 + gid];
            mma8(o[ntd], a, bf);
        }
    }

    const int px = px0 + warp * 16 + gid;
#pragma unroll
    for (int ntd = 0; ntd < 4; ntd++) {
        int d = ntd * 8 + 2 * qid;
        size_t c0 = ((size_t)(b * C1) + d * 4 + head) * HW;
        size_t c1 = ((size_t)(b * C1) + (d + 1) * 4 + head) * HW;
        outp[c0 + px]     = o[ntd][0] * inv0;
        outp[c1 + px]     = o[ntd][1] * inv0;
        outp[c0 + px + 8] = o[ntd][2] * inv1;
        outp[c1 + px + 8] = o[ntd][3] * inv1;
    }
}

// ---------------- host orchestration ----------------
extern "C" void kernel_launch(void* const* d_in, const int* in_sizes, int n_in,
                              void* d_out, int out_size) {
    (void)in_sizes; (void)n_in; (void)out_size;
    const float* x        = (const float*)d_in[0];
    const float* bb_bn1_g = (const float*)d_in[1];
    const float* bb_bn1_b = (const float*)d_in[2];
    const float* bb_conv1 = (const float*)d_in[3];
    const float* bb_bn2_g = (const float*)d_in[4];
    const float* bb_bn2_b = (const float*)d_in[5];
    const float* bb_conv2 = (const float*)d_in[6];
    const float* bb_sbn_g = (const float*)d_in[7];
    const float* bb_sbn_b = (const float*)d_in[8];
    const float* bb_sconv = (const float*)d_in[9];
    const float* tb_bn1_g = (const float*)d_in[10];
    const float* tb_bn1_b = (const float*)d_in[11];
    const float* tb_dwqkv = (const float*)d_in[12];
    const float* tb_pwqkv = (const float*)d_in[13];
    const float* tb_dwout = (const float*)d_in[14];
    const float* tb_pwout = (const float*)d_in[15];
    const float* tb_rel   = (const float*)d_in[16];
    const float* tb_bn2_g = (const float*)d_in[17];
    const float* tb_bn2_b = (const float*)d_in[18];
    const float* tb_mlp   = (const float*)d_in[19];

    void* pv;
    float *pool, *t, *u, *o, *qkv;
    cudaGetSymbolAddress(&pv, g_pool); pool = (float*)pv;
    cudaGetSymbolAddress(&pv, g_t);    t    = (float*)pv;
    cudaGetSymbolAddress(&pv, g_u);    u    = (float*)pv;
    cudaGetSymbolAddress(&pv, g_o);    o    = (float*)pv;
    cudaGetSymbolAddress(&pv, g_qkv);  qkv  = (float*)pv;

    const int ATTN_SMEM = (2 * 256 * 36 + 64 * 36) * 4 + 961 * 4;   // 86788
    cudaFuncSetAttribute(k_attn, cudaFuncAttributeMaxDynamicSharedMemorySize, ATTN_SMEM);

    const dim3 g1(NPIX / 128, 1);
    const dim3 g3(NPIX / 128, 3);
    const dim3 ga(HW / 64, B * 4);

    // ---- one-shot weight conversion; 3x3 convs transposed to offset-major ----
    WArgs wa;
    wa.s[0] = { bb_conv1, WO_CONV1, 128 * 576,  64 };
    wa.s[1] = { bb_conv2, WO_CONV2, 128 * 1152, 128 };
    wa.s[2] = { bb_sconv, WO_SCONV, 128 * 64,   0 };
    wa.s[3] = { tb_pwqkv,               WO_TB,                       384 * 128, 0 };
    wa.s[4] = { tb_pwout,               WO_TB + 49152,               128 * 128, 0 };
    wa.s[5] = { tb_mlp,                 WO_TB + 65536,               128 * 128, 0 };
    wa.s[6] = { tb_pwqkv + 384 * 128,   WO_TB + WO_BLK,              384 * 128, 0 };
    wa.s[7] = { tb_pwout + 128 * 128,   WO_TB + WO_BLK + 49152,      128 * 128, 0 };
    wa.s[8] = { tb_mlp + 128 * 128,     WO_TB + WO_BLK + 65536,      128 * 128, 0 };
    k_wprep_all<<<W_TOTAL / 1024, 256>>>(wa);

    k_maxpool<<<(B * C0 * HW) / 256, 256>>>(x, pool);

    // ---- BasicBlock ----
    k_bnpart<<<dim3(C0, 4), 256>>>(pool, bb_bn1_g, bb_bn1_b, C0, 0, bb_sbn_g, bb_sbn_b, 2);
    k_gemm<576, 64, true, true, true, false><<<g1, 256>>>(pool, u, nullptr, 128, 0, WO_CONV1);
    k_bnpart<<<dim3(C1, 4), 256>>>(u, bb_bn2_g, bb_bn2_b, C1, 1, nullptr, nullptr, 0);
    k_gemm<1152, 128, true, true, true, false><<<g1, 256>>>(u, o, nullptr, 128, 1, WO_CONV2);
    k_gemm<64, 64, false, true, true, true><<<g1, 256>>>(pool, o, o, 128, 2, WO_SCONV);

    // ---- 2 x BasicTransBlock (ping-pong residual between o and t) ----
    float* ob = o;
    float* tb = t;
    for (int i = 0; i < 2; i++) {
        const int wo = WO_TB + i * WO_BLK;
        k_bnpart<<<dim3(C1, 4), 256>>>(ob, tb_bn1_g + i * 128, tb_bn1_b + i * 128, C1, 3,
                                       nullptr, nullptr, 0);
        k_dw3<1><<<(B * C1 * HW) / 256, 256>>>(ob, tb_dwqkv + (size_t)i * 128 * 9, u, 3);
        k_gemm<128, 128, false, false, false, false><<<g3, 256>>>(u, qkv, nullptr, 384, 0, wo);
        k_ds<<<(B * 256 * R2) / 256, 256>>>(qkv);
        k_attn<<<ga, 128, ATTN_SMEM>>>(qkv, tb_rel + (size_t)i * 961 * 4, tb);
        k_dw3<0><<<(B * C1 * HW) / 256, 256>>>(tb, tb_dwout + (size_t)i * 128 * 9, u, 0);
        k_gemm<128, 128, false, false, false, true><<<g1, 256>>>(u, ob, ob, 128, 0, wo + 49152);
        k_bnpart<<<dim3(C1, 4), 256>>>(ob, tb_bn2_g + i * 128, tb_bn2_b + i * 128, C1, 4,
                                       nullptr, nullptr, 0);
        float* dest = (i == 1) ? (float*)d_out : tb;
        k_gemm<128, 128, false, true, true, true><<<g1, 256>>>(ob, dest, ob, 128, 4, wo + 65536);
        float* tmp = ob; ob = tb; tb = tmp;
    }
}

// round 11
// speedup vs baseline: 1.2540x; 1.0807x over previous
#include <cuda_runtime.h>
#include <cuda_fp16.h>
#include <cstdint>

// ---------------- problem constants ----------------
namespace {
constexpr int B    = 2;
constexpr int C0   = 64;
constexpr int C1   = 128;
constexpr int H    = 128, W = 128;
constexpr int HW   = H * W;            // 16384
constexpr int NPIX = B * HW;           // 32768
constexpr int R2   = 256;              // 16x16 reduced K/V
constexpr int DH   = 32;               // dim_head
constexpr float BN_EPS = 1e-5f;
// fp16 weight arena offsets
constexpr int WO_CONV1 = 0;                        // 128*576
constexpr int WO_CONV2 = 73728;                    // 128*1152
constexpr int WO_SCONV = 221184;                   // 128*64
constexpr int WO_TB    = 229376;                   // per block: qkv 49152, pwout 16384, mlp 16384
constexpr int WO_BLK   = 81920;
constexpr int W_TOTAL  = 393216;
}

// ---------------- scratch (static device, no allocs) ----------------
__device__ float g_pool[B * C0 * HW];
__device__ float g_t   [B * C1 * HW];
__device__ float g_u   [B * C1 * HW];
__device__ float g_o   [B * C1 * HW];
__device__ float g_qkv [B * C1 * HW];        // q only now
__device__ float g_ud  [B * C1 * R2];        // downsampled u
__device__ float g_kd  [B * C1 * R2];
__device__ float g_vd  [B * C1 * R2];
__device__ __align__(16) __half g_wth[W_TOTAL];   // pre-converted fp16 weights
__device__ double2 g_part[128][4];
__device__ unsigned g_cnt = 0;
__device__ float g_A   [8 * 128];
__device__ float g_Bv  [8 * 128];

// ---------------- helpers ----------------
__device__ __forceinline__ unsigned f2tf(float x) {
    unsigned r;
    asm("cvt.rna.tf32.f32 %0, %1;" : "=r"(r) : "f"(x));
    return r;
}
__device__ __forceinline__ void mma8(float c[4], const unsigned a[4], const unsigned b[2]) {
    asm volatile(
        "mma.sync.aligned.m16n8k8.row.col.f32.tf32.tf32.f32 "
        "{%0,%1,%2,%3},{%4,%5,%6,%7},{%8,%9},{%0,%1,%2,%3};"
        : "+f"(c[0]), "+f"(c[1]), "+f"(c[2]), "+f"(c[3])
        : "r"(a[0]), "r"(a[1]), "r"(a[2]), "r"(a[3]), "r"(b[0]), "r"(b[1]));
}
__device__ __forceinline__ void mma16(float c[4], const unsigned a[4], const unsigned b[2]) {
    asm volatile(
        "mma.sync.aligned.m16n8k16.row.col.f32.f16.f16.f32 "
        "{%0,%1,%2,%3},{%4,%5,%6,%7},{%8,%9},{%0,%1,%2,%3};"
        : "+f"(c[0]), "+f"(c[1]), "+f"(c[2]), "+f"(c[3])
        : "r"(a[0]), "r"(a[1]), "r"(a[2]), "r"(a[3]), "r"(b[0]), "r"(b[1]));
}
__device__ __forceinline__ void ldm4(unsigned a[4], const void* p) {
    unsigned addr = (unsigned)__cvta_generic_to_shared(p);
    asm volatile("ldmatrix.sync.aligned.m8n8.x4.shared.b16 {%0,%1,%2,%3}, [%4];"
        : "=r"(a[0]), "=r"(a[1]), "=r"(a[2]), "=r"(a[3]) : "r"(addr));
}
__device__ __forceinline__ void cpa16(void* dst, const void* src) {
    unsigned d = (unsigned)__cvta_generic_to_shared(dst);
    asm volatile("cp.async.ca.shared.global [%0], [%1], 16;" :: "r"(d), "l"(src));
}
__device__ __forceinline__ unsigned h2u(__half2 h) {
    return *reinterpret_cast<unsigned*>(&h);
}

// ---------------- weight pre-convert fp32 -> fp16 (one launch) ----------------
// cin == 0: plain copy. cin > 0: 3x3 conv tensor, transpose to offset-major.
struct WSeg { const float* src; int dst; int n; int cin; };
struct WArgs { WSeg s[9]; };
__global__ void k_wprep_all(WArgs a) {
    int i = (blockIdx.x * 256 + threadIdx.x) * 4;
#pragma unroll
    for (int t = 0; t < 9; t++) {
        if (i < a.s[t].n) {
            float v0, v1, v2, v3;
            if (a.s[t].cin == 0) {
                float4 v = *reinterpret_cast<const float4*>(a.s[t].src + i);
                v0 = v.x; v1 = v.y; v2 = v.z; v3 = v.w;
            } else {
                int cin = a.s[t].cin;
                int K = cin * 9;
                int co = i / K, r = i - co * K;
                int q = r / cin, ci = r - q * cin;
                const float* s = a.s[t].src + (size_t)co * K + ci * 9 + q;
                v0 = s[0]; v1 = s[9]; v2 = s[18]; v3 = s[27];
            }
            uint2 pk;
            pk.x = h2u(__floats2half2_rn(v0, v1));
            pk.y = h2u(__floats2half2_rn(v2, v3));
            *reinterpret_cast<uint2*>(g_wth + a.s[t].dst + i) = pk;
            return;
        }
        i -= a.s[t].n;
    }
}

// ---------------- maxpool 2x2 (256x256 -> 128x128) ----------------
__global__ void k_maxpool(const float* __restrict__ x, float* __restrict__ out) {
    int i = blockIdx.x * 256 + threadIdx.x;
    int p  = i & (HW - 1);
    int bc = i >> 14;
    int y = p >> 7, xx = p & 127;
    const float* ip = x + (size_t)bc * 65536 + (size_t)(y * 2) * 256 + xx * 2;
    out[i] = fmaxf(fmaxf(ip[0], ip[1]), fmaxf(ip[256], ip[257]));
}

// ---------------- BN stats: partials + last-block finalize (1 or 2 slots) ----------------
__global__ void k_bnpart(const float* __restrict__ x, const float* __restrict__ gg,
                         const float* __restrict__ bb, int Cc, int slot,
                         const float* __restrict__ gg2, const float* __restrict__ bb2,
                         int slot2) {
    int c = blockIdx.x, part = blockIdx.y;
    int tid = threadIdx.x;
    int lane = tid & 31, wid = tid >> 5;
    const float4* x0 = reinterpret_cast<const float4*>(x + (size_t)c * HW) + part * (HW / 16);
    const float4* x1 = reinterpret_cast<const float4*>(x + (size_t)(Cc + c) * HW) + part * (HW / 16);
    float s = 0.f, s2 = 0.f;
#pragma unroll
    for (int it = 0; it < 4; it++) {
        int p = tid + it * 256;
        float4 a = x0[p];
        s += a.x + a.y + a.z + a.w;
        s2 = fmaf(a.x, a.x, fmaf(a.y, a.y, fmaf(a.z, a.z, fmaf(a.w, a.w, s2))));
        float4 d = x1[p];
        s += d.x + d.y + d.z + d.w;
        s2 = fmaf(d.x, d.x, fmaf(d.y, d.y, fmaf(d.z, d.z, fmaf(d.w, d.w, s2))));
    }
#pragma unroll
    for (int off = 16; off > 0; off >>= 1) {
        s  += __shfl_down_sync(0xffffffffu, s, off);
        s2 += __shfl_down_sync(0xffffffffu, s2, off);
    }
    __shared__ double ws[8], wq[8];
    __shared__ bool lastf;
    if (lane == 0) { ws[wid] = (double)s; wq[wid] = (double)s2; }
    __syncthreads();
    if (tid == 0) {
        double S = 0., Q = 0.;
#pragma unroll
        for (int w = 0; w < 8; w++) { S += ws[w]; Q += wq[w]; }
        g_part[c][part] = make_double2(S, Q);
        __threadfence();
        unsigned v = atomicAdd(&g_cnt, 1u);
        lastf = (v == (unsigned)(Cc * 4 - 1));
    }
    __syncthreads();
    if (lastf) {
        __threadfence();
        int cc = tid;
        if (cc < Cc) {
            double ss = 0., q = 0.;
#pragma unroll
            for (int p = 0; p < 4; p++) { ss += g_part[cc][p].x; q += g_part[cc][p].y; }
            double mean = ss / (double)NPIX;
            double var  = q / (double)NPIX - mean * mean;
            double rstd = 1.0 / sqrt(var + (double)BN_EPS);
            double A    = (double)gg[cc] * rstd;
            g_A[slot * 128 + cc]  = (float)A;
            g_Bv[slot * 128 + cc] = (float)((double)bb[cc] - mean * A);
            if (gg2) {
                double A2 = (double)gg2[cc] * rstd;
                g_A[slot2 * 128 + cc]  = (float)A2;
                g_Bv[slot2 * 128 + cc] = (float)((double)bb2[cc] - mean * A2);
            }
        }
        if (tid == 0) g_cnt = 0;
    }
}

// ---------------- fp16 GEMM: C[M,N] = W[M,K] @ X[K,N] (+add) ----------------
template <int K, int CIN, bool IC, bool BN, bool RELU, bool ADD>
__global__ __launch_bounds__(256)
void k_gemm(const float* __restrict__ in,
            float* __restrict__ out, const float* __restrict__ add,
            int COUT, int slot, int woff) {
    __shared__ __align__(16) __half sA[128 * 40];
    __shared__ __align__(16) __half sB[16 * 272];

    const int tid = threadIdx.x;
    const int lane = tid & 31, warp = tid >> 5;
    const int gid = lane >> 2, qid = lane & 3;
    const int wm = (warp & 1) * 64, wn = (warp >> 1) * 32;

    const int n0 = blockIdx.x * 128;
    const int m0 = blockIdx.y * 128;
    const int b  = n0 >> 14;
    const int pbase = n0 & (HW - 1);
    const int y = pbase >> 7;

    const float* Ap = g_A  + slot * 128;
    const float* Bp = g_Bv + slot * 128;
    const __half* wbase = g_wth + woff;
    const float* inb = in + (size_t)b * CIN * HW;

    float c[4][4][4];
#pragma unroll
    for (int mt = 0; mt < 4; mt++)
#pragma unroll
        for (int nt = 0; nt < 4; nt++)
#pragma unroll
            for (int e = 0; e < 4; e++) c[mt][nt][e] = 0.f;

    const int a_row = tid >> 1;
    const int a_c   = (tid & 1) * 16;
    const int colg  = tid & 31;
    const int kp    = tid >> 5;

    __half* a_ld = sA + (wm + (lane & 15)) * 40 + ((lane >> 4) << 3);
    const unsigned* sbw = reinterpret_cast<const unsigned*>(sB);

    for (int k0 = 0; k0 < K; k0 += 32) {
        __syncthreads();
        {
            const __half* src = wbase + (size_t)(m0 + a_row) * K + k0 + a_c;
            __half* dst = sA + a_row * 40 + a_c;
            cpa16(dst, src);
            cpa16(dst + 8, src + 8);
        }
        asm volatile("cp.async.commit_group;");
        if (IC) {
            const int q  = k0 / CIN;
            const int cb = k0 - q * CIN;
            const int dy = q / 3 - 1, dx = q - (q / 3) * 3 - 1;
            const int gy = y + dy;
            const bool yok = (unsigned)gy < 128u;
            const float* rowp = inb + gy * 128;
            const int xbase = colg * 4 + dx;
#pragma unroll
            for (int it = 0; it < 2; it++) {
                int kpair = kp + it * 8;
                int ci0 = cb + kpair * 2;
                float ve[4], vo[4];
#pragma unroll
                for (int half = 0; half < 2; half++) {
                    int ci = ci0 + half;
                    float* v = half ? vo : ve;
                    float A = 1.f, Bb = 0.f;
                    if (BN) { A = Ap[ci]; Bb = Bp[ci]; }
                    const float* src = rowp + (size_t)ci * HW;
#pragma unroll
                    for (int e = 0; e < 4; e++) {
                        int gx = xbase + e;
                        float vv = 0.f;
                        if (yok && (unsigned)gx < 128u) {
                            vv = src[gx];
                            if (BN) vv = fmaf(vv, A, Bb);
                            if (RELU) vv = fmaxf(vv, 0.f);
                        }
                        v[e] = vv;
                    }
                }
                uint4 pk;
                pk.x = h2u(__floats2half2_rn(ve[0], vo[0]));
                pk.y = h2u(__floats2half2_rn(ve[1], vo[1]));
                pk.z = h2u(__floats2half2_rn(ve[2], vo[2]));
                pk.w = h2u(__floats2half2_rn(ve[3], vo[3]));
                *reinterpret_cast<uint4*>(sB + kpair * 272 + colg * 8) = pk;
            }
        } else {
#pragma unroll
            for (int it = 0; it < 2; it++) {
                int kpair = kp + it * 8;
                int ke = k0 + kpair * 2;
                float ve[4], vo[4];
#pragma unroll
                for (int half = 0; half < 2; half++) {
                    int k = ke + half;
                    float* v = half ? vo : ve;
                    float4 xv = *reinterpret_cast<const float4*>(
                        inb + (size_t)k * HW + pbase + colg * 4);
                    if (BN) {
                        float A = Ap[k], Bb = Bp[k];
                        xv.x = fmaf(xv.x, A, Bb); xv.y = fmaf(xv.y, A, Bb);
                        xv.z = fmaf(xv.z, A, Bb); xv.w = fmaf(xv.w, A, Bb);
                        if (RELU) {
                            xv.x = fmaxf(xv.x, 0.f); xv.y = fmaxf(xv.y, 0.f);
                            xv.z = fmaxf(xv.z, 0.f); xv.w = fmaxf(xv.w, 0.f);
                        }
                    }
                    v[0] = xv.x; v[1] = xv.y; v[2] = xv.z; v[3] = xv.w;
                }
                uint4 pk;
                pk.x = h2u(__floats2half2_rn(ve[0], vo[0]));
                pk.y = h2u(__floats2half2_rn(ve[1], vo[1]));
                pk.z = h2u(__floats2half2_rn(ve[2], vo[2]));
                pk.w = h2u(__floats2half2_rn(ve[3], vo[3]));
                *reinterpret_cast<uint4*>(sB + kpair * 272 + colg * 8) = pk;
            }
        }
        asm volatile("cp.async.wait_group 0;");
        __syncthreads();
#pragma unroll
        for (int ks = 0; ks < 2; ks++) {
            unsigned af[4][4], bf[4][2];
#pragma unroll
            for (int mt = 0; mt < 4; mt++)
                ldm4(af[mt], a_ld + mt * 16 * 40 + ks * 16);
#pragma unroll
            for (int nt = 0; nt < 4; nt++) {
                int n = wn + nt * 8 + gid;
                bf[nt][0] = sbw[(8 * ks + qid) * 136 + n];
                bf[nt][1] = sbw[(8 * ks + qid + 4) * 136 + n];
            }
#pragma unroll
            for (int mt = 0; mt < 4; mt++)
#pragma unroll
                for (int nt = 0; nt < 4; nt++)
                    mma16(c[mt][nt], af[mt], bf[nt]);
        }
    }

#pragma unroll
    for (int mt = 0; mt < 4; mt++) {
        int co = m0 + wm + mt * 16 + gid;
#pragma unroll
        for (int nt = 0; nt < 4; nt++) {
            int cb = wn + nt * 8 + qid * 2;
            size_t idx0 = ((size_t)(b * COUT) + co) * HW + pbase + cb;
            size_t idx1 = ((size_t)(b * COUT) + co + 8) * HW + pbase + cb;
            float2 r0 = make_float2(c[mt][nt][0], c[mt][nt][1]);
            float2 r1 = make_float2(c[mt][nt][2], c[mt][nt][3]);
            if (ADD) {
                float2 a0 = *reinterpret_cast<const float2*>(add + idx0);
                float2 a1 = *reinterpret_cast<const float2*>(add + idx1);
                r0.x += a0.x; r0.y += a0.y; r1.x += a1.x; r1.y += a1.y;
            }
            *reinterpret_cast<float2*>(out + idx0) = r0;
            *reinterpret_cast<float2*>(out + idx1) = r1;
        }
    }
}

// ---------------- depthwise 3x3, pad=1, optional fused BN; 4 px/thread ----------------
template <int BN>
__global__ void k_dw3(const float* __restrict__ in, const float* __restrict__ w,
                      float* __restrict__ out, int slot) {
    int i = blockIdx.x * 256 + threadIdx.x;   // over B*C1*HW/4
    int idx = i * 4;
    int p  = idx & (HW - 1);
    int bc = idx >> 14;
    int c  = bc & 127;
    int y = p >> 7, x0 = p & 127;
    const float* ip = in + (size_t)bc * HW;
    const float* wp = w + c * 9;
    float A = 1.f, Bb = 0.f;
    if (BN) { A = g_A[slot * 128 + c]; Bb = g_Bv[slot * 128 + c]; }
    float acc[4] = {0.f, 0.f, 0.f, 0.f};
#pragma unroll
    for (int dy = 0; dy < 3; dy++) {
        int gy = y + dy - 1;
        if ((unsigned)gy >= 128u) continue;
        const float* r = ip + gy * 128;
        float4 m = *reinterpret_cast<const float4*>(r + x0);
        float v[6];
        v[0] = (x0 > 0)   ? r[x0 - 1] : 0.f;
        v[1] = m.x; v[2] = m.y; v[3] = m.z; v[4] = m.w;
        v[5] = (x0 < 124) ? r[x0 + 4] : 0.f;
        if (BN) {
            if (x0 > 0)   v[0] = fmaf(v[0], A, Bb);
            v[1] = fmaf(v[1], A, Bb); v[2] = fmaf(v[2], A, Bb);
            v[3] = fmaf(v[3], A, Bb); v[4] = fmaf(v[4], A, Bb);
            if (x0 < 124) v[5] = fmaf(v[5], A, Bb);
        }
        float w0 = wp[dy * 3], w1 = wp[dy * 3 + 1], w2 = wp[dy * 3 + 2];
#pragma unroll
        for (int e = 0; e < 4; e++)
            acc[e] = fmaf(v[e], w0, fmaf(v[e + 1], w1, fmaf(v[e + 2], w2, acc[e])));
    }
    *reinterpret_cast<float4*>(out + idx) =
        make_float4(acc[0], acc[1], acc[2], acc[3]);
}

// ---------------- bilinear downsample of u: 128x128 -> 16x16 (128 ch) ----------------
__global__ void k_ds2(const float* __restrict__ u) {
    int i = blockIdx.x * 256 + threadIdx.x;   // over B*128*R2 = 65536
    int j  = i & 255;
    int c  = (i >> 8) & 127;
    int b  = i >> 15;
    const float* ip = u + ((size_t)(b * C1) + c) * HW;
    int r = j >> 4, s = j & 15;
    const float step = (float)(127.0 / 15.0);
    float ph = (float)r * step;
    int   lh = min((int)ph, 126);
    float fh = ph - (float)lh;
    float pw = (float)s * step;
    int   lw = min((int)pw, 126);
    float fw = pw - (float)lw;
    const float* p0 = ip + lh * 128 + lw;
    float v00 = p0[0], v01 = p0[1], v10 = p0[128], v11 = p0[129];
    g_ud[i] = (1.f - fh) * ((1.f - fw) * v00 + fw * v01)
            +        fh  * ((1.f - fw) * v10 + fw * v11);
}

// ---------------- small fp32 GEMM: kd/vd = W_kv[256,128] @ ud[128,R2] ----------------
// grid (16, B): block og handles 16 output rows; 256 threads = j positions.
__global__ void k_kv(const float* __restrict__ w /* pwqkv fp32 */) {
    int og = blockIdx.x, b = blockIdx.y;
    int j = threadIdx.x;
    __shared__ float sw[16 * 128];
    for (int i = j; i < 16 * 128; i += 256)
        sw[i] = w[(size_t)(128 + og * 16) * 128 + i];
    __syncthreads();
    float acc[16];
#pragma unroll
    for (int r = 0; r < 16; r++) acc[r] = 0.f;
    const float* udb = g_ud + (size_t)b * C1 * R2 + j;
#pragma unroll 4
    for (int c = 0; c < 128; c++) {
        float v = udb[(size_t)c * R2];
#pragma unroll
        for (int r = 0; r < 16; r++) acc[r] = fmaf(sw[r * 128 + c], v, acc[r]);
    }
#pragma unroll
    for (int r = 0; r < 16; r++) {
        int oc = og * 16 + r;
        float* dst = (oc < 128) ? g_kd : g_vd;
        dst[((size_t)(b * C1) + (oc & 127)) * R2 + j] = acc[r];
    }
}

// ---------------- tensor-core attention (tf32) ----------------
__global__ __launch_bounds__(128)
void k_attn(const float* __restrict__ qbuf, const float* __restrict__ table,
            float* __restrict__ outp) {
    extern __shared__ unsigned smu[];
    unsigned* k_s = smu;                    // [256][36]
    unsigned* v_s = smu + 256 * 36;         // [256][36]
    unsigned* q_s = v_s + 256 * 36;         // [64][36]
    float*    t_s = reinterpret_cast<float*>(q_s + 64 * 36);   // [961]

    const int tid  = threadIdx.x;
    const int lane = tid & 31, warp = tid >> 5;
    const int gid  = lane >> 2, qid = lane & 3;
    const int bh   = blockIdx.y;
    const int b = bh >> 2, head = bh & 3;
    const int px0 = blockIdx.x * 64;
    const float scale = 0.17677669529663687f;

    for (int i = tid; i < 256 * 32; i += 128) {
        int j = i & 255, d = i >> 8;
        size_t gi = ((size_t)(b * C1) + d * 4 + head) * R2 + j;
        k_s[j * 36 + d] = f2tf(g_kd[gi]);
        v_s[j * 36 + d] = f2tf(g_vd[gi]);
    }
    for (int i = tid; i < 64 * 32; i += 128) {
        int r = i & 63, d = i >> 6;
        q_s[r * 36 + d] = f2tf(qbuf[((size_t)(b * C1) + d * 4 + head) * HW + px0 + r] * scale);
    }
    for (int i = tid; i < 961; i += 128) t_s[i] = table[i * 4 + head] * scale;
    __syncthreads();

    unsigned aq[4][4];
#pragma unroll
    for (int kc = 0; kc < 4; kc++) {
        const unsigned* sa = q_s + (warp * 16 + gid) * 36 + kc * 8 + qid;
        aq[kc][0] = sa[0];
        aq[kc][1] = sa[8 * 36];
        aq[kc][2] = sa[4];
        aq[kc][3] = sa[8 * 36 + 4];
    }
    float s[32][4];
#pragma unroll
    for (int nt = 0; nt < 32; nt++) { s[nt][0]=s[nt][1]=s[nt][2]=s[nt][3]=0.f; }
#pragma unroll
    for (int nt = 0; nt < 32; nt++) {
        const unsigned* kb = k_s + (nt * 8 + gid) * 36;
#pragma unroll
        for (int kc = 0; kc < 4; kc++) {
            unsigned bf[2];
            bf[0] = kb[kc * 8 + qid];
            bf[1] = kb[kc * 8 + qid + 4];
            mma8(s[nt], aq[kc], bf);
        }
    }

    const int xb = (px0 & 127) + warp * 16;
    const int rh = (px0 >> 7) >> 3;
    const int base0 = (rh + 15) * 31 + ((xb + gid) >> 3) + 15;
    const int base1 = (rh + 15) * 31 + ((xb + gid + 8) >> 3) + 15;
    float l0 = 0.f, l1 = 0.f;
#pragma unroll
    for (int nt = 0; nt < 32; nt++) {
        int j = nt * 8 + 2 * qid;
        int off = (j >> 4) * 31 + (j & 15);
        float e0 = __expf(s[nt][0] + t_s[base0 - off]);
        float e1 = __expf(s[nt][1] + t_s[base0 - off - 1]);
        float e2 = __expf(s[nt][2] + t_s[base1 - off]);
        float e3 = __expf(s[nt][3] + t_s[base1 - off - 1]);
        s[nt][0] = e0; s[nt][1] = e1; s[nt][2] = e2; s[nt][3] = e3;
        l0 += e0 + e1; l1 += e2 + e3;
    }
    l0 += __shfl_xor_sync(0xffffffffu, l0, 1);
    l0 += __shfl_xor_sync(0xffffffffu, l0, 2);
    l1 += __shfl_xor_sync(0xffffffffu, l1, 1);
    l1 += __shfl_xor_sync(0xffffffffu, l1, 2);
    const float inv0 = 1.f / l0, inv1 = 1.f / l1;

    float o[4][4];
#pragma unroll
    for (int nt = 0; nt < 4; nt++) { o[nt][0]=o[nt][1]=o[nt][2]=o[nt][3]=0.f; }
    const int src0 = (lane & ~3) | (qid >> 1);
    const int src1 = src0 + 2;
    const bool odd = (qid & 1);
#pragma unroll
    for (int kc = 0; kc < 32; kc++) {
        float p0 = s[kc][0], p1 = s[kc][1], p2 = s[kc][2], p3 = s[kc][3];
        float v00 = __shfl_sync(0xffffffffu, p0, src0);
        float v01 = __shfl_sync(0xffffffffu, p1, src0);
        float v10 = __shfl_sync(0xffffffffu, p2, src0);
        float v11 = __shfl_sync(0xffffffffu, p3, src0);
        float v20 = __shfl_sync(0xffffffffu, p0, src1);
        float v21 = __shfl_sync(0xffffffffu, p1, src1);
        float v30 = __shfl_sync(0xffffffffu, p2, src1);
        float v31 = __shfl_sync(0xffffffffu, p3, src1);
        unsigned a[4];
        a[0] = f2tf(odd ? v01 : v00);
        a[1] = f2tf(odd ? v11 : v10);
        a[2] = f2tf(odd ? v21 : v20);
        a[3] = f2tf(odd ? v31 : v30);
        const unsigned* vb0 = v_s + (kc * 8 + qid) * 36;
        const unsigned* vb1 = v_s + (kc * 8 + qid + 4) * 36;
#pragma unroll
        for (int ntd = 0; ntd < 4; ntd++) {
            unsigned bf[2];
            bf[0] = vb0[ntd * 8 + gid];
            bf[1] = vb1[ntd * 8 + gid];
            mma8(o[ntd], a, bf);
        }
    }

    const int px = px0 + warp * 16 + gid;
#pragma unroll
    for (int ntd = 0; ntd < 4; ntd++) {
        int d = ntd * 8 + 2 * qid;
        size_t c0 = ((size_t)(b * C1) + d * 4 + head) * HW;
        size_t c1 = ((size_t)(b * C1) + (d + 1) * 4 + head) * HW;
        outp[c0 + px]     = o[ntd][0] * inv0;
        outp[c1 + px]     = o[ntd][1] * inv0;
        outp[c0 + px + 8] = o[ntd][2] * inv1;
        outp[c1 + px + 8] = o[ntd][3] * inv1;
    }
}

// ---------------- host orchestration ----------------
extern "C" void kernel_launch(void* const* d_in, const int* in_sizes, int n_in,
                              void* d_out, int out_size) {
    (void)in_sizes; (void)n_in; (void)out_size;
    const float* x        = (const float*)d_in[0];
    const float* bb_bn1_g = (const float*)d_in[1];
    const float* bb_bn1_b = (const float*)d_in[2];
    const float* bb_conv1 = (const float*)d_in[3];
    const float* bb_bn2_g = (const float*)d_in[4];
    const float* bb_bn2_b = (const float*)d_in[5];
    const float* bb_conv2 = (const float*)d_in[6];
    const float* bb_sbn_g = (const float*)d_in[7];
    const float* bb_sbn_b = (const float*)d_in[8];
    const float* bb_sconv = (const float*)d_in[9];
    const float* tb_bn1_g = (const float*)d_in[10];
    const float* tb_bn1_b = (const float*)d_in[11];
    const float* tb_dwqkv = (const float*)d_in[12];
    const float* tb_pwqkv = (const float*)d_in[13];
    const float* tb_dwout = (const float*)d_in[14];
    const float* tb_pwout = (const float*)d_in[15];
    const float* tb_rel   = (const float*)d_in[16];
    const float* tb_bn2_g = (const float*)d_in[17];
    const float* tb_bn2_b = (const float*)d_in[18];
    const float* tb_mlp   = (const float*)d_in[19];

    void* pv;
    float *pool, *t, *u, *o, *qb;
    cudaGetSymbolAddress(&pv, g_pool); pool = (float*)pv;
    cudaGetSymbolAddress(&pv, g_t);    t    = (float*)pv;
    cudaGetSymbolAddress(&pv, g_u);    u    = (float*)pv;
    cudaGetSymbolAddress(&pv, g_o);    o    = (float*)pv;
    cudaGetSymbolAddress(&pv, g_qkv);  qb   = (float*)pv;

    const int ATTN_SMEM = (2 * 256 * 36 + 64 * 36) * 4 + 961 * 4;   // 86788
    cudaFuncSetAttribute(k_attn, cudaFuncAttributeMaxDynamicSharedMemorySize, ATTN_SMEM);

    const dim3 g1(NPIX / 128, 1);
    const dim3 ga(HW / 64, B * 4);

    // ---- one-shot weight conversion; 3x3 convs transposed to offset-major ----
    WArgs wa;
    wa.s[0] = { bb_conv1, WO_CONV1, 128 * 576,  64 };
    wa.s[1] = { bb_conv2, WO_CONV2, 128 * 1152, 128 };
    wa.s[2] = { bb_sconv, WO_SCONV, 128 * 64,   0 };
    wa.s[3] = { tb_pwqkv,               WO_TB,                       384 * 128, 0 };
    wa.s[4] = { tb_pwout,               WO_TB + 49152,               128 * 128, 0 };
    wa.s[5] = { tb_mlp,                 WO_TB + 65536,               128 * 128, 0 };
    wa.s[6] = { tb_pwqkv + 384 * 128,   WO_TB + WO_BLK,              384 * 128, 0 };
    wa.s[7] = { tb_pwout + 128 * 128,   WO_TB + WO_BLK + 49152,      128 * 128, 0 };
    wa.s[8] = { tb_mlp + 128 * 128,     WO_TB + WO_BLK + 65536,      128 * 128, 0 };
    k_wprep_all<<<W_TOTAL / 1024, 256>>>(wa);

    k_maxpool<<<(B * C0 * HW) / 256, 256>>>(x, pool);

    // ---- BasicBlock ----
    k_bnpart<<<dim3(C0, 4), 256>>>(pool, bb_bn1_g, bb_bn1_b, C0, 0, bb_sbn_g, bb_sbn_b, 2);
    k_gemm<576, 64, true, true, true, false><<<g1, 256>>>(pool, u, nullptr, 128, 0, WO_CONV1);
    k_bnpart<<<dim3(C1, 4), 256>>>(u, bb_bn2_g, bb_bn2_b, C1, 1, nullptr, nullptr, 0);
    k_gemm<1152, 128, true, true, true, false><<<g1, 256>>>(u, o, nullptr, 128, 1, WO_CONV2);
    k_gemm<64, 64, false, true, true, true><<<g1, 256>>>(pool, o, o, 128, 2, WO_SCONV);

    // ---- 2 x BasicTransBlock (ping-pong residual between o and t) ----
    float* ob = o;
    float* tb = t;
    for (int i = 0; i < 2; i++) {
        const int wo = WO_TB + i * WO_BLK;
        k_bnpart<<<dim3(C1, 4), 256>>>(ob, tb_bn1_g + i * 128, tb_bn1_b + i * 128, C1, 3,
                                       nullptr, nullptr, 0);
        k_dw3<1><<<(B * C1 * HW) / 1024, 256>>>(ob, tb_dwqkv + (size_t)i * 128 * 9, u, 3);
        // q = pw_q(u)  (rows 0..127 of pwqkv)
        k_gemm<128, 128, false, false, false, false><<<g1, 256>>>(u, qb, nullptr, 128, 0, wo);
        // kd/vd = pw_kv(ds(u))  -- ds commutes with 1x1 conv
        k_ds2<<<(B * C1 * R2) / 256, 256>>>(u);
        k_kv<<<dim3(16, B), 256>>>(tb_pwqkv + (size_t)i * 384 * 128);
        k_attn<<<ga, 128, ATTN_SMEM>>>(qb, tb_rel + (size_t)i * 961 * 4, tb);
        k_dw3<0><<<(B * C1 * HW) / 1024, 256>>>(tb, tb_dwout + (size_t)i * 128 * 9, u, 0);
        k_gemm<128, 128, false, false, false, true><<<g1, 256>>>(u, ob, ob, 128, 0, wo + 49152);
        k_bnpart<<<dim3(C1, 4), 256>>>(ob, tb_bn2_g + i * 128, tb_bn2_b + i * 128, C1, 4,
                                       nullptr, nullptr, 0);
        float* dest = (i == 1) ? (float*)d_out : tb;
        k_gemm<128, 128, false, true, true, true><<<g1, 256>>>(ob, dest, ob, 128, 4, wo + 65536);
        float* tmp = ob; ob = tb; tb = tmp;
    }
}

// round 12
// speedup vs baseline: 1.5437x; 1.2310x over previous
#include <cuda_runtime.h>
#include <cuda_fp16.h>
#include <cstdint>

// ---------------- problem constants ----------------
namespace {
constexpr int B    = 2;
constexpr int C0   = 64;
constexpr int C1   = 128;
constexpr int H    = 128, W = 128;
constexpr int HW   = H * W;            // 16384
constexpr int NPIX = B * HW;           // 32768
constexpr int R2   = 256;              // 16x16 reduced K/V
constexpr int DH   = 32;               // dim_head
constexpr float BN_EPS = 1e-5f;
// fp16 weight arena offsets
constexpr int WO_CONV1 = 0;
constexpr int WO_CONV2 = 73728;
constexpr int WO_SCONV = 221184;
constexpr int WO_TB    = 229376;
constexpr int WO_BLK   = 81920;
constexpr int W_TOTAL  = 393216;
constexpr int PARTS    = 8;
}

// ---------------- scratch (static device, no allocs) ----------------
__device__ float g_pool[B * C0 * HW];
__device__ float g_t   [B * C1 * HW];
__device__ float g_u   [B * C1 * HW];
__device__ float g_o   [B * C1 * HW];
__device__ float g_qkv [B * C1 * HW];        // q only
__device__ float g_ud  [B * C1 * R2];        // downsampled u
__device__ float g_kd  [B * C1 * R2];
__device__ float g_vd  [B * C1 * R2];
__device__ __align__(16) __half g_wth[W_TOTAL];
__device__ double2 g_part[128][PARTS];
__device__ unsigned g_cnt = 0;
__device__ float g_A   [8 * 128];
__device__ float g_Bv  [8 * 128];

// ---------------- helpers ----------------
__device__ __forceinline__ void mma16(float c[4], const unsigned a[4], const unsigned b[2]) {
    asm volatile(
        "mma.sync.aligned.m16n8k16.row.col.f32.f16.f16.f32 "
        "{%0,%1,%2,%3},{%4,%5,%6,%7},{%8,%9},{%0,%1,%2,%3};"
        : "+f"(c[0]), "+f"(c[1]), "+f"(c[2]), "+f"(c[3])
        : "r"(a[0]), "r"(a[1]), "r"(a[2]), "r"(a[3]), "r"(b[0]), "r"(b[1]));
}
__device__ __forceinline__ void ldm4(unsigned a[4], const void* p) {
    unsigned addr = (unsigned)__cvta_generic_to_shared(p);
    asm volatile("ldmatrix.sync.aligned.m8n8.x4.shared.b16 {%0,%1,%2,%3}, [%4];"
        : "=r"(a[0]), "=r"(a[1]), "=r"(a[2]), "=r"(a[3]) : "r"(addr));
}
__device__ __forceinline__ void cpa16(void* dst, const void* src) {
    unsigned d = (unsigned)__cvta_generic_to_shared(dst);
    asm volatile("cp.async.ca.shared.global [%0], [%1], 16;" :: "r"(d), "l"(src));
}
__device__ __forceinline__ unsigned h2u(__half2 h) {
    return *reinterpret_cast<unsigned*>(&h);
}
__device__ __forceinline__ unsigned packh2(float a, float b) {
    return h2u(__floats2half2_rn(a, b));
}

// ---------------- weight pre-convert fp32 -> fp16 (one launch) ----------------
struct WSeg { const float* src; int dst; int n; int cin; };
struct WArgs { WSeg s[9]; };
__global__ void k_wprep_all(WArgs a) {
    int i = (blockIdx.x * 256 + threadIdx.x) * 4;
#pragma unroll
    for (int t = 0; t < 9; t++) {
        if (i < a.s[t].n) {
            float v0, v1, v2, v3;
            if (a.s[t].cin == 0) {
                float4 v = *reinterpret_cast<const float4*>(a.s[t].src + i);
                v0 = v.x; v1 = v.y; v2 = v.z; v3 = v.w;
            } else {
                int cin = a.s[t].cin;
                int K = cin * 9;
                int co = i / K, r = i - co * K;
                int q = r / cin, ci = r - q * cin;
                const float* s = a.s[t].src + (size_t)co * K + ci * 9 + q;
                v0 = s[0]; v1 = s[9]; v2 = s[18]; v3 = s[27];
            }
            uint2 pk;
            pk.x = packh2(v0, v1);
            pk.y = packh2(v2, v3);
            *reinterpret_cast<uint2*>(g_wth + a.s[t].dst + i) = pk;
            return;
        }
        i -= a.s[t].n;
    }
}

// ---------------- maxpool 2x2 ----------------
__global__ void k_maxpool(const float* __restrict__ x, float* __restrict__ out) {
    int i = blockIdx.x * 256 + threadIdx.x;
    int p  = i & (HW - 1);
    int bc = i >> 14;
    int y = p >> 7, xx = p & 127;
    const float* ip = x + (size_t)bc * 65536 + (size_t)(y * 2) * 256 + xx * 2;
    out[i] = fmaxf(fmaxf(ip[0], ip[1]), fmaxf(ip[256], ip[257]));
}

// ---------------- BN stats: 8 partials + last-block finalize ----------------
__global__ void k_bnpart(const float* __restrict__ x, const float* __restrict__ gg,
                         const float* __restrict__ bb, int Cc, int slot,
                         const float* __restrict__ gg2, const float* __restrict__ bb2,
                         int slot2) {
    int c = blockIdx.x, part = blockIdx.y;
    int tid = threadIdx.x;
    int lane = tid & 31, wid = tid >> 5;
    const float4* x0 = reinterpret_cast<const float4*>(x + (size_t)c * HW) + part * (HW / (4 * PARTS));
    const float4* x1 = reinterpret_cast<const float4*>(x + (size_t)(Cc + c) * HW) + part * (HW / (4 * PARTS));
    float s = 0.f, s2 = 0.f;
#pragma unroll
    for (int it = 0; it < 2; it++) {
        int p = tid + it * 256;
        float4 a = x0[p];
        s += a.x + a.y + a.z + a.w;
        s2 = fmaf(a.x, a.x, fmaf(a.y, a.y, fmaf(a.z, a.z, fmaf(a.w, a.w, s2))));
        float4 d = x1[p];
        s += d.x + d.y + d.z + d.w;
        s2 = fmaf(d.x, d.x, fmaf(d.y, d.y, fmaf(d.z, d.z, fmaf(d.w, d.w, s2))));
    }
#pragma unroll
    for (int off = 16; off > 0; off >>= 1) {
        s  += __shfl_down_sync(0xffffffffu, s, off);
        s2 += __shfl_down_sync(0xffffffffu, s2, off);
    }
    __shared__ double ws[8], wq[8];
    __shared__ bool lastf;
    if (lane == 0) { ws[wid] = (double)s; wq[wid] = (double)s2; }
    __syncthreads();
    if (tid == 0) {
        double S = 0., Q = 0.;
#pragma unroll
        for (int w = 0; w < 8; w++) { S += ws[w]; Q += wq[w]; }
        g_part[c][part] = make_double2(S, Q);
        __threadfence();
        unsigned v = atomicAdd(&g_cnt, 1u);
        lastf = (v == (unsigned)(Cc * PARTS - 1));
    }
    __syncthreads();
    if (lastf) {
        __threadfence();
        int cc = tid;
        if (cc < Cc) {
            double ss = 0., q = 0.;
#pragma unroll
            for (int p = 0; p < PARTS; p++) { ss += g_part[cc][p].x; q += g_part[cc][p].y; }
            double mean = ss / (double)NPIX;
            double var  = q / (double)NPIX - mean * mean;
            double rstd = 1.0 / sqrt(var + (double)BN_EPS);
            double A    = (double)gg[cc] * rstd;
            g_A[slot * 128 + cc]  = (float)A;
            g_Bv[slot * 128 + cc] = (float)((double)bb[cc] - mean * A);
            if (gg2) {
                double A2 = (double)gg2[cc] * rstd;
                g_A[slot2 * 128 + cc]  = (float)A2;
                g_Bv[slot2 * 128 + cc] = (float)((double)bb2[cc] - mean * A2);
            }
        }
        if (tid == 0) g_cnt = 0;
    }
}

// ---------------- fp16 GEMM: C[M,N] = W[M,K] @ X[K,N] (+add) ----------------
template <int K, int CIN, bool IC, bool BN, bool RELU, bool ADD>
__global__ __launch_bounds__(256)
void k_gemm(const float* __restrict__ in,
            float* __restrict__ out, const float* __restrict__ add,
            int COUT, int slot, int woff) {
    __shared__ __align__(16) __half sA[128 * 40];
    __shared__ __align__(16) __half sB[16 * 272];

    const int tid = threadIdx.x;
    const int lane = tid & 31, warp = tid >> 5;
    const int gid = lane >> 2, qid = lane & 3;
    const int wm = (warp & 1) * 64, wn = (warp >> 1) * 32;

    const int n0 = blockIdx.x * 128;
    const int m0 = blockIdx.y * 128;
    const int b  = n0 >> 14;
    const int pbase = n0 & (HW - 1);
    const int y = pbase >> 7;

    const float* Ap = g_A  + slot * 128;
    const float* Bp = g_Bv + slot * 128;
    const __half* wbase = g_wth + woff;
    const float* inb = in + (size_t)b * CIN * HW;

    float c[4][4][4];
#pragma unroll
    for (int mt = 0; mt < 4; mt++)
#pragma unroll
        for (int nt = 0; nt < 4; nt++)
#pragma unroll
            for (int e = 0; e < 4; e++) c[mt][nt][e] = 0.f;

    const int a_row = tid >> 1;
    const int a_c   = (tid & 1) * 16;
    const int colg  = tid & 31;
    const int kp    = tid >> 5;

    __half* a_ld = sA + (wm + (lane & 15)) * 40 + ((lane >> 4) << 3);
    const unsigned* sbw = reinterpret_cast<const unsigned*>(sB);

    for (int k0 = 0; k0 < K; k0 += 32) {
        __syncthreads();
        {
            const __half* src = wbase + (size_t)(m0 + a_row) * K + k0 + a_c;
            __half* dst = sA + a_row * 40 + a_c;
            cpa16(dst, src);
            cpa16(dst + 8, src + 8);
        }
        asm volatile("cp.async.commit_group;");
        if (IC) {
            const int q  = k0 / CIN;
            const int cb = k0 - q * CIN;
            const int dy = q / 3 - 1, dx = q - (q / 3) * 3 - 1;
            const int gy = y + dy;
            const bool yok = (unsigned)gy < 128u;
            const float* rowp = inb + gy * 128;
            const int xbase = colg * 4 + dx;
#pragma unroll
            for (int it = 0; it < 2; it++) {
                int kpair = kp + it * 8;
                int ci0 = cb + kpair * 2;
                float ve[4], vo[4];
#pragma unroll
                for (int half = 0; half < 2; half++) {
                    int ci = ci0 + half;
                    float* v = half ? vo : ve;
                    float A = 1.f, Bb = 0.f;
                    if (BN) { A = Ap[ci]; Bb = Bp[ci]; }
                    const float* src = rowp + (size_t)ci * HW;
#pragma unroll
                    for (int e = 0; e < 4; e++) {
                        int gx = xbase + e;
                        float vv = 0.f;
                        if (yok && (unsigned)gx < 128u) {
                            vv = src[gx];
                            if (BN) vv = fmaf(vv, A, Bb);
                            if (RELU) vv = fmaxf(vv, 0.f);
                        }
                        v[e] = vv;
                    }
                }
                uint4 pk;
                pk.x = packh2(ve[0], vo[0]);
                pk.y = packh2(ve[1], vo[1]);
                pk.z = packh2(ve[2], vo[2]);
                pk.w = packh2(ve[3], vo[3]);
                *reinterpret_cast<uint4*>(sB + kpair * 272 + colg * 8) = pk;
            }
        } else {
#pragma unroll
            for (int it = 0; it < 2; it++) {
                int kpair = kp + it * 8;
                int ke = k0 + kpair * 2;
                float ve[4], vo[4];
#pragma unroll
                for (int half = 0; half < 2; half++) {
                    int k = ke + half;
                    float* v = half ? vo : ve;
                    float4 xv = *reinterpret_cast<const float4*>(
                        inb + (size_t)k * HW + pbase + colg * 4);
                    if (BN) {
                        float A = Ap[k], Bb = Bp[k];
                        xv.x = fmaf(xv.x, A, Bb); xv.y = fmaf(xv.y, A, Bb);
                        xv.z = fmaf(xv.z, A, Bb); xv.w = fmaf(xv.w, A, Bb);
                        if (RELU) {
                            xv.x = fmaxf(xv.x, 0.f); xv.y = fmaxf(xv.y, 0.f);
                            xv.z = fmaxf(xv.z, 0.f); xv.w = fmaxf(xv.w, 0.f);
                        }
                    }
                    v[0] = xv.x; v[1] = xv.y; v[2] = xv.z; v[3] = xv.w;
                }
                uint4 pk;
                pk.x = packh2(ve[0], vo[0]);
                pk.y = packh2(ve[1], vo[1]);
                pk.z = packh2(ve[2], vo[2]);
                pk.w = packh2(ve[3], vo[3]);
                *reinterpret_cast<uint4*>(sB + kpair * 272 + colg * 8) = pk;
            }
        }
        asm volatile("cp.async.wait_group 0;");
        __syncthreads();
#pragma unroll
        for (int ks = 0; ks < 2; ks++) {
            unsigned af[4][4], bf[4][2];
#pragma unroll
            for (int mt = 0; mt < 4; mt++)
                ldm4(af[mt], a_ld + mt * 16 * 40 + ks * 16);
#pragma unroll
            for (int nt = 0; nt < 4; nt++) {
                int n = wn + nt * 8 + gid;
                bf[nt][0] = sbw[(8 * ks + qid) * 136 + n];
                bf[nt][1] = sbw[(8 * ks + qid + 4) * 136 + n];
            }
#pragma unroll
            for (int mt = 0; mt < 4; mt++)
#pragma unroll
                for (int nt = 0; nt < 4; nt++)
                    mma16(c[mt][nt], af[mt], bf[nt]);
        }
    }

#pragma unroll
    for (int mt = 0; mt < 4; mt++) {
        int co = m0 + wm + mt * 16 + gid;
#pragma unroll
        for (int nt = 0; nt < 4; nt++) {
            int cb = wn + nt * 8 + qid * 2;
            size_t idx0 = ((size_t)(b * COUT) + co) * HW + pbase + cb;
            size_t idx1 = ((size_t)(b * COUT) + co + 8) * HW + pbase + cb;
            float2 r0 = make_float2(c[mt][nt][0], c[mt][nt][1]);
            float2 r1 = make_float2(c[mt][nt][2], c[mt][nt][3]);
            if (ADD) {
                float2 a0 = *reinterpret_cast<const float2*>(add + idx0);
                float2 a1 = *reinterpret_cast<const float2*>(add + idx1);
                r0.x += a0.x; r0.y += a0.y; r1.x += a1.x; r1.y += a1.y;
            }
            *reinterpret_cast<float2*>(out + idx0) = r0;
            *reinterpret_cast<float2*>(out + idx1) = r1;
        }
    }
}

// ---------------- depthwise 3x3, pad=1, optional fused BN; 4 px/thread ----------------
template <int BN>
__global__ void k_dw3(const float* __restrict__ in, const float* __restrict__ w,
                      float* __restrict__ out, int slot) {
    int i = blockIdx.x * 256 + threadIdx.x;
    int idx = i * 4;
    int p  = idx & (HW - 1);
    int bc = idx >> 14;
    int c  = bc & 127;
    int y = p >> 7, x0 = p & 127;
    const float* ip = in + (size_t)bc * HW;
    const float* wp = w + c * 9;
    float A = 1.f, Bb = 0.f;
    if (BN) { A = g_A[slot * 128 + c]; Bb = g_Bv[slot * 128 + c]; }
    float acc[4] = {0.f, 0.f, 0.f, 0.f};
#pragma unroll
    for (int dy = 0; dy < 3; dy++) {
        int gy = y + dy - 1;
        if ((unsigned)gy >= 128u) continue;
        const float* r = ip + gy * 128;
        float4 m = *reinterpret_cast<const float4*>(r + x0);
        float v[6];
        v[0] = (x0 > 0)   ? r[x0 - 1] : 0.f;
        v[1] = m.x; v[2] = m.y; v[3] = m.z; v[4] = m.w;
        v[5] = (x0 < 124) ? r[x0 + 4] : 0.f;
        if (BN) {
            if (x0 > 0)   v[0] = fmaf(v[0], A, Bb);
            v[1] = fmaf(v[1], A, Bb); v[2] = fmaf(v[2], A, Bb);
            v[3] = fmaf(v[3], A, Bb); v[4] = fmaf(v[4], A, Bb);
            if (x0 < 124) v[5] = fmaf(v[5], A, Bb);
        }
        float w0 = wp[dy * 3], w1 = wp[dy * 3 + 1], w2 = wp[dy * 3 + 2];
#pragma unroll
        for (int e = 0; e < 4; e++)
            acc[e] = fmaf(v[e], w0, fmaf(v[e + 1], w1, fmaf(v[e + 2], w2, acc[e])));
    }
    *reinterpret_cast<float4*>(out + idx) =
        make_float4(acc[0], acc[1], acc[2], acc[3]);
}

// ---------------- bilinear downsample of u: 128x128 -> 16x16 (128 ch) ----------------
__global__ void k_ds2(const float* __restrict__ u) {
    int i = blockIdx.x * 256 + threadIdx.x;
    int j  = i & 255;
    int c  = (i >> 8) & 127;
    int b  = i >> 15;
    const float* ip = u + ((size_t)(b * C1) + c) * HW;
    int r = j >> 4, s = j & 15;
    const float step = (float)(127.0 / 15.0);
    float ph = (float)r * step;
    int   lh = min((int)ph, 126);
    float fh = ph - (float)lh;
    float pw = (float)s * step;
    int   lw = min((int)pw, 126);
    float fw = pw - (float)lw;
    const float* p0 = ip + lh * 128 + lw;
    float v00 = p0[0], v01 = p0[1], v10 = p0[128], v11 = p0[129];
    g_ud[i] = (1.f - fh) * ((1.f - fw) * v00 + fw * v01)
            +        fh  * ((1.f - fw) * v10 + fw * v11);
}

// ---------------- small fp32 GEMM: kd/vd = W_kv[256,128] @ ud[128,R2] ----------------
__global__ void k_kv(const float* __restrict__ w) {
    int og = blockIdx.x, b = blockIdx.y;
    int j = threadIdx.x;
    __shared__ float sw[16 * 128];
    for (int i = j; i < 16 * 128; i += 256)
        sw[i] = w[(size_t)(128 + og * 16) * 128 + i];
    __syncthreads();
    float acc[16];
#pragma unroll
    for (int r = 0; r < 16; r++) acc[r] = 0.f;
    const float* udb = g_ud + (size_t)b * C1 * R2 + j;
#pragma unroll 4
    for (int c = 0; c < 128; c++) {
        float v = udb[(size_t)c * R2];
#pragma unroll
        for (int r = 0; r < 16; r++) acc[r] = fmaf(sw[r * 128 + c], v, acc[r]);
    }
#pragma unroll
    for (int r = 0; r < 16; r++) {
        int oc = og * 16 + r;
        float* dst = (oc < 128) ? g_kd : g_vd;
        dst[((size_t)(b * C1) + (oc & 127)) * R2 + j] = acc[r];
    }
}

// ---------------- fp16 tensor-core attention ----------------
// smem: k16[256 j][20] (word = (K_{2dp},K_{2dp+1}) at pixel j)
//       v16[128 jp][40] (word = (V_{2jp},V_{2jp+1}) at channel d)
//       q16[64 r][20]   (word = (Q_{2dp},Q_{2dp+1}) at row r, pre-scaled)
//       t_s[961]
__global__ __launch_bounds__(128)
void k_attn(const float* __restrict__ qbuf, const float* __restrict__ table,
            float* __restrict__ outp) {
    extern __shared__ unsigned smu[];
    unsigned* k16 = smu;                      // 256*20 = 5120
    unsigned* v16 = smu + 256 * 20;           // 128*40 = 5120
    unsigned* q16 = v16 + 128 * 40;           // 64*20  = 1280
    float*    t_s = reinterpret_cast<float*>(q16 + 64 * 20);   // 961

    const int tid  = threadIdx.x;
    const int lane = tid & 31, warp = tid >> 5;
    const int gid  = lane >> 2, qid = lane & 3;
    const int bh   = blockIdx.y;
    const int b = bh >> 2, head = bh & 3;
    const int px0 = blockIdx.x * 64;
    const float scale = 0.17677669529663687f;
    const float PSC = 0.0625f;     // P pack scale (overflow headroom)

    // ---- stage K: [j][dpair] ----
    for (int i = tid; i < 16 * 256; i += 128) {
        int dp = i >> 8, j = i & 255;
        const float* base = g_kd + (size_t)b * C1 * R2 + j;
        float a = base[(size_t)((2 * dp) * 4 + head) * R2];
        float bb2 = base[(size_t)((2 * dp + 1) * 4 + head) * R2];
        k16[j * 20 + dp] = packh2(a, bb2);
    }
    // ---- stage V: [jpair][d] ----
    for (int i = tid; i < 32 * 128; i += 128) {
        int d = i >> 7, jp = i & 127;
        const float2 vv = *reinterpret_cast<const float2*>(
            g_vd + ((size_t)(b * C1) + d * 4 + head) * R2 + 2 * jp);
        v16[jp * 40 + d] = packh2(vv.x, vv.y);
    }
    // ---- stage Q: [row][dpair], pre-scaled ----
    for (int i = tid; i < 16 * 64; i += 128) {
        int dp = i >> 6, r = i & 63;
        const float* base = qbuf + (size_t)b * C1 * HW + px0 + r;
        float a = base[(size_t)((2 * dp) * 4 + head) * HW] * scale;
        float bb2 = base[(size_t)((2 * dp + 1) * 4 + head) * HW] * scale;
        q16[r * 20 + dp] = packh2(a, bb2);
    }
    for (int i = tid; i < 961; i += 128) t_s[i] = table[i * 4 + head] * scale;
    __syncthreads();

    // ---- QK^T: S[16][256] per warp (2 x k16 chunks) ----
    unsigned aq[2][4];
#pragma unroll
    for (int kc = 0; kc < 2; kc++) {
        const unsigned* r0 = q16 + (warp * 16 + gid) * 20 + kc * 8;
        const unsigned* r1 = r0 + 8 * 20;
        aq[kc][0] = r0[qid];
        aq[kc][1] = r1[qid];
        aq[kc][2] = r0[qid + 4];
        aq[kc][3] = r1[qid + 4];
    }
    float s[32][4];
#pragma unroll
    for (int nt = 0; nt < 32; nt++) { s[nt][0]=s[nt][1]=s[nt][2]=s[nt][3]=0.f; }
#pragma unroll
    for (int nt = 0; nt < 32; nt++) {
        const unsigned* kb = k16 + (nt * 8 + gid) * 20;
#pragma unroll
        for (int kc = 0; kc < 2; kc++) {
            unsigned bf[2];
            bf[0] = kb[kc * 8 + qid];
            bf[1] = kb[kc * 8 + qid + 4];
            mma16(s[nt], aq[kc], bf);
        }
    }

    // ---- bias + exp + row sums ----
    const int xb = (px0 & 127) + warp * 16;
    const int rh = (px0 >> 7) >> 3;
    const int base0 = (rh + 15) * 31 + ((xb + gid) >> 3) + 15;
    const int base1 = (rh + 15) * 31 + ((xb + gid + 8) >> 3) + 15;
    float l0 = 0.f, l1 = 0.f;
#pragma unroll
    for (int nt = 0; nt < 32; nt++) {
        int j = nt * 8 + 2 * qid;
        int off = (j >> 4) * 31 + (j & 15);
        float e0 = __expf(s[nt][0] + t_s[base0 - off]);
        float e1 = __expf(s[nt][1] + t_s[base0 - off - 1]);
        float e2 = __expf(s[nt][2] + t_s[base1 - off]);
        float e3 = __expf(s[nt][3] + t_s[base1 - off - 1]);
        s[nt][0] = e0 * PSC; s[nt][1] = e1 * PSC;
        s[nt][2] = e2 * PSC; s[nt][3] = e3 * PSC;
        l0 += e0 + e1; l1 += e2 + e3;
    }
    l0 += __shfl_xor_sync(0xffffffffu, l0, 1);
    l0 += __shfl_xor_sync(0xffffffffu, l0, 2);
    l1 += __shfl_xor_sync(0xffffffffu, l1, 1);
    l1 += __shfl_xor_sync(0xffffffffu, l1, 2);
    const float inv0 = 1.f / (l0 * PSC), inv1 = 1.f / (l1 * PSC);

    // ---- AV: O[16][32] per warp; A-frags pack directly from S (no shuffles) ----
    float o[4][4];
#pragma unroll
    for (int nt = 0; nt < 4; nt++) { o[nt][0]=o[nt][1]=o[nt][2]=o[nt][3]=0.f; }
#pragma unroll
    for (int kc = 0; kc < 16; kc++) {
        unsigned a[4];
        a[0] = packh2(s[2 * kc][0],     s[2 * kc][1]);
        a[1] = packh2(s[2 * kc][2],     s[2 * kc][3]);
        a[2] = packh2(s[2 * kc + 1][0], s[2 * kc + 1][1]);
        a[3] = packh2(s[2 * kc + 1][2], s[2 * kc + 1][3]);
        const unsigned* vb0 = v16 + (kc * 8 + qid) * 40;
        const unsigned* vb1 = v16 + (kc * 8 + qid + 4) * 40;
#pragma unroll
        for (int ntd = 0; ntd < 4; ntd++) {
            unsigned bf[2];
            bf[0] = vb0[ntd * 8 + gid];
            bf[1] = vb1[ntd * 8 + gid];
            mma16(o[ntd], a, bf);
        }
    }

    // ---- epilogue ----
    const int px = px0 + warp * 16 + gid;
#pragma unroll
    for (int ntd = 0; ntd < 4; ntd++) {
        int d = ntd * 8 + 2 * qid;
        size_t c0 = ((size_t)(b * C1) + d * 4 + head) * HW;
        size_t c1 = ((size_t)(b * C1) + (d + 1) * 4 + head) * HW;
        outp[c0 + px]     = o[ntd][0] * inv0;
        outp[c1 + px]     = o[ntd][1] * inv0;
        outp[c0 + px + 8] = o[ntd][2] * inv1;
        outp[c1 + px + 8] = o[ntd][3] * inv1;
    }
}

// ---------------- host orchestration ----------------
extern "C" void kernel_launch(void* const* d_in, const int* in_sizes, int n_in,
                              void* d_out, int out_size) {
    (void)in_sizes; (void)n_in; (void)out_size;
    const float* x        = (const float*)d_in[0];
    const float* bb_bn1_g = (const float*)d_in[1];
    const float* bb_bn1_b = (const float*)d_in[2];
    const float* bb_conv1 = (const float*)d_in[3];
    const float* bb_bn2_g = (const float*)d_in[4];
    const float* bb_bn2_b = (const float*)d_in[5];
    const float* bb_conv2 = (const float*)d_in[6];
    const float* bb_sbn_g = (const float*)d_in[7];
    const float* bb_sbn_b = (const float*)d_in[8];
    const float* bb_sconv = (const float*)d_in[9];
    const float* tb_bn1_g = (const float*)d_in[10];
    const float* tb_bn1_b = (const float*)d_in[11];
    const float* tb_dwqkv = (const float*)d_in[12];
    const float* tb_pwqkv = (const float*)d_in[13];
    const float* tb_dwout = (const float*)d_in[14];
    const float* tb_pwout = (const float*)d_in[15];
    const float* tb_rel   = (const float*)d_in[16];
    const float* tb_bn2_g = (const float*)d_in[17];
    const float* tb_bn2_b = (const float*)d_in[18];
    const float* tb_mlp   = (const float*)d_in[19];

    void* pv;
    float *pool, *t, *u, *o, *qb;
    cudaGetSymbolAddress(&pv, g_pool); pool = (float*)pv;
    cudaGetSymbolAddress(&pv, g_t);    t    = (float*)pv;
    cudaGetSymbolAddress(&pv, g_u);    u    = (float*)pv;
    cudaGetSymbolAddress(&pv, g_o);    o    = (float*)pv;
    cudaGetSymbolAddress(&pv, g_qkv);  qb   = (float*)pv;

    const int ATTN_SMEM = (256 * 20 + 128 * 40 + 64 * 20) * 4 + 961 * 4;   // 49924
    cudaFuncSetAttribute(k_attn, cudaFuncAttributeMaxDynamicSharedMemorySize, ATTN_SMEM);

    const dim3 g1(NPIX / 128, 1);
    const dim3 ga(HW / 64, B * 4);

    // ---- one-shot weight conversion ----
    WArgs wa;
    wa.s[0] = { bb_conv1, WO_CONV1, 128 * 576,  64 };
    wa.s[1] = { bb_conv2, WO_CONV2, 128 * 1152, 128 };
    wa.s[2] = { bb_sconv, WO_SCONV, 128 * 64,   0 };
    wa.s[3] = { tb_pwqkv,               WO_TB,                       384 * 128, 0 };
    wa.s[4] = { tb_pwout,               WO_TB + 49152,               128 * 128, 0 };
    wa.s[5] = { tb_mlp,                 WO_TB + 65536,               128 * 128, 0 };
    wa.s[6] = { tb_pwqkv + 384 * 128,   WO_TB + WO_BLK,              384 * 128, 0 };
    wa.s[7] = { tb_pwout + 128 * 128,   WO_TB + WO_BLK + 49152,      128 * 128, 0 };
    wa.s[8] = { tb_mlp + 128 * 128,     WO_TB + WO_BLK + 65536,      128 * 128, 0 };
    k_wprep_all<<<W_TOTAL / 1024, 256>>>(wa);

    k_maxpool<<<(B * C0 * HW) / 256, 256>>>(x, pool);

    // ---- BasicBlock ----
    k_bnpart<<<dim3(C0, PARTS), 256>>>(pool, bb_bn1_g, bb_bn1_b, C0, 0, bb_sbn_g, bb_sbn_b, 2);
    k_gemm<576, 64, true, true, true, false><<<g1, 256>>>(pool, u, nullptr, 128, 0, WO_CONV1);
    k_bnpart<<<dim3(C1, PARTS), 256>>>(u, bb_bn2_g, bb_bn2_b, C1, 1, nullptr, nullptr, 0);
    k_gemm<1152, 128, true, true, true, false><<<g1, 256>>>(u, o, nullptr, 128, 1, WO_CONV2);
    k_gemm<64, 64, false, true, true, true><<<g1, 256>>>(pool, o, o, 128, 2, WO_SCONV);

    // ---- 2 x BasicTransBlock (ping-pong residual between o and t) ----
    float* ob = o;
    float* tb = t;
    for (int i = 0; i < 2; i++) {
        const int wo = WO_TB + i * WO_BLK;
        k_bnpart<<<dim3(C1, PARTS), 256>>>(ob, tb_bn1_g + i * 128, tb_bn1_b + i * 128, C1, 3,
                                           nullptr, nullptr, 0);
        k_dw3<1><<<(B * C1 * HW) / 1024, 256>>>(ob, tb_dwqkv + (size_t)i * 128 * 9, u, 3);
        k_gemm<128, 128, false, false, false, false><<<g1, 256>>>(u, qb, nullptr, 128, 0, wo);
        k_ds2<<<(B * C1 * R2) / 256, 256>>>(u);
        k_kv<<<dim3(16, B), 256>>>(tb_pwqkv + (size_t)i * 384 * 128);
        k_attn<<<ga, 128, ATTN_SMEM>>>(qb, tb_rel + (size_t)i * 961 * 4, tb);
        k_dw3<0><<<(B * C1 * HW) / 1024, 256>>>(tb, tb_dwout + (size_t)i * 128 * 9, u, 0);
        k_gemm<128, 128, false, false, false, true><<<g1, 256>>>(u, ob, ob, 128, 0, wo + 49152);
        k_bnpart<<<dim3(C1, PARTS), 256>>>(ob, tb_bn2_g + i * 128, tb_bn2_b + i * 128, C1, 4,
                                           nullptr, nullptr, 0);
        float* dest = (i == 1) ? (float*)d_out : tb;
        k_gemm<128, 128, false, true, true, true><<<g1, 256>>>(ob, dest, ob, 128, 4, wo + 65536);
        float* tmp = ob; ob = tb; tb = tmp;
    }
}

// round 13
// speedup vs baseline: 1.5738x; 1.0195x over previous
#include <cuda_runtime.h>
#include <cuda_fp16.h>
#include <cstdint>

// ---------------- problem constants ----------------
namespace {
constexpr int B    = 2;
constexpr int C0   = 64;
constexpr int C1   = 128;
constexpr int H    = 128, W = 128;
constexpr int HW   = H * W;            // 16384
constexpr int NPIX = B * HW;           // 32768
constexpr int R2   = 256;              // 16x16 reduced K/V
constexpr float BN_EPS = 1e-5f;
constexpr int WO_CONV1 = 0;
constexpr int WO_CONV2 = 73728;
constexpr int WO_SCONV = 221184;
constexpr int WO_TB    = 229376;
constexpr int WO_BLK   = 81920;
constexpr int W_TOTAL  = 393216;
constexpr int PARTS    = 8;
}

// ---------------- scratch (static device, no allocs) ----------------
__device__ float g_pool[B * C0 * HW];
__device__ float g_t   [B * C1 * HW];
__device__ float g_o   [B * C1 * HW];
__device__ float g_qkv [B * C1 * HW];        // q only
__device__ __align__(16) __half g_uh[B * C1 * HW];   // fp16 dw3 output
__device__ float g_ud  [B * C1 * R2];
__device__ float g_kd  [B * C1 * R2];
__device__ float g_vd  [B * C1 * R2];
__device__ __align__(16) __half g_wth[W_TOTAL];
__device__ double2 g_part[128][PARTS];
__device__ unsigned g_cnt = 0;
__device__ float g_A   [8 * 128];
__device__ float g_Bv  [8 * 128];

// ---------------- helpers ----------------
__device__ __forceinline__ void mma16(float c[4], const unsigned a[4], const unsigned b[2]) {
    asm volatile(
        "mma.sync.aligned.m16n8k16.row.col.f32.f16.f16.f32 "
        "{%0,%1,%2,%3},{%4,%5,%6,%7},{%8,%9},{%0,%1,%2,%3};"
        : "+f"(c[0]), "+f"(c[1]), "+f"(c[2]), "+f"(c[3])
        : "r"(a[0]), "r"(a[1]), "r"(a[2]), "r"(a[3]), "r"(b[0]), "r"(b[1]));
}
__device__ __forceinline__ void ldm4(unsigned a[4], const void* p) {
    unsigned addr = (unsigned)__cvta_generic_to_shared(p);
    asm volatile("ldmatrix.sync.aligned.m8n8.x4.shared.b16 {%0,%1,%2,%3}, [%4];"
        : "=r"(a[0]), "=r"(a[1]), "=r"(a[2]), "=r"(a[3]) : "r"(addr));
}
__device__ __forceinline__ void ldm4t(unsigned a[4], const void* p) {
    unsigned addr = (unsigned)__cvta_generic_to_shared(p);
    asm volatile("ldmatrix.sync.aligned.m8n8.x4.trans.shared.b16 {%0,%1,%2,%3}, [%4];"
        : "=r"(a[0]), "=r"(a[1]), "=r"(a[2]), "=r"(a[3]) : "r"(addr));
}
__device__ __forceinline__ void cpa16(void* dst, const void* src) {
    unsigned d = (unsigned)__cvta_generic_to_shared(dst);
    asm volatile("cp.async.ca.shared.global [%0], [%1], 16;" :: "r"(d), "l"(src));
}
__device__ __forceinline__ unsigned h2u(__half2 h) {
    return *reinterpret_cast<unsigned*>(&h);
}
__device__ __forceinline__ unsigned packh2(float a, float b) {
    return h2u(__floats2half2_rn(a, b));
}

// ---------------- weight pre-convert fp32 -> fp16 (one launch) ----------------
struct WSeg { const float* src; int dst; int n; int cin; };
struct WArgs { WSeg s[9]; };
__global__ void k_wprep_all(WArgs a) {
    int i = (blockIdx.x * 256 + threadIdx.x) * 4;
#pragma unroll
    for (int t = 0; t < 9; t++) {
        if (i < a.s[t].n) {
            float v0, v1, v2, v3;
            if (a.s[t].cin == 0) {
                float4 v = *reinterpret_cast<const float4*>(a.s[t].src + i);
                v0 = v.x; v1 = v.y; v2 = v.z; v3 = v.w;
            } else {
                int cin = a.s[t].cin;
                int K = cin * 9;
                int co = i / K, r = i - co * K;
                int q = r / cin, ci = r - q * cin;
                const float* s = a.s[t].src + (size_t)co * K + ci * 9 + q;
                v0 = s[0]; v1 = s[9]; v2 = s[18]; v3 = s[27];
            }
            uint2 pk;
            pk.x = packh2(v0, v1);
            pk.y = packh2(v2, v3);
            *reinterpret_cast<uint2*>(g_wth + a.s[t].dst + i) = pk;
            return;
        }
        i -= a.s[t].n;
    }
}

// ---------------- maxpool 2x2 ----------------
__global__ void k_maxpool(const float* __restrict__ x, float* __restrict__ out) {
    int i = blockIdx.x * 256 + threadIdx.x;
    int p  = i & (HW - 1);
    int bc = i >> 14;
    int y = p >> 7, xx = p & 127;
    const float* ip = x + (size_t)bc * 65536 + (size_t)(y * 2) * 256 + xx * 2;
    out[i] = fmaxf(fmaxf(ip[0], ip[1]), fmaxf(ip[256], ip[257]));
}

// ---------------- BN stats ----------------
__global__ void k_bnpart(const float* __restrict__ x, const float* __restrict__ gg,
                         const float* __restrict__ bb, int Cc, int slot,
                         const float* __restrict__ gg2, const float* __restrict__ bb2,
                         int slot2) {
    int c = blockIdx.x, part = blockIdx.y;
    int tid = threadIdx.x;
    int lane = tid & 31, wid = tid >> 5;
    const float4* x0 = reinterpret_cast<const float4*>(x + (size_t)c * HW) + part * (HW / (4 * PARTS));
    const float4* x1 = reinterpret_cast<const float4*>(x + (size_t)(Cc + c) * HW) + part * (HW / (4 * PARTS));
    float s = 0.f, s2 = 0.f;
#pragma unroll
    for (int it = 0; it < 2; it++) {
        int p = tid + it * 256;
        float4 a = x0[p];
        s += a.x + a.y + a.z + a.w;
        s2 = fmaf(a.x, a.x, fmaf(a.y, a.y, fmaf(a.z, a.z, fmaf(a.w, a.w, s2))));
        float4 d = x1[p];
        s += d.x + d.y + d.z + d.w;
        s2 = fmaf(d.x, d.x, fmaf(d.y, d.y, fmaf(d.z, d.z, fmaf(d.w, d.w, s2))));
    }
#pragma unroll
    for (int off = 16; off > 0; off >>= 1) {
        s  += __shfl_down_sync(0xffffffffu, s, off);
        s2 += __shfl_down_sync(0xffffffffu, s2, off);
    }
    __shared__ double ws[8], wq[8];
    __shared__ bool lastf;
    if (lane == 0) { ws[wid] = (double)s; wq[wid] = (double)s2; }
    __syncthreads();
    if (tid == 0) {
        double S = 0., Q = 0.;
#pragma unroll
        for (int w = 0; w < 8; w++) { S += ws[w]; Q += wq[w]; }
        g_part[c][part] = make_double2(S, Q);
        __threadfence();
        unsigned v = atomicAdd(&g_cnt, 1u);
        lastf = (v == (unsigned)(Cc * PARTS - 1));
    }
    __syncthreads();
    if (lastf) {
        __threadfence();
        int cc = tid;
        if (cc < Cc) {
            double ss = 0., q = 0.;
#pragma unroll
            for (int p = 0; p < PARTS; p++) { ss += g_part[cc][p].x; q += g_part[cc][p].y; }
            double mean = ss / (double)NPIX;
            double var  = q / (double)NPIX - mean * mean;
            double rstd = 1.0 / sqrt(var + (double)BN_EPS);
            double A    = (double)gg[cc] * rstd;
            g_A[slot * 128 + cc]  = (float)A;
            g_Bv[slot * 128 + cc] = (float)((double)bb[cc] - mean * A);
            if (gg2) {
                double A2 = (double)gg2[cc] * rstd;
                g_A[slot2 * 128 + cc]  = (float)A2;
                g_Bv[slot2 * 128 + cc] = (float)((double)bb2[cc] - mean * A2);
            }
        }
        if (tid == 0) g_cnt = 0;
    }
}

// ---------------- fp16 GEMM ----------------
template <int K, int CIN, bool IC, bool BN, bool RELU, bool ADD, bool F16IN>
__global__ __launch_bounds__(256)
void k_gemm(const void* __restrict__ in,
            float* __restrict__ out, const float* __restrict__ add,
            int COUT, int slot, int woff) {
    __shared__ __align__(16) __half sA[128 * 40];
    __shared__ __align__(16) __half sB[32 * 136];

    const int tid = threadIdx.x;
    const int lane = tid & 31, warp = tid >> 5;
    const int gid = lane >> 2, qid = lane & 3;
    const int wm = (warp & 1) * 64, wn = (warp >> 1) * 32;

    const int n0 = blockIdx.x * 128;
    const int m0 = blockIdx.y * 128;
    const int b  = n0 >> 14;
    const int pbase = n0 & (HW - 1);
    const int y = pbase >> 7;

    const float* Ap = g_A  + slot * 128;
    const float* Bp = g_Bv + slot * 128;
    const __half* wbase = g_wth + woff;
    const float* inb = (const float*)in + (size_t)b * CIN * HW;
    const __half* inh = (const __half*)in + (size_t)b * CIN * HW;

    float c[4][4][4];
#pragma unroll
    for (int mt = 0; mt < 4; mt++)
#pragma unroll
        for (int nt = 0; nt < 4; nt++)
#pragma unroll
            for (int e = 0; e < 4; e++) c[mt][nt][e] = 0.f;

    const int a_row = tid >> 1;
    const int a_c   = (tid & 1) * 16;
    const int colg  = tid & 31;
    const int kp    = tid >> 5;

    __half* a_ld = sA + (wm + (lane & 15)) * 40 + ((lane >> 4) << 3);
    const unsigned* sbw = reinterpret_cast<const unsigned*>(sB);

    for (int k0 = 0; k0 < K; k0 += 32) {
        __syncthreads();
        {
            const __half* src = wbase + (size_t)(m0 + a_row) * K + k0 + a_c;
            __half* dst = sA + a_row * 40 + a_c;
            cpa16(dst, src);
            cpa16(dst + 8, src + 8);
        }
        if (F16IN) {
            int row = tid >> 3;
            int col = (tid & 7) * 16;
            const __half* src = inh + (size_t)(k0 + row) * HW + pbase + col;
            __half* dst = sB + row * 136 + col;
            cpa16(dst, src);
            cpa16(dst + 8, src + 8);
            asm volatile("cp.async.commit_group;");
        } else {
            asm volatile("cp.async.commit_group;");
            if (IC) {
                const int q  = k0 / CIN;
                const int cb = k0 - q * CIN;
                const int dy = q / 3 - 1, dx = q - (q / 3) * 3 - 1;
                const int gy = y + dy;
                const bool yok = (unsigned)gy < 128u;
                const float* rowp = inb + gy * 128;
                const int xbase = colg * 4 + dx;
#pragma unroll
                for (int it = 0; it < 2; it++) {
                    int kpair = kp + it * 8;
                    int ci0 = cb + kpair * 2;
                    float ve[4], vo[4];
#pragma unroll
                    for (int half = 0; half < 2; half++) {
                        int ci = ci0 + half;
                        float* v = half ? vo : ve;
                        float A = 1.f, Bb = 0.f;
                        if (BN) { A = Ap[ci]; Bb = Bp[ci]; }
                        const float* src = rowp + (size_t)ci * HW;
#pragma unroll
                        for (int e = 0; e < 4; e++) {
                            int gx = xbase + e;
                            float vv = 0.f;
                            if (yok && (unsigned)gx < 128u) {
                                vv = src[gx];
                                if (BN) vv = fmaf(vv, A, Bb);
                                if (RELU) vv = fmaxf(vv, 0.f);
                            }
                            v[e] = vv;
                        }
                    }
                    uint4 pk;
                    pk.x = packh2(ve[0], vo[0]);
                    pk.y = packh2(ve[1], vo[1]);
                    pk.z = packh2(ve[2], vo[2]);
                    pk.w = packh2(ve[3], vo[3]);
                    *reinterpret_cast<uint4*>(sB + kpair * 272 + colg * 8) = pk;
                }
            } else {
#pragma unroll
                for (int it = 0; it < 2; it++) {
                    int kpair = kp + it * 8;
                    int ke = k0 + kpair * 2;
                    float ve[4], vo[4];
#pragma unroll
                    for (int half = 0; half < 2; half++) {
                        int k = ke + half;
                        float* v = half ? vo : ve;
                        float4 xv = *reinterpret_cast<const float4*>(
                            inb + (size_t)k * HW + pbase + colg * 4);
                        if (BN) {
                            float A = Ap[k], Bb = Bp[k];
                            xv.x = fmaf(xv.x, A, Bb); xv.y = fmaf(xv.y, A, Bb);
                            xv.z = fmaf(xv.z, A, Bb); xv.w = fmaf(xv.w, A, Bb);
                            if (RELU) {
                                xv.x = fmaxf(xv.x, 0.f); xv.y = fmaxf(xv.y, 0.f);
                                xv.z = fmaxf(xv.z, 0.f); xv.w = fmaxf(xv.w, 0.f);
                            }
                        }
                        v[0] = xv.x; v[1] = xv.y; v[2] = xv.z; v[3] = xv.w;
                    }
                    uint4 pk;
                    pk.x = packh2(ve[0], vo[0]);
                    pk.y = packh2(ve[1], vo[1]);
                    pk.z = packh2(ve[2], vo[2]);
                    pk.w = packh2(ve[3], vo[3]);
                    *reinterpret_cast<uint4*>(sB + kpair * 272 + colg * 8) = pk;
                }
            }
        }
        asm volatile("cp.async.wait_group 0;");
        __syncthreads();
#pragma unroll
        for (int ks = 0; ks < 2; ks++) {
            unsigned af[4][4], bf[4][2];
#pragma unroll
            for (int mt = 0; mt < 4; mt++)
                ldm4(af[mt], a_ld + mt * 16 * 40 + ks * 16);
            if (F16IN) {
                const __half* basep = sB + (ks * 16 + (lane & 15)) * 136
                                         + wn + ((lane >> 4) << 3);
                unsigned r[4];
                ldm4t(r, basep);
                bf[0][0] = r[0]; bf[0][1] = r[1];
                bf[1][0] = r[2]; bf[1][1] = r[3];
                ldm4t(r, basep + 16);
                bf[2][0] = r[0]; bf[2][1] = r[1];
                bf[3][0] = r[2]; bf[3][1] = r[3];
            } else {
#pragma unroll
                for (int nt = 0; nt < 4; nt++) {
                    int n = wn + nt * 8 + gid;
                    bf[nt][0] = sbw[(8 * ks + qid) * 136 + n];
                    bf[nt][1] = sbw[(8 * ks + qid + 4) * 136 + n];
                }
            }
#pragma unroll
            for (int mt = 0; mt < 4; mt++)
#pragma unroll
                for (int nt = 0; nt < 4; nt++)
                    mma16(c[mt][nt], af[mt], bf[nt]);
        }
    }

#pragma unroll
    for (int mt = 0; mt < 4; mt++) {
        int co = m0 + wm + mt * 16 + gid;
#pragma unroll
        for (int nt = 0; nt < 4; nt++) {
            int cb = wn + nt * 8 + qid * 2;
            size_t idx0 = ((size_t)(b * COUT) + co) * HW + pbase + cb;
            size_t idx1 = ((size_t)(b * COUT) + co + 8) * HW + pbase + cb;
            float2 r0 = make_float2(c[mt][nt][0], c[mt][nt][1]);
            float2 r1 = make_float2(c[mt][nt][2], c[mt][nt][3]);
            if (ADD) {
                float2 a0 = *reinterpret_cast<const float2*>(add + idx0);
                float2 a1 = *reinterpret_cast<const float2*>(add + idx1);
                r0.x += a0.x; r0.y += a0.y; r1.x += a1.x; r1.y += a1.y;
            }
            *reinterpret_cast<float2*>(out + idx0) = r0;
            *reinterpret_cast<float2*>(out + idx1) = r1;
        }
    }
}

// ---------------- depthwise 3x3 -> fp16 out ----------------
template <int BN>
__global__ void k_dw3(const float* __restrict__ in, const float* __restrict__ w,
                      __half* __restrict__ out, int slot) {
    int i = blockIdx.x * 256 + threadIdx.x;
    int idx = i * 4;
    int p  = idx & (HW - 1);
    int bc = idx >> 14;
    int c  = bc & 127;
    int y = p >> 7, x0 = p & 127;
    const float* ip = in + (size_t)bc * HW;
    const float* wp = w + c * 9;
    float A = 1.f, Bb = 0.f;
    if (BN) { A = g_A[slot * 128 + c]; Bb = g_Bv[slot * 128 + c]; }
    float acc[4] = {0.f, 0.f, 0.f, 0.f};
#pragma unroll
    for (int dy = 0; dy < 3; dy++) {
        int gy = y + dy - 1;
        if ((unsigned)gy >= 128u) continue;
        const float* r = ip + gy * 128;
        float4 m = *reinterpret_cast<const float4*>(r + x0);
        float v[6];
        v[0] = (x0 > 0)   ? r[x0 - 1] : 0.f;
        v[1] = m.x; v[2] = m.y; v[3] = m.z; v[4] = m.w;
        v[5] = (x0 < 124) ? r[x0 + 4] : 0.f;
        if (BN) {
            if (x0 > 0)   v[0] = fmaf(v[0], A, Bb);
            v[1] = fmaf(v[1], A, Bb); v[2] = fmaf(v[2], A, Bb);
            v[3] = fmaf(v[3], A, Bb); v[4] = fmaf(v[4], A, Bb);
            if (x0 < 124) v[5] = fmaf(v[5], A, Bb);
        }
        float w0 = wp[dy * 3], w1 = wp[dy * 3 + 1], w2 = wp[dy * 3 + 2];
#pragma unroll
        for (int e = 0; e < 4; e++)
            acc[e] = fmaf(v[e], w0, fmaf(v[e + 1], w1, fmaf(v[e + 2], w2, acc[e])));
    }
    uint2 pk;
    pk.x = packh2(acc[0], acc[1]);
    pk.y = packh2(acc[2], acc[3]);
    *reinterpret_cast<uint2*>(out + idx) = pk;
}

// ---------------- bilinear downsample of fp16 u ----------------
__global__ void k_ds2(const __half* __restrict__ u) {
    int i = blockIdx.x * 256 + threadIdx.x;
    int j  = i & 255;
    int c  = (i >> 8) & 127;
    int b  = i >> 15;
    const __half* ip = u + ((size_t)(b * C1) + c) * HW;
    int r = j >> 4, s = j & 15;
    const float step = (float)(127.0 / 15.0);
    float ph = (float)r * step;
    int   lh = min((int)ph, 126);
    float fh = ph - (float)lh;
    float pw = (float)s * step;
    int   lw = min((int)pw, 126);
    float fw = pw - (float)lw;
    const __half* p0 = ip + lh * 128 + lw;
    float v00 = __half2float(p0[0]),   v01 = __half2float(p0[1]);
    float v10 = __half2float(p0[128]), v11 = __half2float(p0[129]);
    g_ud[i] = (1.f - fh) * ((1.f - fw) * v00 + fw * v01)
            +        fh  * ((1.f - fw) * v10 + fw * v11);
}

// ---------------- small fp32 GEMM: kd/vd = W_kv @ ud ----------------
__global__ void k_kv(const float* __restrict__ w) {
    int og = blockIdx.x, b = blockIdx.y;
    int j = threadIdx.x;
    __shared__ float sw[16 * 128];
    for (int i = j; i < 16 * 128; i += 256)
        sw[i] = w[(size_t)(128 + og * 16) * 128 + i];
    __syncthreads();
    float acc[16];
#pragma unroll
    for (int r = 0; r < 16; r++) acc[r] = 0.f;
    const float* udb = g_ud + (size_t)b * C1 * R2 + j;
#pragma unroll 4
    for (int c = 0; c < 128; c++) {
        float v = udb[(size_t)c * R2];
#pragma unroll
        for (int r = 0; r < 16; r++) acc[r] = fmaf(sw[r * 128 + c], v, acc[r]);
    }
#pragma unroll
    for (int r = 0; r < 16; r++) {
        int oc = og * 16 + r;
        float* dst = (oc < 128) ? g_kd : g_vd;
        dst[((size_t)(b * C1) + (oc & 127)) * R2 + j] = acc[r];
    }
}

// ---------------- fp16 tensor-core attention ----------------
__global__ __launch_bounds__(128)
void k_attn(const float* __restrict__ qbuf, const float* __restrict__ table,
            float* __restrict__ outp) {
    extern __shared__ unsigned smu[];
    unsigned* k16 = smu;
    unsigned* v16 = smu + 256 * 20;
    unsigned* q16 = v16 + 128 * 40;
    float*    t_s = reinterpret_cast<float*>(q16 + 64 * 20);

    const int tid  = threadIdx.x;
    const int lane = tid & 31, warp = tid >> 5;
    const int gid  = lane >> 2, qid = lane & 3;
    const int bh   = blockIdx.y;
    const int b = bh >> 2, head = bh & 3;
    const int px0 = blockIdx.x * 64;
    const float scale = 0.17677669529663687f;
    const float PSC = 0.0625f;

    for (int i = tid; i < 16 * 256; i += 128) {
        int dp = i >> 8, j = i & 255;
        const float* base = g_kd + (size_t)b * C1 * R2 + j;
        float a = base[(size_t)((2 * dp) * 4 + head) * R2];
        float bb2 = base[(size_t)((2 * dp + 1) * 4 + head) * R2];
        k16[j * 20 + dp] = packh2(a, bb2);
    }
    for (int i = tid; i < 32 * 128; i += 128) {
        int d = i >> 7, jp = i & 127;
        const float2 vv = *reinterpret_cast<const float2*>(
            g_vd + ((size_t)(b * C1) + d * 4 + head) * R2 + 2 * jp);
        v16[jp * 40 + d] = packh2(vv.x, vv.y);
    }
    for (int i = tid; i < 16 * 64; i += 128) {
        int dp = i >> 6, r = i & 63;
        const float* base = qbuf + (size_t)b * C1 * HW + px0 + r;
        float a = base[(size_t)((2 * dp) * 4 + head) * HW] * scale;
        float bb2 = base[(size_t)((2 * dp + 1) * 4 + head) * HW] * scale;
        q16[r * 20 + dp] = packh2(a, bb2);
    }
    for (int i = tid; i < 961; i += 128) t_s[i] = table[i * 4 + head] * scale;
    __syncthreads();

    unsigned aq[2][4];
#pragma unroll
    for (int kc = 0; kc < 2; kc++) {
        const unsigned* r0 = q16 + (warp * 16 + gid) * 20 + kc * 8;
        const unsigned* r1 = r0 + 8 * 20;
        aq[kc][0] = r0[qid];
        aq[kc][1] = r1[qid];
        aq[kc][2] = r0[qid + 4];
        aq[kc][3] = r1[qid + 4];
    }
    float s[32][4];
#pragma unroll
    for (int nt = 0; nt < 32; nt++) { s[nt][0]=s[nt][1]=s[nt][2]=s[nt][3]=0.f; }
#pragma unroll
    for (int nt = 0; nt < 32; nt++) {
        const unsigned* kb = k16 + (nt * 8 + gid) * 20;
#pragma unroll
        for (int kc = 0; kc < 2; kc++) {
            unsigned bf[2];
            bf[0] = kb[kc * 8 + qid];
            bf[1] = kb[kc * 8 + qid + 4];
            mma16(s[nt], aq[kc], bf);
        }
    }

    const int xb = (px0 & 127) + warp * 16;
    const int rh = (px0 >> 7) >> 3;
    const int base0 = (rh + 15) * 31 + ((xb + gid) >> 3) + 15;
    const int base1 = (rh + 15) * 31 + ((xb + gid + 8) >> 3) + 15;
    float l0 = 0.f, l1 = 0.f;
#pragma unroll
    for (int nt = 0; nt < 32; nt++) {
        int j = nt * 8 + 2 * qid;
        int off = (j >> 4) * 31 + (j & 15);
        float e0 = __expf(s[nt][0] + t_s[base0 - off]);
        float e1 = __expf(s[nt][1] + t_s[base0 - off - 1]);
        float e2 = __expf(s[nt][2] + t_s[base1 - off]);
        float e3 = __expf(s[nt][3] + t_s[base1 - off - 1]);
        s[nt][0] = e0 * PSC; s[nt][1] = e1 * PSC;
        s[nt][2] = e2 * PSC; s[nt][3] = e3 * PSC;
        l0 += e0 + e1; l1 += e2 + e3;
    }
    l0 += __shfl_xor_sync(0xffffffffu, l0, 1);
    l0 += __shfl_xor_sync(0xffffffffu, l0, 2);
    l1 += __shfl_xor_sync(0xffffffffu, l1, 1);
    l1 += __shfl_xor_sync(0xffffffffu, l1, 2);
    const float inv0 = 1.f / (l0 * PSC), inv1 = 1.f / (l1 * PSC);

    float o[4][4];
#pragma unroll
    for (int nt = 0; nt < 4; nt++) { o[nt][0]=o[nt][1]=o[nt][2]=o[nt][3]=0.f; }
#pragma unroll
    for (int kc = 0; kc < 16; kc++) {
        unsigned a[4];
        a[0] = packh2(s[2 * kc][0],     s[2 * kc][1]);
        a[1] = packh2(s[2 * kc][2],     s[2 * kc][3]);
        a[2] = packh2(s[2 * kc + 1][0], s[2 * kc + 1][1]);
        a[3] = packh2(s[2 * kc + 1][2], s[2 * kc + 1][3]);
        const unsigned* vb0 = v16 + (kc * 8 + qid) * 40;
        const unsigned* vb1 = v16 + (kc * 8 + qid + 4) * 40;
#pragma unroll
        for (int ntd = 0; ntd < 4; ntd++) {
            unsigned bf[2];
            bf[0] = vb0[ntd * 8 + gid];
            bf[1] = vb1[ntd * 8 + gid];
            mma16(o[ntd], a, bf);
        }
    }

    const int px = px0 + warp * 16 + gid;
#pragma unroll
    for (int ntd = 0; ntd < 4; ntd++) {
        int d = ntd * 8 + 2 * qid;
        size_t c0 = ((size_t)(b * C1) + d * 4 + head) * HW;
        size_t c1 = ((size_t)(b * C1) + (d + 1) * 4 + head) * HW;
        outp[c0 + px]     = o[ntd][0] * inv0;
        outp[c1 + px]     = o[ntd][1] * inv0;
        outp[c0 + px + 8] = o[ntd][2] * inv1;
        outp[c1 + px + 8] = o[ntd][3] * inv1;
    }
}

// ---------------- host orchestration ----------------
extern "C" void kernel_launch(void* const* d_in, const int* in_sizes, int n_in,
                              void* d_out, int out_size) {
    (void)in_sizes; (void)n_in; (void)out_size;
    const float* x        = (const float*)d_in[0];
    const float* bb_bn1_g = (const float*)d_in[1];
    const float* bb_bn1_b = (const float*)d_in[2];
    const float* bb_conv1 = (const float*)d_in[3];
    const float* bb_bn2_g = (const float*)d_in[4];
    const float* bb_bn2_b = (const float*)d_in[5];
    const float* bb_conv2 = (const float*)d_in[6];
    const float* bb_sbn_g = (const float*)d_in[7];
    const float* bb_sbn_b = (const float*)d_in[8];
    const float* bb_sconv = (const float*)d_in[9];
    const float* tb_bn1_g = (const float*)d_in[10];
    const float* tb_bn1_b = (const float*)d_in[11];
    const float* tb_dwqkv = (const float*)d_in[12];
    const float* tb_pwqkv = (const float*)d_in[13];
    const float* tb_dwout = (const float*)d_in[14];
    const float* tb_pwout = (const float*)d_in[15];
    const float* tb_rel   = (const float*)d_in[16];
    const float* tb_bn2_g = (const float*)d_in[17];
    const float* tb_bn2_b = (const float*)d_in[18];
    const float* tb_mlp   = (const float*)d_in[19];

    void* pv;
    float *pool, *t, *o, *qb;
    __half* uh;
    cudaGetSymbolAddress(&pv, g_pool); pool = (float*)pv;
    cudaGetSymbolAddress(&pv, g_t);    t    = (float*)pv;
    cudaGetSymbolAddress(&pv, g_o);    o    = (float*)pv;
    cudaGetSymbolAddress(&pv, g_qkv);  qb   = (float*)pv;
    cudaGetSymbolAddress(&pv, g_uh);   uh   = (__half*)pv;

    const int ATTN_SMEM = (256 * 20 + 128 * 40 + 64 * 20) * 4 + 961 * 4;
    cudaFuncSetAttribute(k_attn, cudaFuncAttributeMaxDynamicSharedMemorySize, ATTN_SMEM);

    const dim3 g1(NPIX / 128, 1);
    const dim3 ga(HW / 64, B * 4);

    WArgs wa;
    wa.s[0] = { bb_conv1, WO_CONV1, 128 * 576,  64 };
    wa.s[1] = { bb_conv2, WO_CONV2, 128 * 1152, 128 };
    wa.s[2] = { bb_sconv, WO_SCONV, 128 * 64,   0 };
    wa.s[3] = { tb_pwqkv,               WO_TB,                       384 * 128, 0 };
    wa.s[4] = { tb_pwout,               WO_TB + 49152,               128 * 128, 0 };
    wa.s[5] = { tb_mlp,                 WO_TB + 65536,               128 * 128, 0 };
    wa.s[6] = { tb_pwqkv + 384 * 128,   WO_TB + WO_BLK,              384 * 128, 0 };
    wa.s[7] = { tb_pwout + 128 * 128,   WO_TB + WO_BLK + 49152,      128 * 128, 0 };
    wa.s[8] = { tb_mlp + 128 * 128,     WO_TB + WO_BLK + 65536,      128 * 128, 0 };
    k_wprep_all<<<W_TOTAL / 1024, 256>>>(wa);

    k_maxpool<<<(B * C0 * HW) / 256, 256>>>(x, pool);

    // ---- BasicBlock (conv outputs: u-stage uses g_t as fp32 temp) ----
    k_bnpart<<<dim3(C0, PARTS), 256>>>(pool, bb_bn1_g, bb_bn1_b, C0, 0, bb_sbn_g, bb_sbn_b, 2);
    k_gemm<576, 64, true, true, true, false, false><<<g1, 256>>>(pool, t, nullptr, 128, 0, WO_CONV1);
    k_bnpart<<<dim3(C1, PARTS), 256>>>(t, bb_bn2_g, bb_bn2_b, C1, 1, nullptr, nullptr, 0);
    k_gemm<1152, 128, true, true, true, false, false><<<g1, 256>>>(t, o, nullptr, 128, 1, WO_CONV2);
    k_gemm<64, 64, false, true, true, true, false><<<g1, 256>>>(pool, o, o, 128, 2, WO_SCONV);

    // ---- 2 x BasicTransBlock (ping-pong residual between o and t) ----
    float* ob = o;
    float* tb = t;
    for (int i = 0; i < 2; i++) {
        const int wo = WO_TB + i * WO_BLK;
        k_bnpart<<<dim3(C1, PARTS), 256>>>(ob, tb_bn1_g + i * 128, tb_bn1_b + i * 128, C1, 3,
                                           nullptr, nullptr, 0);
        k_dw3<1><<<(B * C1 * HW) / 1024, 256>>>(ob, tb_dwqkv + (size_t)i * 128 * 9, uh, 3);
        k_gemm<128, 128, false, false, false, false, true><<<g1, 256>>>(uh, qb, nullptr, 128, 0, wo);
        k_ds2<<<(B * C1 * R2) / 256, 256>>>(uh);
        k_kv<<<dim3(16, B), 256>>>(tb_pwqkv + (size_t)i * 384 * 128);
        k_attn<<<ga, 128, ATTN_SMEM>>>(qb, tb_rel + (size_t)i * 961 * 4, tb);
        k_dw3<0><<<(B * C1 * HW) / 1024, 256>>>(tb, tb_dwout + (size_t)i * 128 * 9, uh, 0);
        k_gemm<128, 128, false, false, false, true, true><<<g1, 256>>>(uh, ob, ob, 128, 0, wo + 49152);
        k_bnpart<<<dim3(C1, PARTS), 256>>>(ob, tb_bn2_g + i * 128, tb_bn2_b + i * 128, C1, 4,
                                           nullptr, nullptr, 0);
        float* dest = (i == 1) ? (float*)d_out : tb;
        k_gemm<128, 128, false, true, true, true, false><<<g1, 256>>>(ob, dest, ob, 128, 4, wo + 65536);
        float* tmp = ob; ob = tb; tb = tmp;
    }
}

// round 14
// speedup vs baseline: 1.5793x; 1.0035x over previous
#include <cuda_runtime.h>
#include <cuda_fp16.h>
#include <cstdint>

// ---------------- problem constants ----------------
namespace {
constexpr int B    = 2;
constexpr int C0   = 64;
constexpr int C1   = 128;
constexpr int H    = 128, W = 128;
constexpr int HW   = H * W;            // 16384
constexpr int NPIX = B * HW;           // 32768
constexpr int R2   = 256;              // 16x16 reduced K/V
constexpr float BN_EPS = 1e-5f;
constexpr int WO_CONV1 = 0;
constexpr int WO_CONV2 = 73728;
constexpr int WO_SCONV = 221184;
constexpr int WO_TB    = 229376;
constexpr int WO_BLK   = 81920;
constexpr int W_TOTAL  = 393216;
constexpr int PARTS    = 8;
}

// ---------------- scratch (static device, no allocs) ----------------
__device__ float g_pool[B * C0 * HW];
__device__ float g_t   [B * C1 * HW];
__device__ float g_o   [B * C1 * HW];
__device__ float g_qkv [B * C1 * HW];        // q only
__device__ __align__(16) __half g_uh[B * C1 * HW];   // fp16 dw3 output
__device__ __align__(16) unsigned g_apk[B * 64 * H * 130];  // paired fp16 act, padded
__device__ float g_ud  [B * C1 * R2];
__device__ float g_kd  [B * C1 * R2];
__device__ float g_vd  [B * C1 * R2];
__device__ __align__(16) __half g_wth[W_TOTAL];
__device__ double2 g_part[128][PARTS];
__device__ unsigned g_cnt = 0;
__device__ float g_A   [8 * 128];
__device__ float g_Bv  [8 * 128];

// ---------------- helpers ----------------
__device__ __forceinline__ void mma16(float c[4], const unsigned a[4], const unsigned b[2]) {
    asm volatile(
        "mma.sync.aligned.m16n8k16.row.col.f32.f16.f16.f32 "
        "{%0,%1,%2,%3},{%4,%5,%6,%7},{%8,%9},{%0,%1,%2,%3};"
        : "+f"(c[0]), "+f"(c[1]), "+f"(c[2]), "+f"(c[3])
        : "r"(a[0]), "r"(a[1]), "r"(a[2]), "r"(a[3]), "r"(b[0]), "r"(b[1]));
}
__device__ __forceinline__ void ldm4(unsigned a[4], const void* p) {
    unsigned addr = (unsigned)__cvta_generic_to_shared(p);
    asm volatile("ldmatrix.sync.aligned.m8n8.x4.shared.b16 {%0,%1,%2,%3}, [%4];"
        : "=r"(a[0]), "=r"(a[1]), "=r"(a[2]), "=r"(a[3]) : "r"(addr));
}
__device__ __forceinline__ void ldm4t(unsigned a[4], const void* p) {
    unsigned addr = (unsigned)__cvta_generic_to_shared(p);
    asm volatile("ldmatrix.sync.aligned.m8n8.x4.trans.shared.b16 {%0,%1,%2,%3}, [%4];"
        : "=r"(a[0]), "=r"(a[1]), "=r"(a[2]), "=r"(a[3]) : "r"(addr));
}
__device__ __forceinline__ void cpa16(void* dst, const void* src) {
    unsigned d = (unsigned)__cvta_generic_to_shared(dst);
    asm volatile("cp.async.ca.shared.global [%0], [%1], 16;" :: "r"(d), "l"(src));
}
__device__ __forceinline__ void cpa4(void* dst, const void* src) {
    unsigned d = (unsigned)__cvta_generic_to_shared(dst);
    asm volatile("cp.async.ca.shared.global [%0], [%1], 4;" :: "r"(d), "l"(src));
}
__device__ __forceinline__ unsigned h2u(__half2 h) {
    return *reinterpret_cast<unsigned*>(&h);
}
__device__ __forceinline__ unsigned packh2(float a, float b) {
    return h2u(__floats2half2_rn(a, b));
}

// ---------------- weight pre-convert fp32 -> fp16 (one launch) ----------------
struct WSeg { const float* src; int dst; int n; int cin; };
struct WArgs { WSeg s[9]; };
__global__ void k_wprep_all(WArgs a) {
    int i = (blockIdx.x * 256 + threadIdx.x) * 4;
#pragma unroll
    for (int t = 0; t < 9; t++) {
        if (i < a.s[t].n) {
            float v0, v1, v2, v3;
            if (a.s[t].cin == 0) {
                float4 v = *reinterpret_cast<const float4*>(a.s[t].src + i);
                v0 = v.x; v1 = v.y; v2 = v.z; v3 = v.w;
            } else {
                int cin = a.s[t].cin;
                int K = cin * 9;
                int co = i / K, r = i - co * K;
                int q = r / cin, ci = r - q * cin;
                const float* s = a.s[t].src + (size_t)co * K + ci * 9 + q;
                v0 = s[0]; v1 = s[9]; v2 = s[18]; v3 = s[27];
            }
            uint2 pk;
            pk.x = packh2(v0, v1);
            pk.y = packh2(v2, v3);
            *reinterpret_cast<uint2*>(g_wth + a.s[t].dst + i) = pk;
            return;
        }
        i -= a.s[t].n;
    }
}

// ---------------- maxpool 2x2 ----------------
__global__ void k_maxpool(const float* __restrict__ x, float* __restrict__ out) {
    int i = blockIdx.x * 256 + threadIdx.x;
    int p  = i & (HW - 1);
    int bc = i >> 14;
    int y = p >> 7, xx = p & 127;
    const float* ip = x + (size_t)bc * 65536 + (size_t)(y * 2) * 256 + xx * 2;
    out[i] = fmaxf(fmaxf(ip[0], ip[1]), fmaxf(ip[256], ip[257]));
}

// ---------------- BN stats ----------------
__global__ void k_bnpart(const float* __restrict__ x, const float* __restrict__ gg,
                         const float* __restrict__ bb, int Cc, int slot,
                         const float* __restrict__ gg2, const float* __restrict__ bb2,
                         int slot2) {
    int c = blockIdx.x, part = blockIdx.y;
    int tid = threadIdx.x;
    int lane = tid & 31, wid = tid >> 5;
    const float4* x0 = reinterpret_cast<const float4*>(x + (size_t)c * HW) + part * (HW / (4 * PARTS));
    const float4* x1 = reinterpret_cast<const float4*>(x + (size_t)(Cc + c) * HW) + part * (HW / (4 * PARTS));
    float s = 0.f, s2 = 0.f;
#pragma unroll
    for (int it = 0; it < 2; it++) {
        int p = tid + it * 256;
        float4 a = x0[p];
        s += a.x + a.y + a.z + a.w;
        s2 = fmaf(a.x, a.x, fmaf(a.y, a.y, fmaf(a.z, a.z, fmaf(a.w, a.w, s2))));
        float4 d = x1[p];
        s += d.x + d.y + d.z + d.w;
        s2 = fmaf(d.x, d.x, fmaf(d.y, d.y, fmaf(d.z, d.z, fmaf(d.w, d.w, s2))));
    }
#pragma unroll
    for (int off = 16; off > 0; off >>= 1) {
        s  += __shfl_down_sync(0xffffffffu, s, off);
        s2 += __shfl_down_sync(0xffffffffu, s2, off);
    }
    __shared__ double ws[8], wq[8];
    __shared__ bool lastf;
    if (lane == 0) { ws[wid] = (double)s; wq[wid] = (double)s2; }
    __syncthreads();
    if (tid == 0) {
        double S = 0., Q = 0.;
#pragma unroll
        for (int w = 0; w < 8; w++) { S += ws[w]; Q += wq[w]; }
        g_part[c][part] = make_double2(S, Q);
        __threadfence();
        unsigned v = atomicAdd(&g_cnt, 1u);
        lastf = (v == (unsigned)(Cc * PARTS - 1));
    }
    __syncthreads();
    if (lastf) {
        __threadfence();
        int cc = tid;
        if (cc < Cc) {
            double ss = 0., q = 0.;
#pragma unroll
            for (int p = 0; p < PARTS; p++) { ss += g_part[cc][p].x; q += g_part[cc][p].y; }
            double mean = ss / (double)NPIX;
            double var  = q / (double)NPIX - mean * mean;
            double rstd = 1.0 / sqrt(var + (double)BN_EPS);
            double A    = (double)gg[cc] * rstd;
            g_A[slot * 128 + cc]  = (float)A;
            g_Bv[slot * 128 + cc] = (float)((double)bb[cc] - mean * A);
            if (gg2) {
                double A2 = (double)gg2[cc] * rstd;
                g_A[slot2 * 128 + cc]  = (float)A2;
                g_Bv[slot2 * 128 + cc] = (float)((double)bb2[cc] - mean * A2);
            }
        }
        if (tid == 0) g_cnt = 0;
    }
}

// ---------------- activation prep: BN+ReLU -> paired fp16, width-padded ----------------
// apk[(b*CP+cp)*128 + y][130]: word(col+1) = (h(act[2cp][y][col]), h(act[2cp+1][y][col]))
__global__ void k_actprep(const float* __restrict__ x, int CP, int slot) {
    int i = blockIdx.x * 256 + threadIdx.x;   // over B*CP*HW
    int col = i & 127;
    int rest = i >> 7;
    int y = rest & 127;
    int bcp = rest >> 7;
    int cp = bcp % CP;
    int b = bcp / CP;
    const float* p0 = x + ((size_t)(b * 2 * CP) + 2 * cp) * HW + y * 128 + col;
    float v0 = p0[0], v1 = p0[HW];
    float A0 = g_A[slot * 128 + 2 * cp],     B0 = g_Bv[slot * 128 + 2 * cp];
    float A1 = g_A[slot * 128 + 2 * cp + 1], B1 = g_Bv[slot * 128 + 2 * cp + 1];
    v0 = fmaxf(fmaf(v0, A0, B0), 0.f);
    v1 = fmaxf(fmaf(v1, A1, B1), 0.f);
    unsigned* row = g_apk + (size_t)bcp * 128 * 130 + y * 130;
    row[col + 1] = packh2(v0, v1);
    if (col == 0)   row[0]   = 0u;
    if (col == 127) row[129] = 0u;
}

// ---------------- conv GEMM: 3-stage cp.async pipeline, im2col from apk ----------------
// C[128,N] = W[128,K] @ im2col(act). Block 128x128, 8 warps (m64 x n32).
template <int K, int CIN>
__global__ __launch_bounds__(256)
void k_cgemm(float* __restrict__ out, int woff) {
    extern __shared__ __align__(16) unsigned char smraw[];
    constexpr int ABYTES = 128 * 40 * 2;     // 10240
    constexpr int BBYTES = 16 * 136 * 4;     // 8704
    constexpr int STAGE  = ABYTES + BBYTES;  // 18944
    constexpr int CP = CIN / 2;
    constexpr int NC = K / 32;

    const int tid = threadIdx.x;
    const int lane = tid & 31, warp = tid >> 5;
    const int gid = lane >> 2, qid = lane & 3;
    const int wm = (warp & 1) * 64, wn = (warp >> 1) * 32;

    const int n0 = blockIdx.x * 128;
    const int b  = n0 >> 14;
    const int pbase = n0 & (HW - 1);
    const int y = pbase >> 7;

    const __half* wbase = g_wth + woff;

    float c[4][4][4];
#pragma unroll
    for (int mt = 0; mt < 4; mt++)
#pragma unroll
        for (int nt = 0; nt < 4; nt++)
#pragma unroll
            for (int e = 0; e < 4; e++) c[mt][nt][e] = 0.f;

    const int a_row = tid >> 1;
    const int a_c   = (tid & 1) * 16;
    const int b_row = tid >> 4;            // 0..15 (cpair within chunk)
    const int b_col = (tid & 15) * 8;      // 8 words

    const int a_off = (wm + (lane & 15)) * 40 + ((lane >> 4) << 3);

    auto issue = [&](int ch) {
        unsigned char* base = smraw + (ch % 3) * STAGE;
        __half* dA = reinterpret_cast<__half*>(base);
        unsigned* dB = reinterpret_cast<unsigned*>(base + ABYTES);
        int k0 = ch * 32;
        // A weights
        const __half* srcA = wbase + (size_t)a_row * K + k0 + a_c;
        cpa16(dA + a_row * 40 + a_c, srcA);
        cpa16(dA + a_row * 40 + a_c + 8, srcA + 8);
        // B im2col from apk
        int q   = k0 / CIN;
        int cb2 = (k0 - q * CIN) >> 1;
        int dyq = q / 3 - 1, dxq = q - (q / 3) * 3 - 1;
        int gy = y + dyq;
        unsigned* db = dB + b_row * 136 + b_col;
        if ((unsigned)gy < 128u) {
            const unsigned* src = g_apk
                + ((size_t)(b * CP + cb2 + b_row) * 128 + gy) * 130 + b_col + dxq + 1;
#pragma unroll
            for (int e = 0; e < 8; e++) cpa4(db + e, src + e);
        } else {
#pragma unroll
            for (int e = 0; e < 8; e++) db[e] = 0u;
        }
        asm volatile("cp.async.commit_group;");
    };

    issue(0);
    if (NC > 1) issue(1);

    for (int ch = 0; ch < NC; ch++) {
        if (ch < NC - 1) asm volatile("cp.async.wait_group 1;");
        else             asm volatile("cp.async.wait_group 0;");
        __syncthreads();
        if (ch + 2 < NC) issue(ch + 2);

        unsigned char* base = smraw + (ch % 3) * STAGE;
        const __half* cA = reinterpret_cast<const __half*>(base);
        const unsigned* cB = reinterpret_cast<const unsigned*>(base + ABYTES);
#pragma unroll
        for (int ks = 0; ks < 2; ks++) {
            unsigned af[4][4], bf[4][2];
#pragma unroll
            for (int mt = 0; mt < 4; mt++)
                ldm4(af[mt], cA + a_off + mt * 16 * 40 + ks * 16);
#pragma unroll
            for (int nt = 0; nt < 4; nt++) {
                int n = wn + nt * 8 + gid;
                bf[nt][0] = cB[(8 * ks + qid) * 136 + n];
                bf[nt][1] = cB[(8 * ks + qid + 4) * 136 + n];
            }
#pragma unroll
            for (int mt = 0; mt < 4; mt++)
#pragma unroll
                for (int nt = 0; nt < 4; nt++)
                    mma16(c[mt][nt], af[mt], bf[nt]);
        }
    }

#pragma unroll
    for (int mt = 0; mt < 4; mt++) {
        int co = wm + mt * 16 + gid;
#pragma unroll
        for (int nt = 0; nt < 4; nt++) {
            int cb = wn + nt * 8 + qid * 2;
            size_t idx0 = ((size_t)(b * 128) + co) * HW + pbase + cb;
            size_t idx1 = ((size_t)(b * 128) + co + 8) * HW + pbase + cb;
            *reinterpret_cast<float2*>(out + idx0) = make_float2(c[mt][nt][0], c[mt][nt][1]);
            *reinterpret_cast<float2*>(out + idx1) = make_float2(c[mt][nt][2], c[mt][nt][3]);
        }
    }
}

// ---------------- fp16 GEMM (non-IC paths, unchanged from R13) ----------------
template <int K, int CIN, bool BN, bool RELU, bool ADD, bool F16IN>
__global__ __launch_bounds__(256)
void k_gemm(const void* __restrict__ in,
            float* __restrict__ out, const float* __restrict__ add,
            int COUT, int slot, int woff) {
    __shared__ __align__(16) __half sA[128 * 40];
    __shared__ __align__(16) __half sB[32 * 136];

    const int tid = threadIdx.x;
    const int lane = tid & 31, warp = tid >> 5;
    const int gid = lane >> 2, qid = lane & 3;
    const int wm = (warp & 1) * 64, wn = (warp >> 1) * 32;

    const int n0 = blockIdx.x * 128;
    const int m0 = blockIdx.y * 128;
    const int b  = n0 >> 14;
    const int pbase = n0 & (HW - 1);

    const float* Ap = g_A  + slot * 128;
    const float* Bp = g_Bv + slot * 128;
    const __half* wbase = g_wth + woff;
    const float* inb = (const float*)in + (size_t)b * CIN * HW;
    const __half* inh = (const __half*)in + (size_t)b * CIN * HW;

    float c[4][4][4];
#pragma unroll
    for (int mt = 0; mt < 4; mt++)
#pragma unroll
        for (int nt = 0; nt < 4; nt++)
#pragma unroll
            for (int e = 0; e < 4; e++) c[mt][nt][e] = 0.f;

    const int a_row = tid >> 1;
    const int a_c   = (tid & 1) * 16;
    const int colg  = tid & 31;
    const int kp    = tid >> 5;

    __half* a_ld = sA + (wm + (lane & 15)) * 40 + ((lane >> 4) << 3);
    const unsigned* sbw = reinterpret_cast<const unsigned*>(sB);

    for (int k0 = 0; k0 < K; k0 += 32) {
        __syncthreads();
        {
            const __half* src = wbase + (size_t)(m0 + a_row) * K + k0 + a_c;
            __half* dst = sA + a_row * 40 + a_c;
            cpa16(dst, src);
            cpa16(dst + 8, src + 8);
        }
        if (F16IN) {
            int row = tid >> 3;
            int col = (tid & 7) * 16;
            const __half* src = inh + (size_t)(k0 + row) * HW + pbase + col;
            __half* dst = sB + row * 136 + col;
            cpa16(dst, src);
            cpa16(dst + 8, src + 8);
            asm volatile("cp.async.commit_group;");
        } else {
            asm volatile("cp.async.commit_group;");
#pragma unroll
            for (int it = 0; it < 2; it++) {
                int kpair = kp + it * 8;
                int ke = k0 + kpair * 2;
                float ve[4], vo[4];
#pragma unroll
                for (int half = 0; half < 2; half++) {
                    int k = ke + half;
                    float* v = half ? vo : ve;
                    float4 xv = *reinterpret_cast<const float4*>(
                        inb + (size_t)k * HW + pbase + colg * 4);
                    if (BN) {
                        float A = Ap[k], Bb = Bp[k];
                        xv.x = fmaf(xv.x, A, Bb); xv.y = fmaf(xv.y, A, Bb);
                        xv.z = fmaf(xv.z, A, Bb); xv.w = fmaf(xv.w, A, Bb);
                        if (RELU) {
                            xv.x = fmaxf(xv.x, 0.f); xv.y = fmaxf(xv.y, 0.f);
                            xv.z = fmaxf(xv.z, 0.f); xv.w = fmaxf(xv.w, 0.f);
                        }
                    }
                    v[0] = xv.x; v[1] = xv.y; v[2] = xv.z; v[3] = xv.w;
                }
                uint4 pk;
                pk.x = packh2(ve[0], vo[0]);
                pk.y = packh2(ve[1], vo[1]);
                pk.z = packh2(ve[2], vo[2]);
                pk.w = packh2(ve[3], vo[3]);
                *reinterpret_cast<uint4*>(sB + kpair * 272 + colg * 8) = pk;
            }
        }
        asm volatile("cp.async.wait_group 0;");
        __syncthreads();
#pragma unroll
        for (int ks = 0; ks < 2; ks++) {
            unsigned af[4][4], bf[4][2];
#pragma unroll
            for (int mt = 0; mt < 4; mt++)
                ldm4(af[mt], a_ld + mt * 16 * 40 + ks * 16);
            if (F16IN) {
                const __half* basep = sB + (ks * 16 + (lane & 15)) * 136
                                         + wn + ((lane >> 4) << 3);
                unsigned r[4];
                ldm4t(r, basep);
                bf[0][0] = r[0]; bf[0][1] = r[1];
                bf[1][0] = r[2]; bf[1][1] = r[3];
                ldm4t(r, basep + 16);
                bf[2][0] = r[0]; bf[2][1] = r[1];
                bf[3][0] = r[2]; bf[3][1] = r[3];
            } else {
#pragma unroll
                for (int nt = 0; nt < 4; nt++) {
                    int n = wn + nt * 8 + gid;
                    bf[nt][0] = sbw[(8 * ks + qid) * 136 + n];
                    bf[nt][1] = sbw[(8 * ks + qid + 4) * 136 + n];
                }
            }
#pragma unroll
            for (int mt = 0; mt < 4; mt++)
#pragma unroll
                for (int nt = 0; nt < 4; nt++)
                    mma16(c[mt][nt], af[mt], bf[nt]);
        }
    }

#pragma unroll
    for (int mt = 0; mt < 4; mt++) {
        int co = m0 + wm + mt * 16 + gid;
#pragma unroll
        for (int nt = 0; nt < 4; nt++) {
            int cb = wn + nt * 8 + qid * 2;
            size_t idx0 = ((size_t)(b * COUT) + co) * HW + pbase + cb;
            size_t idx1 = ((size_t)(b * COUT) + co + 8) * HW + pbase + cb;
            float2 r0 = make_float2(c[mt][nt][0], c[mt][nt][1]);
            float2 r1 = make_float2(c[mt][nt][2], c[mt][nt][3]);
            if (ADD) {
                float2 a0 = *reinterpret_cast<const float2*>(add + idx0);
                float2 a1 = *reinterpret_cast<const float2*>(add + idx1);
                r0.x += a0.x; r0.y += a0.y; r1.x += a1.x; r1.y += a1.y;
            }
            *reinterpret_cast<float2*>(out + idx0) = r0;
            *reinterpret_cast<float2*>(out + idx1) = r1;
        }
    }
}

// ---------------- depthwise 3x3 -> fp16 out ----------------
template <int BN>
__global__ void k_dw3(const float* __restrict__ in, const float* __restrict__ w,
                      __half* __restrict__ out, int slot) {
    int i = blockIdx.x * 256 + threadIdx.x;
    int idx = i * 4;
    int p  = idx & (HW - 1);
    int bc = idx >> 14;
    int c  = bc & 127;
    int y = p >> 7, x0 = p & 127;
    const float* ip = in + (size_t)bc * HW;
    const float* wp = w + c * 9;
    float A = 1.f, Bb = 0.f;
    if (BN) { A = g_A[slot * 128 + c]; Bb = g_Bv[slot * 128 + c]; }
    float acc[4] = {0.f, 0.f, 0.f, 0.f};
#pragma unroll
    for (int dy = 0; dy < 3; dy++) {
        int gy = y + dy - 1;
        if ((unsigned)gy >= 128u) continue;
        const float* r = ip + gy * 128;
        float4 m = *reinterpret_cast<const float4*>(r + x0);
        float v[6];
        v[0] = (x0 > 0)   ? r[x0 - 1] : 0.f;
        v[1] = m.x; v[2] = m.y; v[3] = m.z; v[4] = m.w;
        v[5] = (x0 < 124) ? r[x0 + 4] : 0.f;
        if (BN) {
            if (x0 > 0)   v[0] = fmaf(v[0], A, Bb);
            v[1] = fmaf(v[1], A, Bb); v[2] = fmaf(v[2], A, Bb);
            v[3] = fmaf(v[3], A, Bb); v[4] = fmaf(v[4], A, Bb);
            if (x0 < 124) v[5] = fmaf(v[5], A, Bb);
        }
        float w0 = wp[dy * 3], w1 = wp[dy * 3 + 1], w2 = wp[dy * 3 + 2];
#pragma unroll
        for (int e = 0; e < 4; e++)
            acc[e] = fmaf(v[e], w0, fmaf(v[e + 1], w1, fmaf(v[e + 2], w2, acc[e])));
    }
    uint2 pk;
    pk.x = packh2(acc[0], acc[1]);
    pk.y = packh2(acc[2], acc[3]);
    *reinterpret_cast<uint2*>(out + idx) = pk;
}

// ---------------- bilinear downsample of fp16 u ----------------
__global__ void k_ds2(const __half* __restrict__ u) {
    int i = blockIdx.x * 256 + threadIdx.x;
    int j  = i & 255;
    int c  = (i >> 8) & 127;
    int b  = i >> 15;
    const __half* ip = u + ((size_t)(b * C1) + c) * HW;
    int r = j >> 4, s = j & 15;
    const float step = (float)(127.0 / 15.0);
    float ph = (float)r * step;
    int   lh = min((int)ph, 126);
    float fh = ph - (float)lh;
    float pw = (float)s * step;
    int   lw = min((int)pw, 126);
    float fw = pw - (float)lw;
    const __half* p0 = ip + lh * 128 + lw;
    float v00 = __half2float(p0[0]),   v01 = __half2float(p0[1]);
    float v10 = __half2float(p0[128]), v11 = __half2float(p0[129]);
    g_ud[i] = (1.f - fh) * ((1.f - fw) * v00 + fw * v01)
            +        fh  * ((1.f - fw) * v10 + fw * v11);
}

// ---------------- small fp32 GEMM: kd/vd = W_kv @ ud ----------------
__global__ void k_kv(const float* __restrict__ w) {
    int og = blockIdx.x, b = blockIdx.y;
    int j = threadIdx.x;
    __shared__ float sw[16 * 128];
    for (int i = j; i < 16 * 128; i += 256)
        sw[i] = w[(size_t)(128 + og * 16) * 128 + i];
    __syncthreads();
    float acc[16];
#pragma unroll
    for (int r = 0; r < 16; r++) acc[r] = 0.f;
    const float* udb = g_ud + (size_t)b * C1 * R2 + j;
#pragma unroll 4
    for (int c = 0; c < 128; c++) {
        float v = udb[(size_t)c * R2];
#pragma unroll
        for (int r = 0; r < 16; r++) acc[r] = fmaf(sw[r * 128 + c], v, acc[r]);
    }
#pragma unroll
    for (int r = 0; r < 16; r++) {
        int oc = og * 16 + r;
        float* dst = (oc < 128) ? g_kd : g_vd;
        dst[((size_t)(b * C1) + (oc & 127)) * R2 + j] = acc[r];
    }
}

// ---------------- fp16 tensor-core attention ----------------
__global__ __launch_bounds__(128)
void k_attn(const float* __restrict__ qbuf, const float* __restrict__ table,
            float* __restrict__ outp) {
    extern __shared__ unsigned smu[];
    unsigned* k16 = smu;
    unsigned* v16 = smu + 256 * 20;
    unsigned* q16 = v16 + 128 * 40;
    float*    t_s = reinterpret_cast<float*>(q16 + 64 * 20);

    const int tid  = threadIdx.x;
    const int lane = tid & 31, warp = tid >> 5;
    const int gid  = lane >> 2, qid = lane & 3;
    const int bh   = blockIdx.y;
    const int b = bh >> 2, head = bh & 3;
    const int px0 = blockIdx.x * 64;
    const float scale = 0.17677669529663687f;
    const float PSC = 0.0625f;

    for (int i = tid; i < 16 * 256; i += 128) {
        int dp = i >> 8, j = i & 255;
        const float* base = g_kd + (size_t)b * C1 * R2 + j;
        float a = base[(size_t)((2 * dp) * 4 + head) * R2];
        float bb2 = base[(size_t)((2 * dp + 1) * 4 + head) * R2];
        k16[j * 20 + dp] = packh2(a, bb2);
    }
    for (int i = tid; i < 32 * 128; i += 128) {
        int d = i >> 7, jp = i & 127;
        const float2 vv = *reinterpret_cast<const float2*>(
            g_vd + ((size_t)(b * C1) + d * 4 + head) * R2 + 2 * jp);
        v16[jp * 40 + d] = packh2(vv.x, vv.y);
    }
    for (int i = tid; i < 16 * 64; i += 128) {
        int dp = i >> 6, r = i & 63;
        const float* base = qbuf + (size_t)b * C1 * HW + px0 + r;
        float a = base[(size_t)((2 * dp) * 4 + head) * HW] * scale;
        float bb2 = base[(size_t)((2 * dp + 1) * 4 + head) * HW] * scale;
        q16[r * 20 + dp] = packh2(a, bb2);
    }
    for (int i = tid; i < 961; i += 128) t_s[i] = table[i * 4 + head] * scale;
    __syncthreads();

    unsigned aq[2][4];
#pragma unroll
    for (int kc = 0; kc < 2; kc++) {
        const unsigned* r0 = q16 + (warp * 16 + gid) * 20 + kc * 8;
        const unsigned* r1 = r0 + 8 * 20;
        aq[kc][0] = r0[qid];
        aq[kc][1] = r1[qid];
        aq[kc][2] = r0[qid + 4];
        aq[kc][3] = r1[qid + 4];
    }
    float s[32][4];
#pragma unroll
    for (int nt = 0; nt < 32; nt++) { s[nt][0]=s[nt][1]=s[nt][2]=s[nt][3]=0.f; }
#pragma unroll
    for (int nt = 0; nt < 32; nt++) {
        const unsigned* kb = k16 + (nt * 8 + gid) * 20;
#pragma unroll
        for (int kc = 0; kc < 2; kc++) {
            unsigned bf[2];
            bf[0] = kb[kc * 8 + qid];
            bf[1] = kb[kc * 8 + qid + 4];
            mma16(s[nt], aq[kc], bf);
        }
    }

    const int xb = (px0 & 127) + warp * 16;
    const int rh = (px0 >> 7) >> 3;
    const int base0 = (rh + 15) * 31 + ((xb + gid) >> 3) + 15;
    const int base1 = (rh + 15) * 31 + ((xb + gid + 8) >> 3) + 15;
    float l0 = 0.f, l1 = 0.f;
#pragma unroll
    for (int nt = 0; nt < 32; nt++) {
        int j = nt * 8 + 2 * qid;
        int off = (j >> 4) * 31 + (j & 15);
        float e0 = __expf(s[nt][0] + t_s[base0 - off]);
        float e1 = __expf(s[nt][1] + t_s[base0 - off - 1]);
        float e2 = __expf(s[nt][2] + t_s[base1 - off]);
        float e3 = __expf(s[nt][3] + t_s[base1 - off - 1]);
        s[nt][0] = e0 * PSC; s[nt][1] = e1 * PSC;
        s[nt][2] = e2 * PSC; s[nt][3] = e3 * PSC;
        l0 += e0 + e1; l1 += e2 + e3;
    }
    l0 += __shfl_xor_sync(0xffffffffu, l0, 1);
    l0 += __shfl_xor_sync(0xffffffffu, l0, 2);
    l1 += __shfl_xor_sync(0xffffffffu, l1, 1);
    l1 += __shfl_xor_sync(0xffffffffu, l1, 2);
    const float inv0 = 1.f / (l0 * PSC), inv1 = 1.f / (l1 * PSC);

    float o[4][4];
#pragma unroll
    for (int nt = 0; nt < 4; nt++) { o[nt][0]=o[nt][1]=o[nt][2]=o[nt][3]=0.f; }
#pragma unroll
    for (int kc = 0; kc < 16; kc++) {
        unsigned a[4];
        a[0] = packh2(s[2 * kc][0],     s[2 * kc][1]);
        a[1] = packh2(s[2 * kc][2],     s[2 * kc][3]);
        a[2] = packh2(s[2 * kc + 1][0], s[2 * kc + 1][1]);
        a[3] = packh2(s[2 * kc + 1][2], s[2 * kc + 1][3]);
        const unsigned* vb0 = v16 + (kc * 8 + qid) * 40;
        const unsigned* vb1 = v16 + (kc * 8 + qid + 4) * 40;
#pragma unroll
        for (int ntd = 0; ntd < 4; ntd++) {
            unsigned bf[2];
            bf[0] = vb0[ntd * 8 + gid];
            bf[1] = vb1[ntd * 8 + gid];
            mma16(o[ntd], a, bf);
        }
    }

    const int px = px0 + warp * 16 + gid;
#pragma unroll
    for (int ntd = 0; ntd < 4; ntd++) {
        int d = ntd * 8 + 2 * qid;
        size_t c0 = ((size_t)(b * C1) + d * 4 + head) * HW;
        size_t c1 = ((size_t)(b * C1) + (d + 1) * 4 + head) * HW;
        outp[c0 + px]     = o[ntd][0] * inv0;
        outp[c1 + px]     = o[ntd][1] * inv0;
        outp[c0 + px + 8] = o[ntd][2] * inv1;
        outp[c1 + px + 8] = o[ntd][3] * inv1;
    }
}

// ---------------- host orchestration ----------------
extern "C" void kernel_launch(void* const* d_in, const int* in_sizes, int n_in,
                              void* d_out, int out_size) {
    (void)in_sizes; (void)n_in; (void)out_size;
    const float* x        = (const float*)d_in[0];
    const float* bb_bn1_g = (const float*)d_in[1];
    const float* bb_bn1_b = (const float*)d_in[2];
    const float* bb_conv1 = (const float*)d_in[3];
    const float* bb_bn2_g = (const float*)d_in[4];
    const float* bb_bn2_b = (const float*)d_in[5];
    const float* bb_conv2 = (const float*)d_in[6];
    const float* bb_sbn_g = (const float*)d_in[7];
    const float* bb_sbn_b = (const float*)d_in[8];
    const float* bb_sconv = (const float*)d_in[9];
    const float* tb_bn1_g = (const float*)d_in[10];
    const float* tb_bn1_b = (const float*)d_in[11];
    const float* tb_dwqkv = (const float*)d_in[12];
    const float* tb_pwqkv = (const float*)d_in[13];
    const float* tb_dwout = (const float*)d_in[14];
    const float* tb_pwout = (const float*)d_in[15];
    const float* tb_rel   = (const float*)d_in[16];
    const float* tb_bn2_g = (const float*)d_in[17];
    const float* tb_bn2_b = (const float*)d_in[18];
    const float* tb_mlp   = (const float*)d_in[19];

    void* pv;
    float *pool, *t, *o, *qb;
    __half* uh;
    cudaGetSymbolAddress(&pv, g_pool); pool = (float*)pv;
    cudaGetSymbolAddress(&pv, g_t);    t    = (float*)pv;
    cudaGetSymbolAddress(&pv, g_o);    o    = (float*)pv;
    cudaGetSymbolAddress(&pv, g_qkv);  qb   = (float*)pv;
    cudaGetSymbolAddress(&pv, g_uh);   uh   = (__half*)pv;

    const int ATTN_SMEM = (256 * 20 + 128 * 40 + 64 * 20) * 4 + 961 * 4;
    cudaFuncSetAttribute(k_attn, cudaFuncAttributeMaxDynamicSharedMemorySize, ATTN_SMEM);
    const int CG_SMEM = 3 * (128 * 40 * 2 + 16 * 136 * 4);   // 56832
    cudaFuncSetAttribute(k_cgemm<576, 64>,
                         cudaFuncAttributeMaxDynamicSharedMemorySize, CG_SMEM);
    cudaFuncSetAttribute(k_cgemm<1152, 128>,
                         cudaFuncAttributeMaxDynamicSharedMemorySize, CG_SMEM);

    const dim3 g1(NPIX / 128, 1);
    const dim3 ga(HW / 64, B * 4);

    WArgs wa;
    wa.s[0] = { bb_conv1, WO_CONV1, 128 * 576,  64 };
    wa.s[1] = { bb_conv2, WO_CONV2, 128 * 1152, 128 };
    wa.s[2] = { bb_sconv, WO_SCONV, 128 * 64,   0 };
    wa.s[3] = { tb_pwqkv,               WO_TB,                       384 * 128, 0 };
    wa.s[4] = { tb_pwout,               WO_TB + 49152,               128 * 128, 0 };
    wa.s[5] = { tb_mlp,                 WO_TB + 65536,               128 * 128, 0 };
    wa.s[6] = { tb_pwqkv + 384 * 128,   WO_TB + WO_BLK,              384 * 128, 0 };
    wa.s[7] = { tb_pwout + 128 * 128,   WO_TB + WO_BLK + 49152,      128 * 128, 0 };
    wa.s[8] = { tb_mlp + 128 * 128,     WO_TB + WO_BLK + 65536,      128 * 128, 0 };
    k_wprep_all<<<W_TOTAL / 1024, 256>>>(wa);

    k_maxpool<<<(B * C0 * HW) / 256, 256>>>(x, pool);

    // ---- BasicBlock ----
    k_bnpart<<<dim3(C0, PARTS), 256>>>(pool, bb_bn1_g, bb_bn1_b, C0, 0, bb_sbn_g, bb_sbn_b, 2);
    k_actprep<<<(B * 32 * HW) / 256, 256>>>(pool, 32, 0);
    k_cgemm<576, 64><<<g1, 256, CG_SMEM>>>(t, WO_CONV1);
    k_bnpart<<<dim3(C1, PARTS), 256>>>(t, bb_bn2_g, bb_bn2_b, C1, 1, nullptr, nullptr, 0);
    k_actprep<<<(B * 64 * HW) / 256, 256>>>(t, 64, 1);
    k_cgemm<1152, 128><<<g1, 256, CG_SMEM>>>(o, WO_CONV2);
    k_gemm<64, 64, true, true, true, false><<<g1, 256>>>(pool, o, o, 128, 2, WO_SCONV);

    // ---- 2 x BasicTransBlock (ping-pong residual between o and t) ----
    float* ob = o;
    float* tb = t;
    for (int i = 0; i < 2; i++) {
        const int wo = WO_TB + i * WO_BLK;
        k_bnpart<<<dim3(C1, PARTS), 256>>>(ob, tb_bn1_g + i * 128, tb_bn1_b + i * 128, C1, 3,
                                           nullptr, nullptr, 0);
        k_dw3<1><<<(B * C1 * HW) / 1024, 256>>>(ob, tb_dwqkv + (size_t)i * 128 * 9, uh, 3);
        k_gemm<128, 128, false, false, false, true><<<g1, 256>>>(uh, qb, nullptr, 128, 0, wo);
        k_ds2<<<(B * C1 * R2) / 256, 256>>>(uh);
        k_kv<<<dim3(16, B), 256>>>(tb_pwqkv + (size_t)i * 384 * 128);
        k_attn<<<ga, 128, ATTN_SMEM>>>(qb, tb_rel + (size_t)i * 961 * 4, tb);
        k_dw3<0><<<(B * C1 * HW) / 1024, 256>>>(tb, tb_dwout + (size_t)i * 128 * 9, uh, 0);
        k_gemm<128, 128, false, false, true, true><<<g1, 256>>>(uh, ob, ob, 128, 0, wo + 49152);
        k_bnpart<<<dim3(C1, PARTS), 256>>>(ob, tb_bn2_g + i * 128, tb_bn2_b + i * 128, C1, 4,
                                           nullptr, nullptr, 0);
        float* dest = (i == 1) ? (float*)d_out : tb;
        k_gemm<128, 128, true, true, true, false><<<g1, 256>>>(ob, dest, ob, 128, 4, wo + 65536);
        float* tmp = ob; ob = tb; tb = tmp;
    }
}

// round 16
// speedup vs baseline: 1.6114x; 1.0204x over previous
#include <cuda_runtime.h>
#include <cuda_fp16.h>
#include <cstdint>

// ---------------- problem constants ----------------
namespace {
constexpr int B    = 2;
constexpr int C0   = 64;
constexpr int C1   = 128;
constexpr int H    = 128, W = 128;
constexpr int HW   = H * W;            // 16384
constexpr int NPIX = B * HW;           // 32768
constexpr int R2   = 256;              // 16x16 reduced K/V
constexpr float BN_EPS = 1e-5f;
constexpr int WO_CONV1 = 0;
constexpr int WO_CONV2 = 73728;
constexpr int WO_SCONV = 221184;
constexpr int WO_TB    = 229376;
constexpr int WO_BLK   = 81920;
constexpr int W_TOTAL  = 393216;
constexpr int PARTS    = 8;
}

// ---------------- scratch (static device, no allocs) ----------------
__device__ float g_pool[B * C0 * HW];
__device__ float g_t   [B * C1 * HW];
__device__ float g_o   [B * C1 * HW];
__device__ float g_qkv [B * C1 * HW];        // q only
__device__ __align__(16) __half g_uh[B * C1 * HW];   // fp16 dw3 output
__device__ __align__(16) unsigned g_apk[B * 64 * H * 130];  // paired fp16 act, padded
__device__ float g_ud  [B * C1 * R2];
__device__ __align__(16) unsigned g_kd16[B * 4 * 256 * 16]; // attn-ready packed K
__device__ __align__(16) unsigned g_vd16[B * 4 * 128 * 32]; // attn-ready packed V
__device__ __align__(16) __half g_wth[W_TOTAL];
__device__ double2 g_part[128][PARTS];
__device__ unsigned g_cnt = 0;
__device__ float g_A   [8 * 128];
__device__ float g_Bv  [8 * 128];

// ---------------- helpers ----------------
__device__ __forceinline__ void mma16(float c[4], const unsigned a[4], const unsigned b[2]) {
    asm volatile(
        "mma.sync.aligned.m16n8k16.row.col.f32.f16.f16.f32 "
        "{%0,%1,%2,%3},{%4,%5,%6,%7},{%8,%9},{%0,%1,%2,%3};"
        : "+f"(c[0]), "+f"(c[1]), "+f"(c[2]), "+f"(c[3])
        : "r"(a[0]), "r"(a[1]), "r"(a[2]), "r"(a[3]), "r"(b[0]), "r"(b[1]));
}
__device__ __forceinline__ void ldm4(unsigned a[4], const void* p) {
    unsigned addr = (unsigned)__cvta_generic_to_shared(p);
    asm volatile("ldmatrix.sync.aligned.m8n8.x4.shared.b16 {%0,%1,%2,%3}, [%4];"
        : "=r"(a[0]), "=r"(a[1]), "=r"(a[2]), "=r"(a[3]) : "r"(addr));
}
__device__ __forceinline__ void ldm4t(unsigned a[4], const void* p) {
    unsigned addr = (unsigned)__cvta_generic_to_shared(p);
    asm volatile("ldmatrix.sync.aligned.m8n8.x4.trans.shared.b16 {%0,%1,%2,%3}, [%4];"
        : "=r"(a[0]), "=r"(a[1]), "=r"(a[2]), "=r"(a[3]) : "r"(addr));
}
__device__ __forceinline__ void cpa16(void* dst, const void* src) {
    unsigned d = (unsigned)__cvta_generic_to_shared(dst);
    asm volatile("cp.async.ca.shared.global [%0], [%1], 16;" :: "r"(d), "l"(src));
}
__device__ __forceinline__ void cpa4(void* dst, const void* src) {
    unsigned d = (unsigned)__cvta_generic_to_shared(dst);
    asm volatile("cp.async.ca.shared.global [%0], [%1], 4;" :: "r"(d), "l"(src));
}
__device__ __forceinline__ unsigned h2u(__half2 h) {
    return *reinterpret_cast<unsigned*>(&h);
}
__device__ __forceinline__ unsigned packh2(float a, float b) {
    return h2u(__floats2half2_rn(a, b));
}

// ---------------- weight pre-convert fp32 -> fp16 (one launch) ----------------
struct WSeg { const float* src; int dst; int n; int cin; };
struct WArgs { WSeg s[9]; };
__global__ void k_wprep_all(WArgs a) {
    int i = (blockIdx.x * 256 + threadIdx.x) * 4;
#pragma unroll
    for (int t = 0; t < 9; t++) {
        if (i < a.s[t].n) {
            float v0, v1, v2, v3;
            if (a.s[t].cin == 0) {
                float4 v = *reinterpret_cast<const float4*>(a.s[t].src + i);
                v0 = v.x; v1 = v.y; v2 = v.z; v3 = v.w;
            } else {
                int cin = a.s[t].cin;
                int K = cin * 9;
                int co = i / K, r = i - co * K;
                int q = r / cin, ci = r - q * cin;
                const float* s = a.s[t].src + (size_t)co * K + ci * 9 + q;
                v0 = s[0]; v1 = s[9]; v2 = s[18]; v3 = s[27];
            }
            uint2 pk;
            pk.x = packh2(v0, v1);
            pk.y = packh2(v2, v3);
            *reinterpret_cast<uint2*>(g_wth + a.s[t].dst + i) = pk;
            return;
        }
        i -= a.s[t].n;
    }
}

// ---------------- maxpool 2x2 ----------------
__global__ void k_maxpool(const float* __restrict__ x, float* __restrict__ out) {
    int i = blockIdx.x * 256 + threadIdx.x;
    int p  = i & (HW - 1);
    int bc = i >> 14;
    int y = p >> 7, xx = p & 127;
    const float* ip = x + (size_t)bc * 65536 + (size_t)(y * 2) * 256 + xx * 2;
    out[i] = fmaxf(fmaxf(ip[0], ip[1]), fmaxf(ip[256], ip[257]));
}

// ---------------- BN stats ----------------
__global__ void k_bnpart(const float* __restrict__ x, const float* __restrict__ gg,
                         const float* __restrict__ bb, int Cc, int slot,
                         const float* __restrict__ gg2, const float* __restrict__ bb2,
                         int slot2) {
    int c = blockIdx.x, part = blockIdx.y;
    int tid = threadIdx.x;
    int lane = tid & 31, wid = tid >> 5;
    const float4* x0 = reinterpret_cast<const float4*>(x + (size_t)c * HW) + part * (HW / (4 * PARTS));
    const float4* x1 = reinterpret_cast<const float4*>(x + (size_t)(Cc + c) * HW) + part * (HW / (4 * PARTS));
    float s = 0.f, s2 = 0.f;
#pragma unroll
    for (int it = 0; it < 2; it++) {
        int p = tid + it * 256;
        float4 a = x0[p];
        s += a.x + a.y + a.z + a.w;
        s2 = fmaf(a.x, a.x, fmaf(a.y, a.y, fmaf(a.z, a.z, fmaf(a.w, a.w, s2))));
        float4 d = x1[p];
        s += d.x + d.y + d.z + d.w;
        s2 = fmaf(d.x, d.x, fmaf(d.y, d.y, fmaf(d.z, d.z, fmaf(d.w, d.w, s2))));
    }
#pragma unroll
    for (int off = 16; off > 0; off >>= 1) {
        s  += __shfl_down_sync(0xffffffffu, s, off);
        s2 += __shfl_down_sync(0xffffffffu, s2, off);
    }
    __shared__ double ws[8], wq[8];
    __shared__ bool lastf;
    if (lane == 0) { ws[wid] = (double)s; wq[wid] = (double)s2; }
    __syncthreads();
    if (tid == 0) {
        double S = 0., Q = 0.;
#pragma unroll
        for (int w = 0; w < 8; w++) { S += ws[w]; Q += wq[w]; }
        g_part[c][part] = make_double2(S, Q);
        __threadfence();
        unsigned v = atomicAdd(&g_cnt, 1u);
        lastf = (v == (unsigned)(Cc * PARTS - 1));
    }
    __syncthreads();
    if (lastf) {
        __threadfence();
        int cc = tid;
        if (cc < Cc) {
            double ss = 0., q = 0.;
#pragma unroll
            for (int p = 0; p < PARTS; p++) { ss += g_part[cc][p].x; q += g_part[cc][p].y; }
            double mean = ss / (double)NPIX;
            double var  = q / (double)NPIX - mean * mean;
            double rstd = 1.0 / sqrt(var + (double)BN_EPS);
            double A    = (double)gg[cc] * rstd;
            g_A[slot * 128 + cc]  = (float)A;
            g_Bv[slot * 128 + cc] = (float)((double)bb[cc] - mean * A);
            if (gg2) {
                double A2 = (double)gg2[cc] * rstd;
                g_A[slot2 * 128 + cc]  = (float)A2;
                g_Bv[slot2 * 128 + cc] = (float)((double)bb2[cc] - mean * A2);
            }
        }
        if (tid == 0) g_cnt = 0;
    }
}

// ---------------- activation prep: BN+ReLU -> paired fp16, width-padded ----------------
__global__ void k_actprep(const float* __restrict__ x, int CP, int slot) {
    int i = blockIdx.x * 256 + threadIdx.x;
    int col = i & 127;
    int rest = i >> 7;
    int y = rest & 127;
    int bcp = rest >> 7;
    int cp = bcp % CP;
    int b = bcp / CP;
    const float* p0 = x + ((size_t)(b * 2 * CP) + 2 * cp) * HW + y * 128 + col;
    float v0 = p0[0], v1 = p0[HW];
    float A0 = g_A[slot * 128 + 2 * cp],     B0 = g_Bv[slot * 128 + 2 * cp];
    float A1 = g_A[slot * 128 + 2 * cp + 1], B1 = g_Bv[slot * 128 + 2 * cp + 1];
    v0 = fmaxf(fmaf(v0, A0, B0), 0.f);
    v1 = fmaxf(fmaf(v1, A1, B1), 0.f);
    unsigned* row = g_apk + (size_t)bcp * 128 * 130 + y * 130;
    row[col + 1] = packh2(v0, v1);
    if (col == 0)   row[0]   = 0u;
    if (col == 127) row[129] = 0u;
}

// ---------------- pipelined fp16 GEMM (CONV: im2col from apk; else flat fp16 in) ----------
template <int K, int CIN, bool CONV, bool ADD>
__global__ __launch_bounds__(256)
void k_pgemm(const __half* __restrict__ in, float* __restrict__ out,
             const float* __restrict__ add, int woff) {
    extern __shared__ __align__(16) unsigned char smraw[];
    constexpr int ABYTES = 128 * 40 * 2;     // 10240
    constexpr int BBYTES = 16 * 136 * 4;     // 8704
    constexpr int STAGE  = ABYTES + BBYTES;
    constexpr int CP = CIN / 2;
    constexpr int NC = K / 32;

    const int tid = threadIdx.x;
    const int lane = tid & 31, warp = tid >> 5;
    const int gid = lane >> 2, qid = lane & 3;
    const int wm = (warp & 1) * 64, wn = (warp >> 1) * 32;

    const int n0 = blockIdx.x * 128;
    const int b  = n0 >> 14;
    const int pbase = n0 & (HW - 1);
    const int y = pbase >> 7;

    const __half* wbase = g_wth + woff;
    const __half* inh = in + (size_t)b * CIN * HW;

    float c[4][4][4];
#pragma unroll
    for (int mt = 0; mt < 4; mt++)
#pragma unroll
        for (int nt = 0; nt < 4; nt++)
#pragma unroll
            for (int e = 0; e < 4; e++) c[mt][nt][e] = 0.f;

    const int a_row = tid >> 1;
    const int a_c   = (tid & 1) * 16;
    const int b_row = tid >> 4;
    const int b_col = (tid & 15) * 8;
    const int f_row = tid >> 3;
    const int f_col = (tid & 7) * 16;

    const int a_off = (wm + (lane & 15)) * 40 + ((lane >> 4) << 3);

    auto issue = [&](int ch) {
        unsigned char* base = smraw + (ch % 3) * STAGE;
        __half* dA = reinterpret_cast<__half*>(base);
        int k0 = ch * 32;
        const __half* srcA = wbase + (size_t)a_row * K + k0 + a_c;
        cpa16(dA + a_row * 40 + a_c, srcA);
        cpa16(dA + a_row * 40 + a_c + 8, srcA + 8);
        if (CONV) {
            unsigned* dB = reinterpret_cast<unsigned*>(base + ABYTES);
            int q   = k0 / CIN;
            int cb2 = (k0 - q * CIN) >> 1;
            int dyq = q / 3 - 1, dxq = q - (q / 3) * 3 - 1;
            int gy = y + dyq;
            unsigned* db = dB + b_row * 136 + b_col;
            if ((unsigned)gy < 128u) {
                const unsigned* src = g_apk
                    + ((size_t)(b * CP + cb2 + b_row) * 128 + gy) * 130 + b_col + dxq + 1;
#pragma unroll
                for (int e = 0; e < 8; e++) cpa4(db + e, src + e);
            } else {
#pragma unroll
                for (int e = 0; e < 8; e++) db[e] = 0u;
            }
        } else {
            __half* dB = reinterpret_cast<__half*>(base + ABYTES);
            const __half* src = inh + (size_t)(k0 + f_row) * HW + pbase + f_col;
            __half* dst = dB + f_row * 136 + f_col;
            cpa16(dst, src);
            cpa16(dst + 8, src + 8);
        }
        asm volatile("cp.async.commit_group;");
    };

    issue(0);
    if (NC > 1) issue(1);

    for (int ch = 0; ch < NC; ch++) {
        if (ch < NC - 1) asm volatile("cp.async.wait_group 1;");
        else             asm volatile("cp.async.wait_group 0;");
        __syncthreads();
        if (ch + 2 < NC) issue(ch + 2);

        unsigned char* base = smraw + (ch % 3) * STAGE;
        const __half* cA = reinterpret_cast<const __half*>(base);
#pragma unroll
        for (int ks = 0; ks < 2; ks++) {
            unsigned af[4][4], bf[4][2];
#pragma unroll
            for (int mt = 0; mt < 4; mt++)
                ldm4(af[mt], cA + a_off + mt * 16 * 40 + ks * 16);
            if (CONV) {
                const unsigned* cB = reinterpret_cast<const unsigned*>(base + ABYTES);
#pragma unroll
                for (int nt = 0; nt < 4; nt++) {
                    int n = wn + nt * 8 + gid;
                    bf[nt][0] = cB[(8 * ks + qid) * 136 + n];
                    bf[nt][1] = cB[(8 * ks + qid + 4) * 136 + n];
                }
            } else {
                const __half* basep = reinterpret_cast<const __half*>(base + ABYTES)
                    + (ks * 16 + (lane & 15)) * 136 + wn + ((lane >> 4) << 3);
                unsigned r[4];
                ldm4t(r, basep);
                bf[0][0] = r[0]; bf[0][1] = r[1];
                bf[1][0] = r[2]; bf[1][1] = r[3];
                ldm4t(r, basep + 16);
                bf[2][0] = r[0]; bf[2][1] = r[1];
                bf[3][0] = r[2]; bf[3][1] = r[3];
            }
#pragma unroll
            for (int mt = 0; mt < 4; mt++)
#pragma unroll
                for (int nt = 0; nt < 4; nt++)
                    mma16(c[mt][nt], af[mt], bf[nt]);
        }
    }

#pragma unroll
    for (int mt = 0; mt < 4; mt++) {
        int co = wm + mt * 16 + gid;
#pragma unroll
        for (int nt = 0; nt < 4; nt++) {
            int cb = wn + nt * 8 + qid * 2;
            size_t idx0 = ((size_t)(b * 128) + co) * HW + pbase + cb;
            size_t idx1 = ((size_t)(b * 128) + co + 8) * HW + pbase + cb;
            float2 r0 = make_float2(c[mt][nt][0], c[mt][nt][1]);
            float2 r1 = make_float2(c[mt][nt][2], c[mt][nt][3]);
            if (ADD) {
                float2 a0 = *reinterpret_cast<const float2*>(add + idx0);
                float2 a1 = *reinterpret_cast<const float2*>(add + idx1);
                r0.x += a0.x; r0.y += a0.y; r1.x += a1.x; r1.y += a1.y;
            }
            *reinterpret_cast<float2*>(out + idx0) = r0;
            *reinterpret_cast<float2*>(out + idx1) = r1;
        }
    }
}

// ---------------- fp32-in GEMM with fused BN+ReLU, +add (sconv, mlp) ----------------
template <int K>
__global__ __launch_bounds__(256)
void k_gemm(const float* __restrict__ in, float* __restrict__ out,
            const float* __restrict__ add, int slot, int woff) {
    __shared__ __align__(16) __half sA[128 * 40];
    __shared__ __align__(16) __half sB[16 * 272];

    const int tid = threadIdx.x;
    const int lane = tid & 31, warp = tid >> 5;
    const int gid = lane >> 2, qid = lane & 3;
    const int wm = (warp & 1) * 64, wn = (warp >> 1) * 32;

    const int n0 = blockIdx.x * 128;
    const int b  = n0 >> 14;
    const int pbase = n0 & (HW - 1);

    const float* Ap = g_A  + slot * 128;
    const float* Bp = g_Bv + slot * 128;
    const __half* wbase = g_wth + woff;
    const float* inb = in + (size_t)b * K * HW;

    float c[4][4][4];
#pragma unroll
    for (int mt = 0; mt < 4; mt++)
#pragma unroll
        for (int nt = 0; nt < 4; nt++)
#pragma unroll
            for (int e = 0; e < 4; e++) c[mt][nt][e] = 0.f;

    const int a_row = tid >> 1;
    const int a_c   = (tid & 1) * 16;
    const int colg  = tid & 31;
    const int kp    = tid >> 5;

    __half* a_ld = sA + (wm + (lane & 15)) * 40 + ((lane >> 4) << 3);
    const unsigned* sbw = reinterpret_cast<const unsigned*>(sB);

    for (int k0 = 0; k0 < K; k0 += 32) {
        __syncthreads();
        {
            const __half* src = wbase + (size_t)a_row * K + k0 + a_c;
            __half* dst = sA + a_row * 40 + a_c;
            cpa16(dst, src);
            cpa16(dst + 8, src + 8);
        }
        asm volatile("cp.async.commit_group;");
#pragma unroll
        for (int it = 0; it < 2; it++) {
            int kpair = kp + it * 8;
            int ke = k0 + kpair * 2;
            float ve[4], vo[4];
#pragma unroll
            for (int half = 0; half < 2; half++) {
                int k = ke + half;
                float* v = half ? vo : ve;
                float4 xv = *reinterpret_cast<const float4*>(
                    inb + (size_t)k * HW + pbase + colg * 4);
                float A = Ap[k], Bb = Bp[k];
                v[0] = fmaxf(fmaf(xv.x, A, Bb), 0.f);
                v[1] = fmaxf(fmaf(xv.y, A, Bb), 0.f);
                v[2] = fmaxf(fmaf(xv.z, A, Bb), 0.f);
                v[3] = fmaxf(fmaf(xv.w, A, Bb), 0.f);
            }
            uint4 pk;
            pk.x = packh2(ve[0], vo[0]);
            pk.y = packh2(ve[1], vo[1]);
            pk.z = packh2(ve[2], vo[2]);
            pk.w = packh2(ve[3], vo[3]);
            *reinterpret_cast<uint4*>(sB + kpair * 272 + colg * 8) = pk;
        }
        asm volatile("cp.async.wait_group 0;");
        __syncthreads();
#pragma unroll
        for (int ks = 0; ks < 2; ks++) {
            unsigned af[4][4], bf[4][2];
#pragma unroll
            for (int mt = 0; mt < 4; mt++)
                ldm4(af[mt], a_ld + mt * 16 * 40 + ks * 16);
#pragma unroll
            for (int nt = 0; nt < 4; nt++) {
                int n = wn + nt * 8 + gid;
                bf[nt][0] = sbw[(8 * ks + qid) * 136 + n];
                bf[nt][1] = sbw[(8 * ks + qid + 4) * 136 + n];
            }
#pragma unroll
            for (int mt = 0; mt < 4; mt++)
#pragma unroll
                for (int nt = 0; nt < 4; nt++)
                    mma16(c[mt][nt], af[mt], bf[nt]);
        }
    }

#pragma unroll
    for (int mt = 0; mt < 4; mt++) {
        int co = wm + mt * 16 + gid;
#pragma unroll
        for (int nt = 0; nt < 4; nt++) {
            int cb = wn + nt * 8 + qid * 2;
            size_t idx0 = ((size_t)(b * 128) + co) * HW + pbase + cb;
            size_t idx1 = ((size_t)(b * 128) + co + 8) * HW + pbase + cb;
            float2 a0 = *reinterpret_cast<const float2*>(add + idx0);
            float2 a1 = *reinterpret_cast<const float2*>(add + idx1);
            *reinterpret_cast<float2*>(out + idx0) =
                make_float2(c[mt][nt][0] + a0.x, c[mt][nt][1] + a0.y);
            *reinterpret_cast<float2*>(out + idx1) =
                make_float2(c[mt][nt][2] + a1.x, c[mt][nt][3] + a1.y);
        }
    }
}

// ---------------- depthwise 3x3 -> fp16 out ----------------
template <int BN>
__global__ void k_dw3(const float* __restrict__ in, const float* __restrict__ w,
                      __half* __restrict__ out, int slot) {
    int i = blockIdx.x * 256 + threadIdx.x;
    int idx = i * 4;
    int p  = idx & (HW - 1);
    int bc = idx >> 14;
    int c  = bc & 127;
    int y = p >> 7, x0 = p & 127;
    const float* ip = in + (size_t)bc * HW;
    const float* wp = w + c * 9;
    float A = 1.f, Bb = 0.f;
    if (BN) { A = g_A[slot * 128 + c]; Bb = g_Bv[slot * 128 + c]; }
    float acc[4] = {0.f, 0.f, 0.f, 0.f};
#pragma unroll
    for (int dy = 0; dy < 3; dy++) {
        int gy = y + dy - 1;
        if ((unsigned)gy >= 128u) continue;
        const float* r = ip + gy * 128;
        float4 m = *reinterpret_cast<const float4*>(r + x0);
        float v[6];
        v[0] = (x0 > 0)   ? r[x0 - 1] : 0.f;
        v[1] = m.x; v[2] = m.y; v[3] = m.z; v[4] = m.w;
        v[5] = (x0 < 124) ? r[x0 + 4] : 0.f;
        if (BN) {
            if (x0 > 0)   v[0] = fmaf(v[0], A, Bb);
            v[1] = fmaf(v[1], A, Bb); v[2] = fmaf(v[2], A, Bb);
            v[3] = fmaf(v[3], A, Bb); v[4] = fmaf(v[4], A, Bb);
            if (x0 < 124) v[5] = fmaf(v[5], A, Bb);
        }
        float w0 = wp[dy * 3], w1 = wp[dy * 3 + 1], w2 = wp[dy * 3 + 2];
#pragma unroll
        for (int e = 0; e < 4; e++)
            acc[e] = fmaf(v[e], w0, fmaf(v[e + 1], w1, fmaf(v[e + 2], w2, acc[e])));
    }
    uint2 pk;
    pk.x = packh2(acc[0], acc[1]);
    pk.y = packh2(acc[2], acc[3]);
    *reinterpret_cast<uint2*>(out + idx) = pk;
}

// ---------------- bilinear downsample of fp16 u ----------------
__global__ void k_ds2(const __half* __restrict__ u) {
    int i = blockIdx.x * 256 + threadIdx.x;
    int j  = i & 255;
    int c  = (i >> 8) & 127;
    int b  = i >> 15;
    const __half* ip = u + ((size_t)(b * C1) + c) * HW;
    int r = j >> 4, s = j & 15;
    const float step = (float)(127.0 / 15.0);
    float ph = (float)r * step;
    int   lh = min((int)ph, 126);
    float fh = ph - (float)lh;
    float pw = (float)s * step;
    int   lw = min((int)pw, 126);
    float fw = pw - (float)lw;
    const __half* p0 = ip + lh * 128 + lw;
    float v00 = __half2float(p0[0]),   v01 = __half2float(p0[1]);
    float v10 = __half2float(p0[128]), v11 = __half2float(p0[129]);
    g_ud[i] = (1.f - fh) * ((1.f - fw) * v00 + fw * v01)
            +        fh  * ((1.f - fw) * v10 + fw * v11);
}

// ---------------- kd/vd = W_kv @ ud, written attn-ready (packed fp16) ----------------
__global__ void k_kv(const float* __restrict__ w) {
    int og = blockIdx.x, b = blockIdx.y;
    int j = threadIdx.x;
    __shared__ float sw[16 * 128];
    for (int i = j; i < 16 * 128; i += 256)
        sw[i] = w[(size_t)(128 + og * 16) * 128 + i];
    __syncthreads();
    float acc[16];
#pragma unroll
    for (int r = 0; r < 16; r++) acc[r] = 0.f;
    const float* udb = g_ud + (size_t)b * C1 * R2 + j;
#pragma unroll 4
    for (int c = 0; c < 128; c++) {
        float v = udb[(size_t)c * R2];
#pragma unroll
        for (int r = 0; r < 16; r++) acc[r] = fmaf(sw[r * 128 + c], v, acc[r]);
    }
    if (og < 8) {
#pragma unroll
        for (int head = 0; head < 4; head++) {
            size_t base = ((size_t)(b * 4 + head) * 256 + j) * 16;
            g_kd16[base + 2 * og]     = packh2(acc[head],     acc[head + 4]);
            g_kd16[base + 2 * og + 1] = packh2(acc[8 + head], acc[12 + head]);
        }
    } else {
        int ogv = og - 8;
#pragma unroll
        for (int r = 0; r < 16; r++) {
            float partner = __shfl_down_sync(0xffffffffu, acc[r], 1);
            if ((j & 1) == 0) {
                int d = ogv * 4 + (r >> 2), head = r & 3;
                g_vd16[((size_t)(b * 4 + head) * 128 + (j >> 1)) * 32 + d] =
                    packh2(acc[r], partner);
            }
        }
    }
}

// ---------------- fp16 tensor-core attention (coalesced K/V staging) ----------------
__global__ __launch_bounds__(128)
void k_attn(const float* __restrict__ qbuf, const float* __restrict__ table,
            float* __restrict__ outp) {
    extern __shared__ unsigned smu[];
    unsigned* k16 = smu;                      // [256 j][20]
    unsigned* v16 = smu + 256 * 20;           // [128 jp][40]
    unsigned* q16 = v16 + 128 * 40;           // [64 r][20]
    float*    t_s = reinterpret_cast<float*>(q16 + 64 * 20);

    const int tid  = threadIdx.x;
    const int lane = tid & 31, warp = tid >> 5;
    const int gid  = lane >> 2, qid = lane & 3;
    const int bh   = blockIdx.y;
    const int b = bh >> 2, head = bh & 3;
    const int px0 = blockIdx.x * 64;
    const float scale = 0.17677669529663687f;
    const float PSC = 0.0625f;

    const uint4* kg = reinterpret_cast<const uint4*>(g_kd16) + (size_t)(b * 4 + head) * 1024;
    for (int i = tid; i < 1024; i += 128) {
        uint4 wv = kg[i];
        int j = i >> 2, c4 = (i & 3) << 2;
        *reinterpret_cast<uint4*>(k16 + j * 20 + c4) = wv;
    }
    const uint4* vg = reinterpret_cast<const uint4*>(g_vd16) + (size_t)(b * 4 + head) * 1024;
    for (int i = tid; i < 1024; i += 128) {
        uint4 wv = vg[i];
        int jp = i >> 3, c4 = (i & 7) << 2;
        *reinterpret_cast<uint4*>(v16 + jp * 40 + c4) = wv;
    }
    for (int i = tid; i < 16 * 64; i += 128) {
        int dp = i >> 6, r = i & 63;
        const float* base = qbuf + (size_t)b * C1 * HW + px0 + r;
        float a = base[(size_t)((2 * dp) * 4 + head) * HW] * scale;
        float bb2 = base[(size_t)((2 * dp + 1) * 4 + head) * HW] * scale;
        q16[r * 20 + dp] = packh2(a, bb2);
    }
    for (int i = tid; i < 961; i += 128) t_s[i] = table[i * 4 + head] * scale;
    __syncthreads();

    unsigned aq[2][4];
#pragma unroll
    for (int kc = 0; kc < 2; kc++) {
        const unsigned* r0 = q16 + (warp * 16 + gid) * 20 + kc * 8;
        const unsigned* r1 = r0 + 8 * 20;
        aq[kc][0] = r0[qid];
        aq[kc][1] = r1[qid];
        aq[kc][2] = r0[qid + 4];
        aq[kc][3] = r1[qid + 4];
    }
    float s[32][4];
#pragma unroll
    for (int nt = 0; nt < 32; nt++) { s[nt][0]=s[nt][1]=s[nt][2]=s[nt][3]=0.f; }
#pragma unroll
    for (int nt = 0; nt < 32; nt++) {
        const unsigned* kb = k16 + (nt * 8 + gid) * 20;
#pragma unroll
        for (int kc = 0; kc < 2; kc++) {
            unsigned bf[2];
            bf[0] = kb[kc * 8 + qid];
            bf[1] = kb[kc * 8 + qid + 4];
            mma16(s[nt], aq[kc], bf);
        }
    }

    const int xb = (px0 & 127) + warp * 16;
    const int rh = (px0 >> 7) >> 3;
    const int base0 = (rh + 15) * 31 + ((xb + gid) >> 3) + 15;
    const int base1 = (rh + 15) * 31 + ((xb + gid + 8) >> 3) + 15;
    float l0 = 0.f, l1 = 0.f;
#pragma unroll
    for (int nt = 0; nt < 32; nt++) {
        int j = nt * 8 + 2 * qid;
        int off = (j >> 4) * 31 + (j & 15);
        float e0 = __expf(s[nt][0] + t_s[base0 - off]);
        float e1 = __expf(s[nt][1] + t_s[base0 - off - 1]);
        float e2 = __expf(s[nt][2] + t_s[base1 - off]);
        float e3 = __expf(s[nt][3] + t_s[base1 - off - 1]);
        s[nt][0] = e0 * PSC; s[nt][1] = e1 * PSC;
        s[nt][2] = e2 * PSC; s[nt][3] = e3 * PSC;
        l0 += e0 + e1; l1 += e2 + e3;
    }
    l0 += __shfl_xor_sync(0xffffffffu, l0, 1);
    l0 += __shfl_xor_sync(0xffffffffu, l0, 2);
    l1 += __shfl_xor_sync(0xffffffffu, l1, 1);
    l1 += __shfl_xor_sync(0xffffffffu, l1, 2);
    const float inv0 = 1.f / (l0 * PSC), inv1 = 1.f / (l1 * PSC);

    float o[4][4];
#pragma unroll
    for (int nt = 0; nt < 4; nt++) { o[nt][0]=o[nt][1]=o[nt][2]=o[nt][3]=0.f; }
#pragma unroll
    for (int kc = 0; kc < 16; kc++) {
        unsigned a[4];
        a[0] = packh2(s[2 * kc][0],     s[2 * kc][1]);
        a[1] = packh2(s[2 * kc][2],     s[2 * kc][3]);
        a[2] = packh2(s[2 * kc + 1][0], s[2 * kc + 1][1]);
        a[3] = packh2(s[2 * kc + 1][2], s[2 * kc + 1][3]);
        const unsigned* vb0 = v16 + (kc * 8 + qid) * 40;
        const unsigned* vb1 = v16 + (kc * 8 + qid + 4) * 40;
#pragma unroll
        for (int ntd = 0; ntd < 4; ntd++) {
            unsigned bf[2];
            bf[0] = vb0[ntd * 8 + gid];
            bf[1] = vb1[ntd * 8 + gid];
            mma16(o[ntd], a, bf);
        }
    }

    const int px = px0 + warp * 16 + gid;
#pragma unroll
    for (int ntd = 0; ntd < 4; ntd++) {
        int d = ntd * 8 + 2 * qid;
        size_t c0 = ((size_t)(b * C1) + d * 4 + head) * HW;
        size_t c1 = ((size_t)(b * C1) + (d + 1) * 4 + head) * HW;
        outp[c0 + px]     = o[ntd][0] * inv0;
        outp[c1 + px]     = o[ntd][1] * inv0;
        outp[c0 + px + 8] = o[ntd][2] * inv1;
        outp[c1 + px + 8] = o[ntd][3] * inv1;
    }
}

// ---------------- host orchestration ----------------
extern "C" void kernel_launch(void* const* d_in, const int* in_sizes, int n_in,
                              void* d_out, int out_size) {
    (void)in_sizes; (void)n_in; (void)out_size;
    const float* x        = (const float*)d_in[0];
    const float* bb_bn1_g = (const float*)d_in[1];
    const float* bb_bn1_b = (const float*)d_in[2];
    const float* bb_conv1 = (const float*)d_in[3];
    const float* bb_bn2_g = (const float*)d_in[4];
    const float* bb_bn2_b = (const float*)d_in[5];
    const float* bb_conv2 = (const float*)d_in[6];
    const float* bb_sbn_g = (const float*)d_in[7];
    const float* bb_sbn_b = (const float*)d_in[8];
    const float* bb_sconv = (const float*)d_in[9];
    const float* tb_bn1_g = (const float*)d_in[10];
    const float* tb_bn1_b = (const float*)d_in[11];
    const float* tb_dwqkv = (const float*)d_in[12];
    const float* tb_pwqkv = (const float*)d_in[13];
    const float* tb_dwout = (const float*)d_in[14];
    const float* tb_pwout = (const float*)d_in[15];
    const float* tb_rel   = (const float*)d_in[16];
    const float* tb_bn2_g = (const float*)d_in[17];
    const float* tb_bn2_b = (const float*)d_in[18];
    const float* tb_mlp   = (const float*)d_in[19];

    void* pv;
    float *pool, *t, *o, *qb;
    __half* uh;
    cudaGetSymbolAddress(&pv, g_pool); pool = (float*)pv;
    cudaGetSymbolAddress(&pv, g_t);    t    = (float*)pv;
    cudaGetSymbolAddress(&pv, g_o);    o    = (float*)pv;
    cudaGetSymbolAddress(&pv, g_qkv);  qb   = (float*)pv;
    cudaGetSymbolAddress(&pv, g_uh);   uh   = (__half*)pv;

    const int ATTN_SMEM = (256 * 20 + 128 * 40 + 64 * 20) * 4 + 961 * 4;
    cudaFuncSetAttribute(k_attn, cudaFuncAttributeMaxDynamicSharedMemorySize, ATTN_SMEM);
    const int CG_SMEM = 3 * (128 * 40 * 2 + 16 * 136 * 4);   // 56832
    cudaFuncSetAttribute(k_pgemm<576, 64, true, false>,
                         cudaFuncAttributeMaxDynamicSharedMemorySize, CG_SMEM);
    cudaFuncSetAttribute(k_pgemm<1152, 128, true, false>,
                         cudaFuncAttributeMaxDynamicSharedMemorySize, CG_SMEM);
    cudaFuncSetAttribute(k_pgemm<128, 128, false, false>,
                         cudaFuncAttributeMaxDynamicSharedMemorySize, CG_SMEM);
    cudaFuncSetAttribute(k_pgemm<128, 128, false, true>,
                         cudaFuncAttributeMaxDynamicSharedMemorySize, CG_SMEM);

    const dim3 g1(NPIX / 128, 1);
    const dim3 ga(HW / 64, B * 4);

    WArgs wa;
    wa.s[0] = { bb_conv1, WO_CONV1, 128 * 576,  64 };
    wa.s[1] = { bb_conv2, WO_CONV2, 128 * 1152, 128 };
    wa.s[2] = { bb_sconv, WO_SCONV, 128 * 64,   0 };
    wa.s[3] = { tb_pwqkv,               WO_TB,                       384 * 128, 0 };
    wa.s[4] = { tb_pwout,               WO_TB + 49152,               128 * 128, 0 };
    wa.s[5] = { tb_mlp,                 WO_TB + 65536,               128 * 128, 0 };
    wa.s[6] = { tb_pwqkv + 384 * 128,   WO_TB + WO_BLK,              384 * 128, 0 };
    wa.s[7] = { tb_pwout + 128 * 128,   WO_TB + WO_BLK + 49152,      128 * 128, 0 };
    wa.s[8] = { tb_mlp + 128 * 128,     WO_TB + WO_BLK + 65536,      128 * 128, 0 };
    k_wprep_all<<<W_TOTAL / 1024, 256>>>(wa);

    k_maxpool<<<(B * C0 * HW) / 256, 256>>>(x, pool);

    // ---- BasicBlock ----
    k_bnpart<<<dim3(C0, PARTS), 256>>>(pool, bb_bn1_g, bb_bn1_b, C0, 0, bb_sbn_g, bb_sbn_b, 2);
    k_actprep<<<(B * 32 * HW) / 256, 256>>>(pool, 32, 0);
    k_pgemm<576, 64, true, false><<<g1, 256, CG_SMEM>>>(nullptr, t, nullptr, WO_CONV1);
    k_bnpart<<<dim3(C1, PARTS), 256>>>(t, bb_bn2_g, bb_bn2_b, C1, 1, nullptr, nullptr, 0);
    k_actprep<<<(B * 64 * HW) / 256, 256>>>(t, 64, 1);
    k_pgemm<1152, 128, true, false><<<g1, 256, CG_SMEM>>>(nullptr, o, nullptr, WO_CONV2);
    k_gemm<64><<<g1, 256>>>(pool, o, o, 2, WO_SCONV);

    // ---- 2 x BasicTransBlock (ping-pong residual between o and t) ----
    float* ob = o;
    float* tb = t;
    for (int i = 0; i < 2; i++) {
        const int wo = WO_TB + i * WO_BLK;
        k_bnpart<<<dim3(C1, PARTS), 256>>>(ob, tb_bn1_g + i * 128, tb_bn1_b + i * 128, C1, 3,
                                           nullptr, nullptr, 0);
        k_dw3<1><<<(B * C1 * HW) / 1024, 256>>>(ob, tb_dwqkv + (size_t)i * 128 * 9, uh, 3);
        k_pgemm<128, 128, false, false><<<g1, 256, CG_SMEM>>>(uh, qb, nullptr, wo);
        k_ds2<<<(B * C1 * R2) / 256, 256>>>(uh);
        k_kv<<<dim3(16, B), 256>>>(tb_pwqkv + (size_t)i * 384 * 128);
        k_attn<<<ga, 128, ATTN_SMEM>>>(qb, tb_rel + (size_t)i * 961 * 4, tb);
        k_dw3<0><<<(B * C1 * HW) / 1024, 256>>>(tb, tb_dwout + (size_t)i * 128 * 9, uh, 0);
        k_pgemm<128, 128, false, true><<<g1, 256, CG_SMEM>>>(uh, ob, ob, wo + 49152);
        k_bnpart<<<dim3(C1, PARTS), 256>>>(ob, tb_bn2_g + i * 128, tb_bn2_b + i * 128, C1, 4,
                                           nullptr, nullptr, 0);
        float* dest = (i == 1) ? (float*)d_out : tb;
        k_gemm<128><<<g1, 256>>>(ob, dest, ob, 4, wo + 65536);
        float* tmp = ob; ob = tb; tb = tmp;
    }
}